// round 1
// baseline (speedup 1.0000x reference)
#include <cuda_runtime.h>
#include <math.h>

// ---------------- fixed problem shape ----------------
#define TT      4096
#define HID     2048
#define NH      16
#define HD      128
#define ROTD    32
#define HROT    16
#define NSLOTS  16384
#define BB      2
#define SS      2048
#define QKV_N   (3*HID)

// ---------------- device scratch (no allocs allowed) ----------------
__device__ float g_qkv[(size_t)TT * QKV_N];   // 96 MB
__device__ float g_q  [(size_t)TT * HID];     // 32 MB
__device__ float g_k  [(size_t)TT * HID];
__device__ float g_v  [(size_t)TT * HID];
__device__ float g_attn[(size_t)TT * HID];

// ---------------- GEMM: C[M,N] = A[M,K] * B[N,K]^T + bias[N] ----------------
// BM=BN=128, BK=16, 256 threads, 8x8 per thread.
#define BM 128
#define BN 128
#define BK 16

__global__ __launch_bounds__(256)
void gemm_nt_bias(const float* __restrict__ A, const float* __restrict__ Bm,
                  const float* __restrict__ bias, float* __restrict__ C,
                  int M, int N, int K)
{
    __shared__ float As[BK][BM + 4];
    __shared__ float Bs[BK][BN + 4];

    const int tid = threadIdx.x;
    const int tx = tid & 15;        // 0..15  -> N direction
    const int ty = tid >> 4;        // 0..15  -> M direction
    const int m0 = blockIdx.y * BM;
    const int n0 = blockIdx.x * BN;

    float acc[8][8];
#pragma unroll
    for (int i = 0; i < 8; i++)
#pragma unroll
        for (int j = 0; j < 8; j++) acc[i][j] = 0.f;

    for (int k0 = 0; k0 < K; k0 += BK) {
        // load A tile (BM x BK) as float4, store transposed
#pragma unroll
        for (int it = 0; it < (BM * BK) / (256 * 4); it++) {
            int idx = tid + it * 256;          // float4 slot
            int row = idx >> 2;                // /(BK/4)
            int c4  = idx & 3;
            float4 v = *(const float4*)&A[(size_t)(m0 + row) * K + k0 + c4 * 4];
            As[c4 * 4 + 0][row] = v.x;
            As[c4 * 4 + 1][row] = v.y;
            As[c4 * 4 + 2][row] = v.z;
            As[c4 * 4 + 3][row] = v.w;
        }
#pragma unroll
        for (int it = 0; it < (BN * BK) / (256 * 4); it++) {
            int idx = tid + it * 256;
            int row = idx >> 2;
            int c4  = idx & 3;
            float4 v = *(const float4*)&Bm[(size_t)(n0 + row) * K + k0 + c4 * 4];
            Bs[c4 * 4 + 0][row] = v.x;
            Bs[c4 * 4 + 1][row] = v.y;
            Bs[c4 * 4 + 2][row] = v.z;
            Bs[c4 * 4 + 3][row] = v.w;
        }
        __syncthreads();

#pragma unroll
        for (int kk = 0; kk < BK; kk++) {
            float a[8], b[8];
            float4 a0 = *(const float4*)&As[kk][ty * 8];
            float4 a1 = *(const float4*)&As[kk][ty * 8 + 4];
            float4 b0 = *(const float4*)&Bs[kk][tx * 8];
            float4 b1 = *(const float4*)&Bs[kk][tx * 8 + 4];
            a[0]=a0.x; a[1]=a0.y; a[2]=a0.z; a[3]=a0.w;
            a[4]=a1.x; a[5]=a1.y; a[6]=a1.z; a[7]=a1.w;
            b[0]=b0.x; b[1]=b0.y; b[2]=b0.z; b[3]=b0.w;
            b[4]=b1.x; b[5]=b1.y; b[6]=b1.z; b[7]=b1.w;
#pragma unroll
            for (int i = 0; i < 8; i++)
#pragma unroll
                for (int j = 0; j < 8; j++)
                    acc[i][j] += a[i] * b[j];
        }
        __syncthreads();
    }

#pragma unroll
    for (int i = 0; i < 8; i++) {
        int m = m0 + ty * 8 + i;
#pragma unroll
        for (int j = 0; j < 8; j += 4) {
            int n = n0 + tx * 8 + j;
            float4 w;
            w.x = acc[i][j + 0] + bias[n + 0];
            w.y = acc[i][j + 1] + bias[n + 1];
            w.z = acc[i][j + 2] + bias[n + 2];
            w.w = acc[i][j + 3] + bias[n + 3];
            *(float4*)&C[(size_t)m * N + n] = w;
        }
    }
}

// ---------------- RoPE + pack + cache scatter ----------------
__global__ __launch_bounds__(256)
void rope_scatter(const float* __restrict__ cosp, const float* __restrict__ sinp,
                  const int* __restrict__ slots,
                  float* __restrict__ kc_out, float* __restrict__ vc_out)
{
    int idx = blockIdx.x * 256 + threadIdx.x;   // t*HID + h*HD + d
    int d = idx & (HD - 1);
    int h = (idx >> 7) & (NH - 1);
    int t = idx >> 11;

    const float* base = g_qkv + (size_t)t * QKV_N;
    float qv = base[h * HD + d];
    float kv = base[HID + h * HD + d];
    float vv = base[2 * HID + h * HD + d];

    if (d < ROTD) {
        if (d < HROT) {
            float c = cosp[t * HROT + d];
            float s = sinp[t * HROT + d];
            float q2 = base[h * HD + d + HROT];
            float k2 = base[HID + h * HD + d + HROT];
            qv = qv * c - q2 * s;
            kv = kv * c - k2 * s;
        } else {
            float c = cosp[t * HROT + d - HROT];
            float s = sinp[t * HROT + d - HROT];
            float q1 = base[h * HD + d - HROT];
            float k1 = base[HID + h * HD + d - HROT];
            qv = qv * c + q1 * s;
            kv = kv * c + k1 * s;
        }
    }
    g_q[idx] = qv;
    g_k[idx] = kv;
    g_v[idx] = vv;

    int slot = slots[t];
    size_t co = (size_t)slot * (NH * HD) + h * HD + d;
    kc_out[co] = kv;
    vc_out[co] = vv;
}

// ---------------- flash attention (fp32, causal) ----------------
// grid: (S/64, NH, B). 256 threads: 8 warps, each warp = 8 q rows,
// 4 threads per q row (32-dim slices).
__global__ __launch_bounds__(256)
void attn_kernel()
{
    __shared__ float KVs[64][HD];   // 32 KB, reused for K then V

    const int b  = blockIdx.z;
    const int h  = blockIdx.y;
    const int qt = blockIdx.x;
    const int tid  = threadIdx.x;
    const int warp = tid >> 5;
    const int lane = tid & 31;
    const int qrow = warp * 8 + (lane >> 2);
    const int quad = lane & 3;

    const int tq = b * SS + qt * 64 + qrow;
    const float* qptr = g_q + (size_t)tq * HID + h * HD + quad * 32;

    float4 qreg[8];
#pragma unroll
    for (int i = 0; i < 8; i++) qreg[i] = ((const float4*)qptr)[i];

    float o[32];
#pragma unroll
    for (int i = 0; i < 32; i++) o[i] = 0.f;
    float mrun = -1e30f, lrun = 0.f;
    const float scale = 0.08838834764831845f;   // 1/sqrt(128)

    const int ntiles = qt + 1;
    for (int kt = 0; kt < ntiles; kt++) {
        const float* kbase = g_k + (size_t)(b * SS + kt * 64) * HID + h * HD;

        __syncthreads();   // previous V-tile reads done
#pragma unroll
        for (int it = 0; it < 8; it++) {
            int idx = tid + it * 256;
            int row = idx >> 5;
            int c4  = idx & 31;
            ((float4*)&KVs[row][0])[c4] =
                ((const float4*)(kbase + (size_t)row * HID))[c4];
        }
        __syncthreads();

        float s[64];
#pragma unroll
        for (int kj = 0; kj < 64; kj++) {
            const float4* krow = (const float4*)&KVs[kj][quad * 32];
            float acc = 0.f;
#pragma unroll
            for (int i = 0; i < 8; i++) {
                float4 kv4 = krow[i];
                acc += qreg[i].x * kv4.x + qreg[i].y * kv4.y
                     + qreg[i].z * kv4.z + qreg[i].w * kv4.w;
            }
            acc += __shfl_xor_sync(0xffffffffu, acc, 1);
            acc += __shfl_xor_sync(0xffffffffu, acc, 2);
            s[kj] = acc * scale;
        }

        if (kt == qt) {
#pragma unroll
            for (int kj = 0; kj < 64; kj++)
                if (kj > qrow) s[kj] = -1e30f;
        }

        float tmax = -1e30f;
#pragma unroll
        for (int kj = 0; kj < 64; kj++) tmax = fmaxf(tmax, s[kj]);
        float mnew = fmaxf(mrun, tmax);
        float corr = __expf(mrun - mnew);
        lrun *= corr;
#pragma unroll
        for (int i = 0; i < 32; i++) o[i] *= corr;

        float lsum = 0.f;
#pragma unroll
        for (int kj = 0; kj < 64; kj++) {
            float p = __expf(s[kj] - mnew);
            s[kj] = p;
            lsum += p;
        }
        lrun += lsum;
        mrun = mnew;

        // V tile (reuse the same smem buffer)
        const float* vbase = g_v + (size_t)(b * SS + kt * 64) * HID + h * HD;
        __syncthreads();
#pragma unroll
        for (int it = 0; it < 8; it++) {
            int idx = tid + it * 256;
            int row = idx >> 5;
            int c4  = idx & 31;
            ((float4*)&KVs[row][0])[c4] =
                ((const float4*)(vbase + (size_t)row * HID))[c4];
        }
        __syncthreads();

#pragma unroll
        for (int kj = 0; kj < 64; kj++) {
            float p = s[kj];
            const float4* vrow = (const float4*)&KVs[kj][quad * 32];
#pragma unroll
            for (int i = 0; i < 8; i++) {
                float4 v4 = vrow[i];
                o[i * 4 + 0] += p * v4.x;
                o[i * 4 + 1] += p * v4.y;
                o[i * 4 + 2] += p * v4.z;
                o[i * 4 + 3] += p * v4.w;
            }
        }
    }

    float inv = 1.f / lrun;
    float* optr = g_attn + (size_t)tq * HID + h * HD + quad * 32;
#pragma unroll
    for (int i = 0; i < 8; i++) {
        float4 w;
        w.x = o[i * 4 + 0] * inv;
        w.y = o[i * 4 + 1] * inv;
        w.z = o[i * 4 + 2] * inv;
        w.w = o[i * 4 + 3] * inv;
        ((float4*)optr)[i] = w;
    }
}

// ---------------- launch ----------------
extern "C" void kernel_launch(void* const* d_in, const int* in_sizes, int n_in,
                              void* d_out, int out_size)
{
    const float* hidden  = (const float*)d_in[0];
    const float* cosp    = (const float*)d_in[1];
    const float* sinp    = (const float*)d_in[2];
    const float* w_qkv   = (const float*)d_in[3];
    const float* b_qkv   = (const float*)d_in[4];
    const float* w_dense = (const float*)d_in[5];
    const float* b_dense = (const float*)d_in[6];
    const int*   slots   = (const int*)d_in[9];

    float* out = (float*)d_out;
    float* kc  = out + (size_t)TT * HID;                 // k_cache region
    float* vc  = kc + (size_t)NSLOTS * NH * HD;          // v_cache region

    // scratch pointers from device globals
    float *p_qkv, *p_attn;
    cudaGetSymbolAddress((void**)&p_qkv,  g_qkv);
    cudaGetSymbolAddress((void**)&p_attn, g_attn);

    // zero cache regions (d_out is poisoned)
    cudaMemsetAsync(kc, 0, (size_t)NSLOTS * NH * HD * sizeof(float), 0);
    cudaMemsetAsync(vc, 0, (size_t)NSLOTS * NH * HD * sizeof(float), 0);

    // 1) QKV GEMM: [4096,2048] x [6144,2048]^T + b
    {
        dim3 grid(QKV_N / BN, TT / BM);
        gemm_nt_bias<<<grid, 256>>>(hidden, w_qkv, b_qkv, p_qkv,
                                    TT, QKV_N, HID);
    }

    // 2) RoPE + pack + cache scatter
    {
        int total = TT * HID;
        rope_scatter<<<total / 256, 256>>>(cosp, sinp, slots, kc, vc);
    }

    // 3) flash attention
    {
        dim3 grid(SS / 64, NH, BB);
        attn_kernel<<<grid, 256>>>();
    }

    // 4) dense projection: [4096,2048] x [2048,2048]^T + b -> out
    {
        dim3 grid(HID / BN, TT / BM);
        gemm_nt_bias<<<grid, 256>>>(p_attn, w_dense, b_dense, out,
                                    TT, HID, HID);
    }
}

// round 2
// speedup vs baseline: 1.0311x; 1.0311x over previous
#include <cuda_runtime.h>
#include <math.h>

// ---------------- fixed problem shape ----------------
#define TT      4096
#define HID     2048
#define NH      16
#define HD      128
#define ROTD    32
#define HROT    16
#define NSLOTS  16384
#define BB      2
#define SS      2048
#define QKV_N   (3*HID)

// ---------------- device scratch (no allocs allowed) ----------------
__device__ float g_qkv[(size_t)TT * QKV_N];   // 96 MB
__device__ float g_q  [(size_t)TT * HID];     // 32 MB
__device__ float g_k  [(size_t)TT * HID];
__device__ float g_v  [(size_t)TT * HID];
__device__ float g_attn[(size_t)TT * HID];

// ---------------- GEMM: C[M,N] = A[M,K] * B[N,K]^T + bias[N] ----------------
// BM=BN=128, BK=16, 256 threads, 8x8 per thread.
#define BM 128
#define BN 128
#define BK 16

__global__ __launch_bounds__(256)
void gemm_nt_bias(const float* __restrict__ A, const float* __restrict__ Bm,
                  const float* __restrict__ bias, float* __restrict__ C,
                  int M, int N, int K)
{
    __shared__ float As[BK][BM + 4];
    __shared__ float Bs[BK][BN + 4];

    const int tid = threadIdx.x;
    const int tx = tid & 15;        // 0..15  -> N direction
    const int ty = tid >> 4;        // 0..15  -> M direction
    const int m0 = blockIdx.y * BM;
    const int n0 = blockIdx.x * BN;

    float acc[8][8];
#pragma unroll
    for (int i = 0; i < 8; i++)
#pragma unroll
        for (int j = 0; j < 8; j++) acc[i][j] = 0.f;

    for (int k0 = 0; k0 < K; k0 += BK) {
        // load A tile (BM x BK) as float4, store transposed
#pragma unroll
        for (int it = 0; it < (BM * BK) / (256 * 4); it++) {
            int idx = tid + it * 256;          // float4 slot
            int row = idx >> 2;                // /(BK/4)
            int c4  = idx & 3;
            float4 v = *(const float4*)&A[(size_t)(m0 + row) * K + k0 + c4 * 4];
            As[c4 * 4 + 0][row] = v.x;
            As[c4 * 4 + 1][row] = v.y;
            As[c4 * 4 + 2][row] = v.z;
            As[c4 * 4 + 3][row] = v.w;
        }
#pragma unroll
        for (int it = 0; it < (BN * BK) / (256 * 4); it++) {
            int idx = tid + it * 256;
            int row = idx >> 2;
            int c4  = idx & 3;
            float4 v = *(const float4*)&Bm[(size_t)(n0 + row) * K + k0 + c4 * 4];
            Bs[c4 * 4 + 0][row] = v.x;
            Bs[c4 * 4 + 1][row] = v.y;
            Bs[c4 * 4 + 2][row] = v.z;
            Bs[c4 * 4 + 3][row] = v.w;
        }
        __syncthreads();

#pragma unroll
        for (int kk = 0; kk < BK; kk++) {
            float a[8], b[8];
            float4 a0 = *(const float4*)&As[kk][ty * 8];
            float4 a1 = *(const float4*)&As[kk][ty * 8 + 4];
            float4 b0 = *(const float4*)&Bs[kk][tx * 8];
            float4 b1 = *(const float4*)&Bs[kk][tx * 8 + 4];
            a[0]=a0.x; a[1]=a0.y; a[2]=a0.z; a[3]=a0.w;
            a[4]=a1.x; a[5]=a1.y; a[6]=a1.z; a[7]=a1.w;
            b[0]=b0.x; b[1]=b0.y; b[2]=b0.z; b[3]=b0.w;
            b[4]=b1.x; b[5]=b1.y; b[6]=b1.z; b[7]=b1.w;
#pragma unroll
            for (int i = 0; i < 8; i++)
#pragma unroll
                for (int j = 0; j < 8; j++)
                    acc[i][j] += a[i] * b[j];
        }
        __syncthreads();
    }

#pragma unroll
    for (int i = 0; i < 8; i++) {
        int m = m0 + ty * 8 + i;
#pragma unroll
        for (int j = 0; j < 8; j += 4) {
            int n = n0 + tx * 8 + j;
            float4 w;
            w.x = acc[i][j + 0] + bias[n + 0];
            w.y = acc[i][j + 1] + bias[n + 1];
            w.z = acc[i][j + 2] + bias[n + 2];
            w.w = acc[i][j + 3] + bias[n + 3];
            *(float4*)&C[(size_t)m * N + n] = w;
        }
    }
}

// ---------------- RoPE + pack + cache scatter ----------------
__global__ __launch_bounds__(256)
void rope_scatter(const float* __restrict__ cosp, const float* __restrict__ sinp,
                  const int* __restrict__ slots,
                  float* __restrict__ kc_out, float* __restrict__ vc_out)
{
    int idx = blockIdx.x * 256 + threadIdx.x;   // t*HID + h*HD + d
    int d = idx & (HD - 1);
    int h = (idx >> 7) & (NH - 1);
    int t = idx >> 11;

    const float* base = g_qkv + (size_t)t * QKV_N;
    float qv = base[h * HD + d];
    float kv = base[HID + h * HD + d];
    float vv = base[2 * HID + h * HD + d];

    if (d < ROTD) {
        if (d < HROT) {
            float c = cosp[t * HROT + d];
            float s = sinp[t * HROT + d];
            float q2 = base[h * HD + d + HROT];
            float k2 = base[HID + h * HD + d + HROT];
            qv = qv * c - q2 * s;
            kv = kv * c - k2 * s;
        } else {
            float c = cosp[t * HROT + d - HROT];
            float s = sinp[t * HROT + d - HROT];
            float q1 = base[h * HD + d - HROT];
            float k1 = base[HID + h * HD + d - HROT];
            qv = qv * c + q1 * s;
            kv = kv * c + k1 * s;
        }
    }
    g_q[idx] = qv;
    g_k[idx] = kv;
    g_v[idx] = vv;

    int slot = slots[t];
    size_t co = (size_t)slot * (NH * HD) + h * HD + d;
    kc_out[co] = kv;
    vc_out[co] = vv;
}

// ---------------- flash attention v2 (fp32, causal) ----------------
// grid: (S/64, NH, B), 256 threads: 8 warps x (8 q-rows x 4 quad-threads).
// Separate K/V smem tiles (64KB dynamic), scores chunked to s[16] (no spills).
__global__ __launch_bounds__(256)
void attn_kernel()
{
    extern __shared__ float sm[];
    float* Ks = sm;              // [64][128]
    float* Vs = sm + 64 * HD;    // [64][128]

    const int b  = blockIdx.z;
    const int h  = blockIdx.y;
    const int qt = (int)gridDim.x - 1 - (int)blockIdx.x;  // heaviest tiles first
    const int tid  = threadIdx.x;
    const int warp = tid >> 5;
    const int lane = tid & 31;
    const int qrow = warp * 8 + (lane >> 2);
    const int quad = lane & 3;

    const int tq = b * SS + qt * 64 + qrow;
    const float4* qptr = (const float4*)(g_q + (size_t)tq * HID + h * HD + quad * 32);

    float4 qreg[8];
#pragma unroll
    for (int i = 0; i < 8; i++) qreg[i] = qptr[i];

    float o[32];
#pragma unroll
    for (int i = 0; i < 32; i++) o[i] = 0.f;
    float mrun = -1e30f, lrun = 0.f;
    const float scale = 0.08838834764831845f;   // 1/sqrt(128)

    for (int kt = 0; kt <= qt; kt++) {
        const float* kbase = g_k + (size_t)(b * SS + kt * 64) * HID + h * HD;
        const float* vbase = g_v + (size_t)(b * SS + kt * 64) * HID + h * HD;

        __syncthreads();   // protect prev-tile smem reads
#pragma unroll
        for (int it = 0; it < 8; it++) {
            int idx = tid + it * 256;
            int row = idx >> 5;
            int c4  = idx & 31;
            ((float4*)(Ks + row * HD))[c4] =
                ((const float4*)(kbase + (size_t)row * HID))[c4];
            ((float4*)(Vs + row * HD))[c4] =
                ((const float4*)(vbase + (size_t)row * HID))[c4];
        }
        __syncthreads();

        const bool diag = (kt == qt);

#pragma unroll
        for (int c = 0; c < 4; c++) {
            // warp-uniform skip: whole chunk above the diagonal for all 8 rows
            if (diag && c * 16 > warp * 8 + 7) break;

            const int kb = c * 16;
            float s[16];
#pragma unroll
            for (int j = 0; j < 16; j++) {
                const float4* krow = (const float4*)(Ks + (kb + j) * HD + quad * 32);
                float acc = 0.f;
#pragma unroll
                for (int i = 0; i < 8; i++) {
                    float4 k4 = krow[i];
                    acc += qreg[i].x * k4.x + qreg[i].y * k4.y
                         + qreg[i].z * k4.z + qreg[i].w * k4.w;
                }
                acc += __shfl_xor_sync(0xffffffffu, acc, 1);
                acc += __shfl_xor_sync(0xffffffffu, acc, 2);
                s[j] = acc * scale;
            }

            if (diag) {
#pragma unroll
                for (int j = 0; j < 16; j++)
                    if (kb + j > qrow) s[j] = -1e30f;
            }

            float tmax = -1e30f;
#pragma unroll
            for (int j = 0; j < 16; j++) tmax = fmaxf(tmax, s[j]);
            float mnew = fmaxf(mrun, tmax);
            float corr = __expf(mrun - mnew);
            lrun *= corr;
#pragma unroll
            for (int i = 0; i < 32; i++) o[i] *= corr;

            float lsum = 0.f;
#pragma unroll
            for (int j = 0; j < 16; j++) {
                float p = __expf(s[j] - mnew);
                s[j] = p;
                lsum += p;
            }
            lrun += lsum;
            mrun = mnew;

#pragma unroll
            for (int j = 0; j < 16; j++) {
                float p = s[j];
                const float4* vrow = (const float4*)(Vs + (kb + j) * HD + quad * 32);
#pragma unroll
                for (int i = 0; i < 8; i++) {
                    float4 v4 = vrow[i];
                    o[i * 4 + 0] += p * v4.x;
                    o[i * 4 + 1] += p * v4.y;
                    o[i * 4 + 2] += p * v4.z;
                    o[i * 4 + 3] += p * v4.w;
                }
            }
        }
    }

    float inv = 1.f / lrun;
    float* optr = g_attn + (size_t)tq * HID + h * HD + quad * 32;
#pragma unroll
    for (int i = 0; i < 8; i++) {
        float4 w;
        w.x = o[i * 4 + 0] * inv;
        w.y = o[i * 4 + 1] * inv;
        w.z = o[i * 4 + 2] * inv;
        w.w = o[i * 4 + 3] * inv;
        ((float4*)optr)[i] = w;
    }
}

// ---------------- launch ----------------
extern "C" void kernel_launch(void* const* d_in, const int* in_sizes, int n_in,
                              void* d_out, int out_size)
{
    const float* hidden  = (const float*)d_in[0];
    const float* cosp    = (const float*)d_in[1];
    const float* sinp    = (const float*)d_in[2];
    const float* w_qkv   = (const float*)d_in[3];
    const float* b_qkv   = (const float*)d_in[4];
    const float* w_dense = (const float*)d_in[5];
    const float* b_dense = (const float*)d_in[6];
    const int*   slots   = (const int*)d_in[9];

    float* out = (float*)d_out;
    float* kc  = out + (size_t)TT * HID;                 // k_cache region
    float* vc  = kc + (size_t)NSLOTS * NH * HD;          // v_cache region

    // scratch pointers from device globals
    float *p_qkv, *p_attn;
    cudaGetSymbolAddress((void**)&p_qkv,  g_qkv);
    cudaGetSymbolAddress((void**)&p_attn, g_attn);

    // allow 64KB dynamic smem for attention (idempotent, not a graph node)
    static int smem_set = 0;
    if (!smem_set) {
        cudaFuncSetAttribute(attn_kernel,
                             cudaFuncAttributeMaxDynamicSharedMemorySize,
                             2 * 64 * HD * (int)sizeof(float));
        smem_set = 1;
    }

    // zero cache regions (d_out is poisoned)
    cudaMemsetAsync(kc, 0, (size_t)NSLOTS * NH * HD * sizeof(float), 0);
    cudaMemsetAsync(vc, 0, (size_t)NSLOTS * NH * HD * sizeof(float), 0);

    // 1) QKV GEMM: [4096,2048] x [6144,2048]^T + b
    {
        dim3 grid(QKV_N / BN, TT / BM);
        gemm_nt_bias<<<grid, 256>>>(hidden, w_qkv, b_qkv, p_qkv,
                                    TT, QKV_N, HID);
    }

    // 2) RoPE + pack + cache scatter
    {
        int total = TT * HID;
        rope_scatter<<<total / 256, 256>>>(cosp, sinp, slots, kc, vc);
    }

    // 3) flash attention
    {
        dim3 grid(SS / 64, NH, BB);
        attn_kernel<<<grid, 256, 2 * 64 * HD * (int)sizeof(float)>>>();
    }

    // 4) dense projection: [4096,2048] x [2048,2048]^T + b -> out
    {
        dim3 grid(HID / BN, TT / BM);
        gemm_nt_bias<<<grid, 256>>>(p_attn, w_dense, b_dense, out,
                                    TT, HID, HID);
    }
}

// round 3
// speedup vs baseline: 2.1505x; 2.0857x over previous
#include <cuda_runtime.h>
#include <math.h>

// ---------------- fixed problem shape ----------------
#define TT      4096
#define HID     2048
#define NH      16
#define HD      128
#define ROTD    32
#define HROT    16
#define NSLOTS  16384
#define BB      2
#define SS      2048
#define QKV_N   (3*HID)

// ---------------- device scratch (no allocs allowed) ----------------
__device__ float g_qkv[(size_t)TT * QKV_N];   // 96 MB
__device__ float g_q  [(size_t)TT * HID];     // 32 MB
__device__ float g_k  [(size_t)TT * HID];
__device__ float g_v  [(size_t)TT * HID];
__device__ float g_attn[(size_t)TT * HID];

// ---------------- GEMM: C[M,N] = A[M,K] * B[N,K]^T + bias[N] ----------------
#define BM 128
#define BN 128
#define BK 16

__global__ __launch_bounds__(256)
void gemm_nt_bias(const float* __restrict__ A, const float* __restrict__ Bm,
                  const float* __restrict__ bias, float* __restrict__ C,
                  int M, int N, int K)
{
    __shared__ float As[BK][BM + 4];
    __shared__ float Bs[BK][BN + 4];

    const int tid = threadIdx.x;
    const int tx = tid & 15;        // 0..15  -> N direction
    const int ty = tid >> 4;        // 0..15  -> M direction
    const int m0 = blockIdx.y * BM;
    const int n0 = blockIdx.x * BN;

    float acc[8][8];
#pragma unroll
    for (int i = 0; i < 8; i++)
#pragma unroll
        for (int j = 0; j < 8; j++) acc[i][j] = 0.f;

    for (int k0 = 0; k0 < K; k0 += BK) {
#pragma unroll
        for (int it = 0; it < (BM * BK) / (256 * 4); it++) {
            int idx = tid + it * 256;
            int row = idx >> 2;
            int c4  = idx & 3;
            float4 v = *(const float4*)&A[(size_t)(m0 + row) * K + k0 + c4 * 4];
            As[c4 * 4 + 0][row] = v.x;
            As[c4 * 4 + 1][row] = v.y;
            As[c4 * 4 + 2][row] = v.z;
            As[c4 * 4 + 3][row] = v.w;
        }
#pragma unroll
        for (int it = 0; it < (BN * BK) / (256 * 4); it++) {
            int idx = tid + it * 256;
            int row = idx >> 2;
            int c4  = idx & 3;
            float4 v = *(const float4*)&Bm[(size_t)(n0 + row) * K + k0 + c4 * 4];
            Bs[c4 * 4 + 0][row] = v.x;
            Bs[c4 * 4 + 1][row] = v.y;
            Bs[c4 * 4 + 2][row] = v.z;
            Bs[c4 * 4 + 3][row] = v.w;
        }
        __syncthreads();

#pragma unroll
        for (int kk = 0; kk < BK; kk++) {
            float a[8], b[8];
            float4 a0 = *(const float4*)&As[kk][ty * 8];
            float4 a1 = *(const float4*)&As[kk][ty * 8 + 4];
            float4 b0 = *(const float4*)&Bs[kk][tx * 8];
            float4 b1 = *(const float4*)&Bs[kk][tx * 8 + 4];
            a[0]=a0.x; a[1]=a0.y; a[2]=a0.z; a[3]=a0.w;
            a[4]=a1.x; a[5]=a1.y; a[6]=a1.z; a[7]=a1.w;
            b[0]=b0.x; b[1]=b0.y; b[2]=b0.z; b[3]=b0.w;
            b[4]=b1.x; b[5]=b1.y; b[6]=b1.z; b[7]=b1.w;
#pragma unroll
            for (int i = 0; i < 8; i++)
#pragma unroll
                for (int j = 0; j < 8; j++)
                    acc[i][j] += a[i] * b[j];
        }
        __syncthreads();
    }

#pragma unroll
    for (int i = 0; i < 8; i++) {
        int m = m0 + ty * 8 + i;
#pragma unroll
        for (int j = 0; j < 8; j += 4) {
            int n = n0 + tx * 8 + j;
            float4 w;
            w.x = acc[i][j + 0] + bias[n + 0];
            w.y = acc[i][j + 1] + bias[n + 1];
            w.z = acc[i][j + 2] + bias[n + 2];
            w.w = acc[i][j + 3] + bias[n + 3];
            *(float4*)&C[(size_t)m * N + n] = w;
        }
    }
}

// ---------------- RoPE + pack + cache scatter ----------------
__global__ __launch_bounds__(256)
void rope_scatter(const float* __restrict__ cosp, const float* __restrict__ sinp,
                  const int* __restrict__ slots,
                  float* __restrict__ kc_out, float* __restrict__ vc_out)
{
    int idx = blockIdx.x * 256 + threadIdx.x;   // t*HID + h*HD + d
    int d = idx & (HD - 1);
    int h = (idx >> 7) & (NH - 1);
    int t = idx >> 11;

    const float* base = g_qkv + (size_t)t * QKV_N;
    float qv = base[h * HD + d];
    float kv = base[HID + h * HD + d];
    float vv = base[2 * HID + h * HD + d];

    if (d < ROTD) {
        if (d < HROT) {
            float c = cosp[t * HROT + d];
            float s = sinp[t * HROT + d];
            float q2 = base[h * HD + d + HROT];
            float k2 = base[HID + h * HD + d + HROT];
            qv = qv * c - q2 * s;
            kv = kv * c - k2 * s;
        } else {
            float c = cosp[t * HROT + d - HROT];
            float s = sinp[t * HROT + d - HROT];
            float q1 = base[h * HD + d - HROT];
            float k1 = base[HID + h * HD + d - HROT];
            qv = qv * c + q1 * s;
            kv = kv * c + k1 * s;
        }
    }
    g_q[idx] = qv;
    g_k[idx] = kv;
    g_v[idx] = vv;

    int slot = slots[t];
    size_t co = (size_t)slot * (NH * HD) + h * HD + d;
    kc_out[co] = kv;
    vc_out[co] = vv;
}

// ---------------- tiny spacer so attention lands in ncu's -s 5 slot ------
__global__ void nop_kernel() {}

// ---------------- flash attention v3 (fp32, causal) ----------------
// grid: (S/64, NH, B), 256 threads: 8 warps x (8 q-rows x 4 quad-threads).
// Quad slices are INTERLEAVED (cols i*16 + quad*4 .. +3) so that the four
// quads of a warp hit banks 0..15 instead of all aliasing banks 0..3.
__global__ __launch_bounds__(256)
void attn_kernel()
{
    extern __shared__ float sm[];
    float* Ks = sm;              // [64][128]
    float* Vs = sm + 64 * HD;    // [64][128]

    const int b  = blockIdx.z;
    const int h  = blockIdx.y;
    const int qt = (int)gridDim.x - 1 - (int)blockIdx.x;  // heaviest first
    const int tid  = threadIdx.x;
    const int warp = tid >> 5;
    const int lane = tid & 31;
    const int qrow = warp * 8 + (lane >> 2);
    const int quad = lane & 3;
    const int qoff = quad * 4;            // interleaved slice base

    const int tq = b * SS + qt * 64 + qrow;
    const float* qbase = g_q + (size_t)tq * HID + h * HD;

    // thread's 32 columns: { i*16 + quad*4 + 0..3 : i = 0..7 }
    float4 qreg[8];
#pragma unroll
    for (int i = 0; i < 8; i++)
        qreg[i] = *(const float4*)(qbase + i * 16 + qoff);

    float o[32];
#pragma unroll
    for (int i = 0; i < 32; i++) o[i] = 0.f;
    float mrun = -1e30f, lrun = 0.f;
    const float scale = 0.08838834764831845f;   // 1/sqrt(128)

    for (int kt = 0; kt <= qt; kt++) {
        const float* kbase = g_k + (size_t)(b * SS + kt * 64) * HID + h * HD;
        const float* vbase = g_v + (size_t)(b * SS + kt * 64) * HID + h * HD;

        __syncthreads();   // protect prev-tile smem reads
#pragma unroll
        for (int it = 0; it < 8; it++) {
            int idx = tid + it * 256;
            int row = idx >> 5;
            int c4  = idx & 31;
            ((float4*)(Ks + row * HD))[c4] =
                ((const float4*)(kbase + (size_t)row * HID))[c4];
            ((float4*)(Vs + row * HD))[c4] =
                ((const float4*)(vbase + (size_t)row * HID))[c4];
        }
        __syncthreads();

        const bool diag = (kt == qt);

#pragma unroll
        for (int c = 0; c < 4; c++) {
            if (diag && c * 16 > warp * 8 + 7) break;   // warp-uniform skip

            const int kb = c * 16;
            float s[16];
#pragma unroll
            for (int j = 0; j < 16; j++) {
                const float* krow = Ks + (kb + j) * HD + qoff;
                float acc = 0.f;
#pragma unroll
                for (int i = 0; i < 8; i++) {
                    float4 k4 = *(const float4*)(krow + i * 16);
                    acc += qreg[i].x * k4.x + qreg[i].y * k4.y
                         + qreg[i].z * k4.z + qreg[i].w * k4.w;
                }
                acc += __shfl_xor_sync(0xffffffffu, acc, 1);
                acc += __shfl_xor_sync(0xffffffffu, acc, 2);
                s[j] = acc * scale;
            }

            if (diag) {
#pragma unroll
                for (int j = 0; j < 16; j++)
                    if (kb + j > qrow) s[j] = -1e30f;
            }

            float tmax = -1e30f;
#pragma unroll
            for (int j = 0; j < 16; j++) tmax = fmaxf(tmax, s[j]);
            float mnew = fmaxf(mrun, tmax);
            float corr = __expf(mrun - mnew);
            lrun *= corr;
#pragma unroll
            for (int i = 0; i < 32; i++) o[i] *= corr;

            float lsum = 0.f;
#pragma unroll
            for (int j = 0; j < 16; j++) {
                float p = __expf(s[j] - mnew);
                s[j] = p;
                lsum += p;
            }
            lrun += lsum;
            mrun = mnew;

#pragma unroll
            for (int j = 0; j < 16; j++) {
                float p = s[j];
                const float* vrow = Vs + (kb + j) * HD + qoff;
#pragma unroll
                for (int i = 0; i < 8; i++) {
                    float4 v4 = *(const float4*)(vrow + i * 16);
                    o[i * 4 + 0] += p * v4.x;
                    o[i * 4 + 1] += p * v4.y;
                    o[i * 4 + 2] += p * v4.z;
                    o[i * 4 + 3] += p * v4.w;
                }
            }
        }
    }

    float inv = 1.f / lrun;
    float* obase = g_attn + (size_t)tq * HID + h * HD;
#pragma unroll
    for (int i = 0; i < 8; i++) {
        float4 w;
        w.x = o[i * 4 + 0] * inv;
        w.y = o[i * 4 + 1] * inv;
        w.z = o[i * 4 + 2] * inv;
        w.w = o[i * 4 + 3] * inv;
        *(float4*)(obase + i * 16 + qoff) = w;
    }
}

// ---------------- launch ----------------
extern "C" void kernel_launch(void* const* d_in, const int* in_sizes, int n_in,
                              void* d_out, int out_size)
{
    const float* hidden  = (const float*)d_in[0];
    const float* cosp    = (const float*)d_in[1];
    const float* sinp    = (const float*)d_in[2];
    const float* w_qkv   = (const float*)d_in[3];
    const float* b_qkv   = (const float*)d_in[4];
    const float* w_dense = (const float*)d_in[5];
    const float* b_dense = (const float*)d_in[6];
    const int*   slots   = (const int*)d_in[9];

    float* out = (float*)d_out;
    float* kc  = out + (size_t)TT * HID;                 // k_cache region
    float* vc  = kc + (size_t)NSLOTS * NH * HD;          // v_cache region

    float *p_qkv, *p_attn;
    cudaGetSymbolAddress((void**)&p_qkv,  g_qkv);
    cudaGetSymbolAddress((void**)&p_attn, g_attn);

    static int smem_set = 0;
    if (!smem_set) {
        cudaFuncSetAttribute(attn_kernel,
                             cudaFuncAttributeMaxDynamicSharedMemorySize,
                             2 * 64 * HD * (int)sizeof(float));
        smem_set = 1;
    }

    // zero cache regions (d_out is poisoned)
    cudaMemsetAsync(kc, 0, (size_t)NSLOTS * NH * HD * sizeof(float), 0);
    cudaMemsetAsync(vc, 0, (size_t)NSLOTS * NH * HD * sizeof(float), 0);

    // 1) QKV GEMM
    {
        dim3 grid(QKV_N / BN, TT / BM);
        gemm_nt_bias<<<grid, 256>>>(hidden, w_qkv, b_qkv, p_qkv,
                                    TT, QKV_N, HID);
    }

    // 2) RoPE + pack + cache scatter
    {
        int total = TT * HID;
        rope_scatter<<<total / 256, 256>>>(cosp, sinp, slots, kc, vc);
    }

    // spacer: puts attn_kernel at ncu launch index 5 (-s 5 -c 1)
    nop_kernel<<<1, 32>>>();

    // 3) flash attention
    {
        dim3 grid(SS / 64, NH, BB);
        attn_kernel<<<grid, 256, 2 * 64 * HD * (int)sizeof(float)>>>();
    }

    // 4) dense projection
    {
        dim3 grid(HID / BN, TT / BM);
        gemm_nt_bias<<<grid, 256>>>(p_attn, w_dense, b_dense, out,
                                    TT, HID, HID);
    }
}

// round 6
// speedup vs baseline: 2.9272x; 1.3611x over previous
#include <cuda_runtime.h>
#include <cuda_bf16.h>
#include <stdint.h>
#include <math.h>

// ---------------- fixed problem shape ----------------
#define TT      4096
#define HID     2048
#define NH      16
#define HD      128
#define ROTD    32
#define HROT    16
#define NSLOTS  16384
#define BB      2
#define SS      2048
#define QKV_N   (3*HID)
#define KP3     (3*HID)      // 3xBF16 split K' = 6144
#define NIT     (KP3/32)     // 192 k-iterations of BK=32

// ---------------- device scratch (no allocs allowed) ----------------
__device__ float g_qkv[(size_t)TT * QKV_N];   // 96 MB
__device__ float g_q  [(size_t)TT * HID];
__device__ float g_k  [(size_t)TT * HID];
__device__ float g_v  [(size_t)TT * HID];
__device__ float g_attn[(size_t)TT * HID];
__device__ __nv_bfloat16 g_h3 [(size_t)TT * KP3];      // hidden  [ah|al|ah] 48 MB
__device__ __nv_bfloat16 g_wq3[(size_t)QKV_N * KP3];   // w_qkv   [bh|bh|bl] 72 MB
__device__ __nv_bfloat16 g_wd3[(size_t)HID * KP3];     // w_dense [bh|bh|bl] 24 MB
__device__ __nv_bfloat16 g_a3 [(size_t)TT * KP3];      // attn    [ah|al|ah] 48 MB

// ---------------- helpers ----------------
__device__ __forceinline__ uint32_t smem_u32(const void* p) {
    uint32_t a;
    asm("{ .reg .u64 t; cvta.to.shared.u64 t, %1; cvt.u32.u64 %0, t; }"
        : "=r"(a) : "l"(p));
    return a;
}
__device__ __forceinline__ void ldm_x4(uint32_t& r0, uint32_t& r1,
                                       uint32_t& r2, uint32_t& r3, uint32_t a) {
    asm volatile("ldmatrix.sync.aligned.m8n8.x4.shared.b16 {%0,%1,%2,%3}, [%4];"
                 : "=r"(r0), "=r"(r1), "=r"(r2), "=r"(r3) : "r"(a));
}
__device__ __forceinline__ void mma16816(float* c, const uint32_t* a,
                                         const uint32_t* b) {
    asm volatile(
        "mma.sync.aligned.m16n8k16.row.col.f32.bf16.bf16.f32 "
        "{%0,%1,%2,%3}, {%4,%5,%6,%7}, {%8,%9}, {%0,%1,%2,%3};"
        : "+f"(c[0]), "+f"(c[1]), "+f"(c[2]), "+f"(c[3])
        : "r"(a[0]), "r"(a[1]), "r"(a[2]), "r"(a[3]), "r"(b[0]), "r"(b[1]));
}

// ---------------- 3xBF16 splits: segments along K' --------------------------
// A-side: out[row][k]=hi, out[row][K+k]=lo, out[row][2K+k]=hi
__global__ __launch_bounds__(256)
void split_a(const float* __restrict__ in, __nv_bfloat16* __restrict__ out)
{
    size_t i = (size_t)blockIdx.x * 256 + threadIdx.x;
    size_t row = i >> 11;                // K = HID = 2048
    size_t k   = i & (HID - 1);
    float a = in[i];
    __nv_bfloat16 hi = __float2bfloat16(a);
    __nv_bfloat16 lo = __float2bfloat16(a - __bfloat162float(hi));
    __nv_bfloat16* o = out + row * KP3;
    o[k]            = hi;
    o[HID + k]      = lo;
    o[2 * HID + k]  = hi;
}
// B-side: out[row][k]=hi, out[row][K+k]=hi, out[row][2K+k]=lo
__global__ __launch_bounds__(256)
void split_b(const float* __restrict__ in, __nv_bfloat16* __restrict__ out)
{
    size_t i = (size_t)blockIdx.x * 256 + threadIdx.x;
    size_t row = i >> 11;
    size_t k   = i & (HID - 1);
    float a = in[i];
    __nv_bfloat16 hi = __float2bfloat16(a);
    __nv_bfloat16 lo = __float2bfloat16(a - __bfloat162float(hi));
    __nv_bfloat16* o = out + row * KP3;
    o[k]            = hi;
    o[HID + k]      = hi;
    o[2 * HID + k]  = lo;
}

// ---------------- HMMA GEMM: C[M,N] = A3[M,K'] * B3[N,K']^T + bias[N] -----
// CTA 128x128, 256 threads = 2(M) x 4(N) warps, warp tile 64x32.
// mma.sync.m16n8k16 bf16, cp.async double buffer, BK=32.
#define LDA 40   // bf16 per smem row (32 data + 8 pad) -> 80B stride

__global__ __launch_bounds__(256)
void gemm_mma(const __nv_bfloat16* __restrict__ A3,
              const __nv_bfloat16* __restrict__ B3,
              const float* __restrict__ bias,
              float* __restrict__ C, int Nstride)
{
    __shared__ __align__(16) __nv_bfloat16 As[2][128 * LDA];
    __shared__ __align__(16) __nv_bfloat16 Bs[2][128 * LDA];

    const int tid  = threadIdx.x;
    const int warp = tid >> 5;
    const int lane = tid & 31;
    const int wm = warp & 1;        // 0..1  (M)
    const int wn = warp >> 1;       // 0..3  (N)
    const int m0 = blockIdx.y * 128;
    const int n0 = blockIdx.x * 128;

    const int crow0 = tid >> 2;          // chunk row (0..63)
    const int ckc   = tid & 3;           // 16B chunk in 64B k-slice

    float acc[16][4];
#pragma unroll
    for (int i = 0; i < 16; i++)
#pragma unroll
        for (int j = 0; j < 4; j++) acc[i][j] = 0.f;

#define PREF(stage, kt) do {                                                   \
    const __nv_bfloat16* _ab = A3 + (size_t)m0 * KP3 + (size_t)(kt) * 32;      \
    const __nv_bfloat16* _bb = B3 + (size_t)n0 * KP3 + (size_t)(kt) * 32;      \
    _Pragma("unroll")                                                          \
    for (int _i = 0; _i < 2; _i++) {                                           \
        int _row = crow0 + _i * 64;                                            \
        uint32_t _sa = smem_u32(&As[stage][_row * LDA + ckc * 8]);             \
        uint32_t _sb = smem_u32(&Bs[stage][_row * LDA + ckc * 8]);             \
        asm volatile("cp.async.cg.shared.global [%0], [%1], 16;"               \
            :: "r"(_sa), "l"(_ab + (size_t)_row * KP3 + ckc * 8) : "memory");  \
        asm volatile("cp.async.cg.shared.global [%0], [%1], 16;"               \
            :: "r"(_sb), "l"(_bb + (size_t)_row * KP3 + ckc * 8) : "memory");  \
    }                                                                          \
    asm volatile("cp.async.commit_group;" ::: "memory");                       \
} while (0)

    PREF(0, 0);

    const int a_r = lane & 15;
    const int a_c = (lane >> 4) * 8;
    const int b_r = (lane & 7) + ((lane >> 4) & 1) * 8;
    const int b_c = ((lane >> 3) & 1) * 8;

    for (int kt = 0; kt < NIT; kt++) {
        const int buf = kt & 1;
        if (kt + 1 < NIT) PREF(buf ^ 1, kt + 1);
        asm volatile("cp.async.wait_group %0;" :: "n"(1) : "memory");
        if (kt + 1 == NIT)
            asm volatile("cp.async.wait_group 0;" ::: "memory");
        __syncthreads();

#pragma unroll
        for (int s = 0; s < 2; s++) {
            uint32_t a[4][4], b[2][4];
#pragma unroll
            for (int mi = 0; mi < 4; mi++) {
                uint32_t addr = smem_u32(
                    &As[buf][(wm * 64 + mi * 16 + a_r) * LDA + s * 16 + a_c]);
                ldm_x4(a[mi][0], a[mi][1], a[mi][2], a[mi][3], addr);
            }
#pragma unroll
            for (int p = 0; p < 2; p++) {
                uint32_t addr = smem_u32(
                    &Bs[buf][(wn * 32 + p * 16 + b_r) * LDA + s * 16 + b_c]);
                ldm_x4(b[p][0], b[p][1], b[p][2], b[p][3], addr);
            }
#pragma unroll
            for (int mi = 0; mi < 4; mi++)
#pragma unroll
                for (int ni = 0; ni < 4; ni++) {
                    const uint32_t* bf = &b[ni >> 1][(ni & 1) * 2];
                    mma16816(acc[mi * 4 + ni], a[mi], bf);
                }
        }
        __syncthreads();
    }

    const int er = lane >> 2;
    const int ec = (lane & 3) * 2;
#pragma unroll
    for (int mi = 0; mi < 4; mi++) {
        int gm = m0 + wm * 64 + mi * 16 + er;
#pragma unroll
        for (int ni = 0; ni < 4; ni++) {
            int gn = n0 + wn * 32 + ni * 8 + ec;
            float* c = acc[mi * 4 + ni];
            float2 w0, w1;
            w0.x = c[0] + bias[gn];
            w0.y = c[1] + bias[gn + 1];
            w1.x = c[2] + bias[gn];
            w1.y = c[3] + bias[gn + 1];
            *(float2*)(C + (size_t)gm * Nstride + gn) = w0;
            *(float2*)(C + (size_t)(gm + 8) * Nstride + gn) = w1;
        }
    }
}

// ---------------- RoPE + pack + cache scatter ----------------
__global__ __launch_bounds__(256)
void rope_scatter(const float* __restrict__ cosp, const float* __restrict__ sinp,
                  const int* __restrict__ slots,
                  float* __restrict__ kc_out, float* __restrict__ vc_out)
{
    int idx = blockIdx.x * 256 + threadIdx.x;
    int d = idx & (HD - 1);
    int h = (idx >> 7) & (NH - 1);
    int t = idx >> 11;

    const float* base = g_qkv + (size_t)t * QKV_N;
    float qv = base[h * HD + d];
    float kv = base[HID + h * HD + d];
    float vv = base[2 * HID + h * HD + d];

    if (d < ROTD) {
        if (d < HROT) {
            float c = cosp[t * HROT + d];
            float s = sinp[t * HROT + d];
            float q2 = base[h * HD + d + HROT];
            float k2 = base[HID + h * HD + d + HROT];
            qv = qv * c - q2 * s;
            kv = kv * c - k2 * s;
        } else {
            float c = cosp[t * HROT + d - HROT];
            float s = sinp[t * HROT + d - HROT];
            float q1 = base[h * HD + d - HROT];
            float k1 = base[HID + h * HD + d - HROT];
            qv = qv * c + q1 * s;
            kv = kv * c + k1 * s;
        }
    }
    g_q[idx] = qv;
    g_k[idx] = kv;
    g_v[idx] = vv;

    int slot = slots[t];
    size_t co = (size_t)slot * (NH * HD) + h * HD + d;
    kc_out[co] = kv;
    vc_out[co] = vv;
}

// ---------------- flash attention (fp32, causal, conflict-free) -----------
__global__ __launch_bounds__(256)
void attn_kernel()
{
    extern __shared__ float sm[];
    float* Ks = sm;
    float* Vs = sm + 64 * HD;

    const int b  = blockIdx.z;
    const int h  = blockIdx.y;
    const int qt = (int)gridDim.x - 1 - (int)blockIdx.x;
    const int tid  = threadIdx.x;
    const int warp = tid >> 5;
    const int lane = tid & 31;
    const int qrow = warp * 8 + (lane >> 2);
    const int quad = lane & 3;
    const int qoff = quad * 4;

    const int tq = b * SS + qt * 64 + qrow;
    const float* qbase = g_q + (size_t)tq * HID + h * HD;

    float4 qreg[8];
#pragma unroll
    for (int i = 0; i < 8; i++)
        qreg[i] = *(const float4*)(qbase + i * 16 + qoff);

    float o[32];
#pragma unroll
    for (int i = 0; i < 32; i++) o[i] = 0.f;
    float mrun = -1e30f, lrun = 0.f;
    const float scale = 0.08838834764831845f;

    for (int kt = 0; kt <= qt; kt++) {
        const float* kbase = g_k + (size_t)(b * SS + kt * 64) * HID + h * HD;
        const float* vbase = g_v + (size_t)(b * SS + kt * 64) * HID + h * HD;

        __syncthreads();
#pragma unroll
        for (int it = 0; it < 8; it++) {
            int idx = tid + it * 256;
            int row = idx >> 5;
            int c4  = idx & 31;
            ((float4*)(Ks + row * HD))[c4] =
                ((const float4*)(kbase + (size_t)row * HID))[c4];
            ((float4*)(Vs + row * HD))[c4] =
                ((const float4*)(vbase + (size_t)row * HID))[c4];
        }
        __syncthreads();

        const bool diag = (kt == qt);

#pragma unroll
        for (int c = 0; c < 4; c++) {
            if (diag && c * 16 > warp * 8 + 7) break;

            const int kb = c * 16;
            float s[16];
#pragma unroll
            for (int j = 0; j < 16; j++) {
                const float* krow = Ks + (kb + j) * HD + qoff;
                float acc = 0.f;
#pragma unroll
                for (int i = 0; i < 8; i++) {
                    float4 k4 = *(const float4*)(krow + i * 16);
                    acc += qreg[i].x * k4.x + qreg[i].y * k4.y
                         + qreg[i].z * k4.z + qreg[i].w * k4.w;
                }
                acc += __shfl_xor_sync(0xffffffffu, acc, 1);
                acc += __shfl_xor_sync(0xffffffffu, acc, 2);
                s[j] = acc * scale;
            }

            if (diag) {
#pragma unroll
                for (int j = 0; j < 16; j++)
                    if (kb + j > qrow) s[j] = -1e30f;
            }

            float tmax = -1e30f;
#pragma unroll
            for (int j = 0; j < 16; j++) tmax = fmaxf(tmax, s[j]);
            float mnew = fmaxf(mrun, tmax);
            float corr = __expf(mrun - mnew);
            lrun *= corr;
#pragma unroll
            for (int i = 0; i < 32; i++) o[i] *= corr;

            float lsum = 0.f;
#pragma unroll
            for (int j = 0; j < 16; j++) {
                float p = __expf(s[j] - mnew);
                s[j] = p;
                lsum += p;
            }
            lrun += lsum;
            mrun = mnew;

#pragma unroll
            for (int j = 0; j < 16; j++) {
                float p = s[j];
                const float* vrow = Vs + (kb + j) * HD + qoff;
#pragma unroll
                for (int i = 0; i < 8; i++) {
                    float4 v4 = *(const float4*)(vrow + i * 16);
                    o[i * 4 + 0] += p * v4.x;
                    o[i * 4 + 1] += p * v4.y;
                    o[i * 4 + 2] += p * v4.z;
                    o[i * 4 + 3] += p * v4.w;
                }
            }
        }
    }

    float inv = 1.f / lrun;
    float* obase = g_attn + (size_t)tq * HID + h * HD;
#pragma unroll
    for (int i = 0; i < 8; i++) {
        float4 w;
        w.x = o[i * 4 + 0] * inv;
        w.y = o[i * 4 + 1] * inv;
        w.z = o[i * 4 + 2] * inv;
        w.w = o[i * 4 + 3] * inv;
        *(float4*)(obase + i * 16 + qoff) = w;
    }
}

// ---------------- launch ----------------
extern "C" void kernel_launch(void* const* d_in, const int* in_sizes, int n_in,
                              void* d_out, int out_size)
{
    const float* hidden  = (const float*)d_in[0];
    const float* cosp    = (const float*)d_in[1];
    const float* sinp    = (const float*)d_in[2];
    const float* w_qkv   = (const float*)d_in[3];
    const float* b_qkv   = (const float*)d_in[4];
    const float* w_dense = (const float*)d_in[5];
    const float* b_dense = (const float*)d_in[6];
    const int*   slots   = (const int*)d_in[9];

    float* out = (float*)d_out;
    float* kc  = out + (size_t)TT * HID;
    float* vc  = kc + (size_t)NSLOTS * NH * HD;

    float *p_qkv, *p_attn;
    __nv_bfloat16 *p_h3, *p_wq3, *p_wd3, *p_a3;
    cudaGetSymbolAddress((void**)&p_qkv,  g_qkv);
    cudaGetSymbolAddress((void**)&p_attn, g_attn);
    cudaGetSymbolAddress((void**)&p_h3,  g_h3);
    cudaGetSymbolAddress((void**)&p_wq3, g_wq3);
    cudaGetSymbolAddress((void**)&p_wd3, g_wd3);
    cudaGetSymbolAddress((void**)&p_a3,  g_a3);

    static int attr_set = 0;
    if (!attr_set) {
        cudaFuncSetAttribute(attn_kernel,
                             cudaFuncAttributeMaxDynamicSharedMemorySize,
                             2 * 64 * HD * (int)sizeof(float));
        attr_set = 1;
    }

    // zero cache regions (d_out is poisoned)
    cudaMemsetAsync(kc, 0, (size_t)NSLOTS * NH * HD * sizeof(float), 0);
    cudaMemsetAsync(vc, 0, (size_t)NSLOTS * NH * HD * sizeof(float), 0);

    // 3xBF16 splits
    split_a<<<(TT * HID) / 256, 256>>>(hidden, p_h3);
    split_b<<<((size_t)QKV_N * HID) / 256, 256>>>(w_qkv, p_wq3);
    split_b<<<((size_t)HID * HID) / 256, 256>>>(w_dense, p_wd3);

    // 1) QKV GEMM on tensor cores (launch idx 5 -> ncu profiles this)
    {
        dim3 grid(QKV_N / 128, TT / 128);
        gemm_mma<<<grid, 256>>>(p_h3, p_wq3, b_qkv, p_qkv, QKV_N);
    }

    // 2) RoPE + pack + cache scatter
    rope_scatter<<<(TT * HID) / 256, 256>>>(cosp, sinp, slots, kc, vc);

    // 3) flash attention
    {
        dim3 grid(SS / 64, NH, BB);
        attn_kernel<<<grid, 256, 2 * 64 * HD * (int)sizeof(float)>>>();
    }

    // 4) dense projection on tensor cores
    split_a<<<(TT * HID) / 256, 256>>>(p_attn, p_a3);
    {
        dim3 grid(HID / 128, TT / 128);
        gemm_mma<<<grid, 256>>>(p_a3, p_wd3, b_dense, out, HID);
    }
}

// round 7
// speedup vs baseline: 5.5693x; 1.9026x over previous
#include <cuda_runtime.h>
#include <cuda_bf16.h>
#include <stdint.h>
#include <math.h>

// ---------------- fixed problem shape ----------------
#define TT      4096
#define HID     2048
#define NH      16
#define HD      128
#define ROTD    32
#define HROT    16
#define NSLOTS  16384
#define BB      2
#define SS      2048
#define QKV_N   (3*HID)
#define KP3     (3*HID)      // 3xBF16 split K' = 6144
#define NIT     (KP3/32)     // 192 k-iterations of BK=32

// ---------------- device scratch (no allocs allowed) ----------------
__device__ float g_qkv[(size_t)TT * QKV_N];   // 96 MB
__device__ float g_attn[(size_t)TT * HID];
__device__ __nv_bfloat16 g_h3 [(size_t)TT * KP3];      // hidden  [ah|al|ah]
__device__ __nv_bfloat16 g_wq3[(size_t)QKV_N * KP3];   // w_qkv   [bh|bh|bl]
__device__ __nv_bfloat16 g_wd3[(size_t)HID * KP3];     // w_dense [bh|bh|bl]
__device__ __nv_bfloat16 g_a3 [(size_t)TT * KP3];      // attn    [ah|al|ah]
// attention operand planes (bf16 hi/lo)
__device__ __nv_bfloat16 g_qh[(size_t)TT * HID];
__device__ __nv_bfloat16 g_ql[(size_t)TT * HID];
__device__ __nv_bfloat16 g_kh[(size_t)TT * HID];
__device__ __nv_bfloat16 g_kl[(size_t)TT * HID];
__device__ __nv_bfloat16 g_vh[(size_t)TT * HID];
__device__ __nv_bfloat16 g_vl[(size_t)TT * HID];

// ---------------- helpers ----------------
__device__ __forceinline__ uint32_t smem_u32(const void* p) {
    uint32_t a;
    asm("{ .reg .u64 t; cvta.to.shared.u64 t, %1; cvt.u32.u64 %0, t; }"
        : "=r"(a) : "l"(p));
    return a;
}
__device__ __forceinline__ void ldm_x4(uint32_t& r0, uint32_t& r1,
                                       uint32_t& r2, uint32_t& r3, uint32_t a) {
    asm volatile("ldmatrix.sync.aligned.m8n8.x4.shared.b16 {%0,%1,%2,%3}, [%4];"
                 : "=r"(r0), "=r"(r1), "=r"(r2), "=r"(r3) : "r"(a));
}
__device__ __forceinline__ void ldm_x4t(uint32_t& r0, uint32_t& r1,
                                        uint32_t& r2, uint32_t& r3, uint32_t a) {
    asm volatile("ldmatrix.sync.aligned.m8n8.x4.trans.shared.b16 {%0,%1,%2,%3}, [%4];"
                 : "=r"(r0), "=r"(r1), "=r"(r2), "=r"(r3) : "r"(a));
}
__device__ __forceinline__ void mma16816(float* c, const uint32_t* a,
                                         const uint32_t* b) {
    asm volatile(
        "mma.sync.aligned.m16n8k16.row.col.f32.bf16.bf16.f32 "
        "{%0,%1,%2,%3}, {%4,%5,%6,%7}, {%8,%9}, {%0,%1,%2,%3};"
        : "+f"(c[0]), "+f"(c[1]), "+f"(c[2]), "+f"(c[3])
        : "r"(a[0]), "r"(a[1]), "r"(a[2]), "r"(a[3]), "r"(b[0]), "r"(b[1]));
}
__device__ __forceinline__ uint32_t pack_bf16x2(float lo, float hi) {
    __nv_bfloat162 t = __floats2bfloat162_rn(lo, hi);   // x=lo(even col), y=hi
    return *reinterpret_cast<uint32_t*>(&t);
}

// ---------------- 3xBF16 splits: segments along K' -------------------------
__global__ __launch_bounds__(256)
void split_a(const float* __restrict__ in, __nv_bfloat16* __restrict__ out)
{
    size_t i = (size_t)blockIdx.x * 256 + threadIdx.x;
    size_t row = i >> 11;
    size_t k   = i & (HID - 1);
    float a = in[i];
    __nv_bfloat16 hi = __float2bfloat16(a);
    __nv_bfloat16 lo = __float2bfloat16(a - __bfloat162float(hi));
    __nv_bfloat16* o = out + row * KP3;
    o[k]            = hi;
    o[HID + k]      = lo;
    o[2 * HID + k]  = hi;
}
__global__ __launch_bounds__(256)
void split_b(const float* __restrict__ in, __nv_bfloat16* __restrict__ out)
{
    size_t i = (size_t)blockIdx.x * 256 + threadIdx.x;
    size_t row = i >> 11;
    size_t k   = i & (HID - 1);
    float a = in[i];
    __nv_bfloat16 hi = __float2bfloat16(a);
    __nv_bfloat16 lo = __float2bfloat16(a - __bfloat162float(hi));
    __nv_bfloat16* o = out + row * KP3;
    o[k]            = hi;
    o[HID + k]      = hi;
    o[2 * HID + k]  = lo;
}

// ---------------- HMMA GEMM (unchanged from R6) ---------------------------
#define LDA 40
__global__ __launch_bounds__(256)
void gemm_mma(const __nv_bfloat16* __restrict__ A3,
              const __nv_bfloat16* __restrict__ B3,
              const float* __restrict__ bias,
              float* __restrict__ C, int Nstride)
{
    __shared__ __align__(16) __nv_bfloat16 As[2][128 * LDA];
    __shared__ __align__(16) __nv_bfloat16 Bs[2][128 * LDA];

    const int tid  = threadIdx.x;
    const int warp = tid >> 5;
    const int lane = tid & 31;
    const int wm = warp & 1;
    const int wn = warp >> 1;
    const int m0 = blockIdx.y * 128;
    const int n0 = blockIdx.x * 128;

    const int crow0 = tid >> 2;
    const int ckc   = tid & 3;

    float acc[16][4];
#pragma unroll
    for (int i = 0; i < 16; i++)
#pragma unroll
        for (int j = 0; j < 4; j++) acc[i][j] = 0.f;

#define PREF(stage, kt) do {                                                   \
    const __nv_bfloat16* _ab = A3 + (size_t)m0 * KP3 + (size_t)(kt) * 32;      \
    const __nv_bfloat16* _bb = B3 + (size_t)n0 * KP3 + (size_t)(kt) * 32;      \
    _Pragma("unroll")                                                          \
    for (int _i = 0; _i < 2; _i++) {                                           \
        int _row = crow0 + _i * 64;                                            \
        uint32_t _sa = smem_u32(&As[stage][_row * LDA + ckc * 8]);             \
        uint32_t _sb = smem_u32(&Bs[stage][_row * LDA + ckc * 8]);             \
        asm volatile("cp.async.cg.shared.global [%0], [%1], 16;"               \
            :: "r"(_sa), "l"(_ab + (size_t)_row * KP3 + ckc * 8) : "memory");  \
        asm volatile("cp.async.cg.shared.global [%0], [%1], 16;"               \
            :: "r"(_sb), "l"(_bb + (size_t)_row * KP3 + ckc * 8) : "memory");  \
    }                                                                          \
    asm volatile("cp.async.commit_group;" ::: "memory");                       \
} while (0)

    PREF(0, 0);

    const int a_r = lane & 15;
    const int a_c = (lane >> 4) * 8;
    const int b_r = (lane & 7) + ((lane >> 4) & 1) * 8;
    const int b_c = ((lane >> 3) & 1) * 8;

    for (int kt = 0; kt < NIT; kt++) {
        const int buf = kt & 1;
        if (kt + 1 < NIT) PREF(buf ^ 1, kt + 1);
        asm volatile("cp.async.wait_group %0;" :: "n"(1) : "memory");
        if (kt + 1 == NIT)
            asm volatile("cp.async.wait_group 0;" ::: "memory");
        __syncthreads();

#pragma unroll
        for (int s = 0; s < 2; s++) {
            uint32_t a[4][4], b[2][4];
#pragma unroll
            for (int mi = 0; mi < 4; mi++) {
                uint32_t addr = smem_u32(
                    &As[buf][(wm * 64 + mi * 16 + a_r) * LDA + s * 16 + a_c]);
                ldm_x4(a[mi][0], a[mi][1], a[mi][2], a[mi][3], addr);
            }
#pragma unroll
            for (int p = 0; p < 2; p++) {
                uint32_t addr = smem_u32(
                    &Bs[buf][(wn * 32 + p * 16 + b_r) * LDA + s * 16 + b_c]);
                ldm_x4(b[p][0], b[p][1], b[p][2], b[p][3], addr);
            }
#pragma unroll
            for (int mi = 0; mi < 4; mi++)
#pragma unroll
                for (int ni = 0; ni < 4; ni++) {
                    const uint32_t* bf = &b[ni >> 1][(ni & 1) * 2];
                    mma16816(acc[mi * 4 + ni], a[mi], bf);
                }
        }
        __syncthreads();
    }

    const int er = lane >> 2;
    const int ec = (lane & 3) * 2;
#pragma unroll
    for (int mi = 0; mi < 4; mi++) {
        int gm = m0 + wm * 64 + mi * 16 + er;
#pragma unroll
        for (int ni = 0; ni < 4; ni++) {
            int gn = n0 + wn * 32 + ni * 8 + ec;
            float* c = acc[mi * 4 + ni];
            float2 w0, w1;
            w0.x = c[0] + bias[gn];
            w0.y = c[1] + bias[gn + 1];
            w1.x = c[2] + bias[gn];
            w1.y = c[3] + bias[gn + 1];
            *(float2*)(C + (size_t)gm * Nstride + gn) = w0;
            *(float2*)(C + (size_t)(gm + 8) * Nstride + gn) = w1;
        }
    }
}

// ---------------- RoPE + bf16 hi/lo planes + cache scatter -----------------
__global__ __launch_bounds__(256)
void rope_scatter(const float* __restrict__ cosp, const float* __restrict__ sinp,
                  const int* __restrict__ slots,
                  float* __restrict__ kc_out, float* __restrict__ vc_out)
{
    int idx = blockIdx.x * 256 + threadIdx.x;
    int d = idx & (HD - 1);
    int h = (idx >> 7) & (NH - 1);
    int t = idx >> 11;

    const float* base = g_qkv + (size_t)t * QKV_N;
    float qv = base[h * HD + d];
    float kv = base[HID + h * HD + d];
    float vv = base[2 * HID + h * HD + d];

    if (d < ROTD) {
        if (d < HROT) {
            float c = cosp[t * HROT + d];
            float s = sinp[t * HROT + d];
            float q2 = base[h * HD + d + HROT];
            float k2 = base[HID + h * HD + d + HROT];
            qv = qv * c - q2 * s;
            kv = kv * c - k2 * s;
        } else {
            float c = cosp[t * HROT + d - HROT];
            float s = sinp[t * HROT + d - HROT];
            float q1 = base[h * HD + d - HROT];
            float k1 = base[HID + h * HD + d - HROT];
            qv = qv * c + q1 * s;
            kv = kv * c + k1 * s;
        }
    }

    // scale folded into q
    float qs = qv * 0.08838834764831845f;
    __nv_bfloat16 qh = __float2bfloat16(qs);
    g_qh[idx] = qh;
    g_ql[idx] = __float2bfloat16(qs - __bfloat162float(qh));
    __nv_bfloat16 kh = __float2bfloat16(kv);
    g_kh[idx] = kh;
    g_kl[idx] = __float2bfloat16(kv - __bfloat162float(kh));
    __nv_bfloat16 vh = __float2bfloat16(vv);
    g_vh[idx] = vh;
    g_vl[idx] = __float2bfloat16(vv - __bfloat162float(vh));

    int slot = slots[t];
    size_t co = (size_t)slot * (NH * HD) + h * HD + d;
    kc_out[co] = kv;
    vc_out[co] = vv;
}

// ---------------- flash attention v4: HMMA split-bf16 ----------------------
// CTA: 64 q x 64 k tile, 128 threads (4 warps x 16 q-rows).
// S = qh*kh + ql*kh + qh*kl ; O += ph*vh + pl*vh + ph*vl
#define LDT 136   // smem row stride in bf16 (272B, conflict-free for ldmatrix)

__global__ __launch_bounds__(128)
void attn_mma()
{
    extern __shared__ __nv_bfloat16 sb[];
    __nv_bfloat16* Qh = sb;
    __nv_bfloat16* Ql = sb + 1 * 64 * LDT;
    __nv_bfloat16* Kh = sb + 2 * 64 * LDT;
    __nv_bfloat16* Kl = sb + 3 * 64 * LDT;
    __nv_bfloat16* Vh = sb + 4 * 64 * LDT;
    __nv_bfloat16* Vl = sb + 5 * 64 * LDT;

    const int b  = blockIdx.z;
    const int h  = blockIdx.y;
    const int qt = (int)gridDim.x - 1 - (int)blockIdx.x;
    const int tid  = threadIdx.x;
    const int warp = tid >> 5;
    const int lane = tid & 31;

    const int er = lane >> 2;
    const int ec = (lane & 3) * 2;
    const int a_r = lane & 15;
    const int a_c = (lane >> 4) * 8;
    const int b_r = (lane & 7) + ((lane >> 4) & 1) * 8;
    const int b_c = ((lane >> 3) & 1) * 8;
    const int v_r = (lane & 7) + ((lane >> 3) & 1) * 8;
    const int v_c = (lane >> 4) * 8;

    // load Q tile (64 x 128) hi/lo once
    const size_t qgbase = (size_t)(b * SS + qt * 64) * HID + h * HD;
#pragma unroll
    for (int it = 0; it < 8; it++) {
        int idx = tid + it * 128;
        int row = idx >> 4, c8 = idx & 15;
        size_t g = qgbase + (size_t)row * HID + c8 * 8;
        *(float4*)(Qh + row * LDT + c8 * 8) = *(const float4*)(g_qh + g);
        *(float4*)(Ql + row * LDT + c8 * 8) = *(const float4*)(g_ql + g);
    }

    float O[16][4];
#pragma unroll
    for (int i = 0; i < 16; i++)
#pragma unroll
        for (int j = 0; j < 4; j++) O[i][j] = 0.f;
    float m0 = -1e30f, m1 = -1e30f, l0 = 0.f, l1 = 0.f;

    for (int kt = 0; kt <= qt; kt++) {
        __syncthreads();   // protect prev-tile K/V reads
        const size_t kgbase = (size_t)(b * SS + kt * 64) * HID + h * HD;
#pragma unroll
        for (int it = 0; it < 8; it++) {
            int idx = tid + it * 128;
            int row = idx >> 4, c8 = idx & 15;
            size_t g = kgbase + (size_t)row * HID + c8 * 8;
            uint32_t so = row * LDT + c8 * 8;
            *(float4*)(Kh + so) = *(const float4*)(g_kh + g);
            *(float4*)(Kl + so) = *(const float4*)(g_kl + g);
            *(float4*)(Vh + so) = *(const float4*)(g_vh + g);
            *(float4*)(Vl + so) = *(const float4*)(g_vl + g);
        }
        __syncthreads();

        // ---- S = Q K^T (3-term split), warp tile 16 x 64 ----
        float S[8][4];
#pragma unroll
        for (int i = 0; i < 8; i++)
#pragma unroll
            for (int j = 0; j < 4; j++) S[i][j] = 0.f;

#pragma unroll
        for (int ks = 0; ks < 8; ks++) {
            uint32_t qh4[4], ql4[4];
            ldm_x4(qh4[0], qh4[1], qh4[2], qh4[3],
                   smem_u32(&Qh[(warp * 16 + a_r) * LDT + ks * 16 + a_c]));
            ldm_x4(ql4[0], ql4[1], ql4[2], ql4[3],
                   smem_u32(&Ql[(warp * 16 + a_r) * LDT + ks * 16 + a_c]));
            uint32_t kh4[4][4], kl4[4][4];
#pragma unroll
            for (int p = 0; p < 4; p++) {
                ldm_x4(kh4[p][0], kh4[p][1], kh4[p][2], kh4[p][3],
                       smem_u32(&Kh[(p * 16 + b_r) * LDT + ks * 16 + b_c]));
                ldm_x4(kl4[p][0], kl4[p][1], kl4[p][2], kl4[p][3],
                       smem_u32(&Kl[(p * 16 + b_r) * LDT + ks * 16 + b_c]));
            }
#pragma unroll
            for (int ni = 0; ni < 8; ni++) {
                const uint32_t* bh = &kh4[ni >> 1][(ni & 1) * 2];
                const uint32_t* bl = &kl4[ni >> 1][(ni & 1) * 2];
                mma16816(S[ni], qh4, bh);
                mma16816(S[ni], ql4, bh);
                mma16816(S[ni], qh4, bl);
            }
        }

        // ---- causal mask on diagonal tile ----
        if (kt == qt) {
            const int q0 = warp * 16 + er;
            const int q1 = q0 + 8;
#pragma unroll
            for (int ni = 0; ni < 8; ni++) {
                int key = ni * 8 + ec;
                if (key     > q0) S[ni][0] = -1e30f;
                if (key + 1 > q0) S[ni][1] = -1e30f;
                if (key     > q1) S[ni][2] = -1e30f;
                if (key + 1 > q1) S[ni][3] = -1e30f;
            }
        }

        // ---- online softmax (rows er and er+8) ----
        float rx0 = -1e30f, rx1 = -1e30f;
#pragma unroll
        for (int ni = 0; ni < 8; ni++) {
            rx0 = fmaxf(rx0, fmaxf(S[ni][0], S[ni][1]));
            rx1 = fmaxf(rx1, fmaxf(S[ni][2], S[ni][3]));
        }
        rx0 = fmaxf(rx0, __shfl_xor_sync(0xffffffffu, rx0, 1));
        rx0 = fmaxf(rx0, __shfl_xor_sync(0xffffffffu, rx0, 2));
        rx1 = fmaxf(rx1, __shfl_xor_sync(0xffffffffu, rx1, 1));
        rx1 = fmaxf(rx1, __shfl_xor_sync(0xffffffffu, rx1, 2));

        float mn0 = fmaxf(m0, rx0), mn1 = fmaxf(m1, rx1);
        float c0 = __expf(m0 - mn0), c1 = __expf(m1 - mn1);
        l0 *= c0; l1 *= c1;
        m0 = mn0; m1 = mn1;
#pragma unroll
        for (int ni = 0; ni < 16; ni++) {
            O[ni][0] *= c0; O[ni][1] *= c0;
            O[ni][2] *= c1; O[ni][3] *= c1;
        }

        // ---- p = exp(S - m), split into ph/pl fragments for PV ----
        uint32_t PH[4][4], PL[4][4];
        float ls0 = 0.f, ls1 = 0.f;
#pragma unroll
        for (int ni = 0; ni < 8; ni++) {
            float p00 = __expf(S[ni][0] - mn0);
            float p01 = __expf(S[ni][1] - mn0);
            float p10 = __expf(S[ni][2] - mn1);
            float p11 = __expf(S[ni][3] - mn1);
            ls0 += p00 + p01;
            ls1 += p10 + p11;

            __nv_bfloat16 h00 = __float2bfloat16(p00);
            __nv_bfloat16 h01 = __float2bfloat16(p01);
            __nv_bfloat16 h10 = __float2bfloat16(p10);
            __nv_bfloat16 h11 = __float2bfloat16(p11);
            int kk = ni >> 1, base = (ni & 1) * 2;
            PH[kk][base + 0] = pack_bf16x2(__bfloat162float(h00), __bfloat162float(h01));
            PH[kk][base + 1] = pack_bf16x2(__bfloat162float(h10), __bfloat162float(h11));
            PL[kk][base + 0] = pack_bf16x2(p00 - __bfloat162float(h00),
                                           p01 - __bfloat162float(h01));
            PL[kk][base + 1] = pack_bf16x2(p10 - __bfloat162float(h10),
                                           p11 - __bfloat162float(h11));
        }
        ls0 += __shfl_xor_sync(0xffffffffu, ls0, 1);
        ls0 += __shfl_xor_sync(0xffffffffu, ls0, 2);
        ls1 += __shfl_xor_sync(0xffffffffu, ls1, 1);
        ls1 += __shfl_xor_sync(0xffffffffu, ls1, 2);
        l0 += ls0; l1 += ls1;

        // ---- O += P V (3-term split) ----
#pragma unroll
        for (int kk = 0; kk < 4; kk++) {
#pragma unroll
            for (int dp = 0; dp < 8; dp++) {
                uint32_t vh4[4], vl4[4];
                ldm_x4t(vh4[0], vh4[1], vh4[2], vh4[3],
                        smem_u32(&Vh[(kk * 16 + v_r) * LDT + dp * 16 + v_c]));
                ldm_x4t(vl4[0], vl4[1], vl4[2], vl4[3],
                        smem_u32(&Vl[(kk * 16 + v_r) * LDT + dp * 16 + v_c]));
                mma16816(O[dp * 2],     PH[kk], &vh4[0]);
                mma16816(O[dp * 2],     PL[kk], &vh4[0]);
                mma16816(O[dp * 2],     PH[kk], &vl4[0]);
                mma16816(O[dp * 2 + 1], PH[kk], &vh4[2]);
                mma16816(O[dp * 2 + 1], PL[kk], &vh4[2]);
                mma16816(O[dp * 2 + 1], PH[kk], &vl4[2]);
            }
        }
    }

    // ---- epilogue ----
    float inv0 = 1.f / l0, inv1 = 1.f / l1;
    const size_t tq0 = (size_t)(b * SS + qt * 64 + warp * 16 + er);
    const size_t tq1 = tq0 + 8;
#pragma unroll
    for (int ni = 0; ni < 16; ni++) {
        int d = h * HD + ni * 8 + ec;
        float2 w0, w1;
        w0.x = O[ni][0] * inv0; w0.y = O[ni][1] * inv0;
        w1.x = O[ni][2] * inv1; w1.y = O[ni][3] * inv1;
        *(float2*)(g_attn + tq0 * HID + d) = w0;
        *(float2*)(g_attn + tq1 * HID + d) = w1;
    }
}

// ---------------- launch ----------------
extern "C" void kernel_launch(void* const* d_in, const int* in_sizes, int n_in,
                              void* d_out, int out_size)
{
    const float* hidden  = (const float*)d_in[0];
    const float* cosp    = (const float*)d_in[1];
    const float* sinp    = (const float*)d_in[2];
    const float* w_qkv   = (const float*)d_in[3];
    const float* b_qkv   = (const float*)d_in[4];
    const float* w_dense = (const float*)d_in[5];
    const float* b_dense = (const float*)d_in[6];
    const int*   slots   = (const int*)d_in[9];

    float* out = (float*)d_out;
    float* kc  = out + (size_t)TT * HID;
    float* vc  = kc + (size_t)NSLOTS * NH * HD;

    float *p_qkv, *p_attn;
    __nv_bfloat16 *p_h3, *p_wq3, *p_wd3, *p_a3;
    cudaGetSymbolAddress((void**)&p_qkv,  g_qkv);
    cudaGetSymbolAddress((void**)&p_attn, g_attn);
    cudaGetSymbolAddress((void**)&p_h3,  g_h3);
    cudaGetSymbolAddress((void**)&p_wq3, g_wq3);
    cudaGetSymbolAddress((void**)&p_wd3, g_wd3);
    cudaGetSymbolAddress((void**)&p_a3,  g_a3);

    const int ATTN_SMEM = 6 * 64 * LDT * (int)sizeof(__nv_bfloat16);  // 104448
    static int attr_set = 0;
    if (!attr_set) {
        cudaFuncSetAttribute(attn_mma,
                             cudaFuncAttributeMaxDynamicSharedMemorySize,
                             ATTN_SMEM);
        attr_set = 1;
    }

    // zero both cache regions (contiguous) in ONE memset -> attn lands at ncu idx 5
    cudaMemsetAsync(kc, 0, (size_t)2 * NSLOTS * NH * HD * sizeof(float), 0);

    // splits needed before QKV GEMM
    split_a<<<(TT * HID) / 256, 256>>>(hidden, p_h3);                       // idx 1
    split_b<<<((size_t)QKV_N * HID) / 256, 256>>>(w_qkv, p_wq3);            // idx 2

    // 1) QKV GEMM                                                           // idx 3
    {
        dim3 grid(QKV_N / 128, TT / 128);
        gemm_mma<<<grid, 256>>>(p_h3, p_wq3, b_qkv, p_qkv, QKV_N);
    }

    // 2) RoPE + bf16 planes + cache scatter                                 // idx 4
    rope_scatter<<<(TT * HID) / 256, 256>>>(cosp, sinp, slots, kc, vc);

    // 3) flash attention (HMMA)                                             // idx 5
    {
        dim3 grid(SS / 64, NH, BB);
        attn_mma<<<grid, 128, ATTN_SMEM>>>();
    }

    // 4) dense projection
    split_b<<<((size_t)HID * HID) / 256, 256>>>(w_dense, p_wd3);
    split_a<<<(TT * HID) / 256, 256>>>(p_attn, p_a3);
    {
        dim3 grid(HID / 128, TT / 128);
        gemm_mma<<<grid, 256>>>(p_a3, p_wd3, b_dense, out, HID);
    }
}

// round 8
// speedup vs baseline: 6.6945x; 1.2020x over previous
#include <cuda_runtime.h>
#include <cuda_bf16.h>
#include <stdint.h>
#include <math.h>

// ---------------- fixed problem shape ----------------
#define TT      4096
#define HID     2048
#define NH      16
#define HD      128
#define ROTD    32
#define HROT    16
#define NSLOTS  16384
#define BB      2
#define SS      2048
#define QKV_N   (3*HID)
#define KP3     (3*HID)      // 3xBF16 split K' = 6144
#define BK2     64
#define LDA2    72           // 64 data + 8 pad bf16 -> 144B row stride
#define NIT2    (KP3/BK2)    // 96 iterations

// ---------------- device scratch (no allocs allowed) ----------------
__device__ float g_qkv[(size_t)TT * QKV_N];   // 96 MB
__device__ float g_attn[(size_t)TT * HID];
__device__ __nv_bfloat16 g_h3 [(size_t)TT * KP3];      // hidden  [ah|al|ah]
__device__ __nv_bfloat16 g_wq3[(size_t)QKV_N * KP3];   // w_qkv   [bh|bh|bl]
__device__ __nv_bfloat16 g_wd3[(size_t)HID * KP3];     // w_dense [bh|bh|bl]
__device__ __nv_bfloat16 g_a3 [(size_t)TT * KP3];      // attn    [ah|al|ah]
// attention operand planes (bf16 hi/lo)
__device__ __nv_bfloat16 g_qh[(size_t)TT * HID];
__device__ __nv_bfloat16 g_ql[(size_t)TT * HID];
__device__ __nv_bfloat16 g_kh[(size_t)TT * HID];
__device__ __nv_bfloat16 g_kl[(size_t)TT * HID];
__device__ __nv_bfloat16 g_vh[(size_t)TT * HID];
__device__ __nv_bfloat16 g_vl[(size_t)TT * HID];

// ---------------- helpers ----------------
__device__ __forceinline__ uint32_t smem_u32(const void* p) {
    uint32_t a;
    asm("{ .reg .u64 t; cvta.to.shared.u64 t, %1; cvt.u32.u64 %0, t; }"
        : "=r"(a) : "l"(p));
    return a;
}
__device__ __forceinline__ void ldm_x4(uint32_t& r0, uint32_t& r1,
                                       uint32_t& r2, uint32_t& r3, uint32_t a) {
    asm volatile("ldmatrix.sync.aligned.m8n8.x4.shared.b16 {%0,%1,%2,%3}, [%4];"
                 : "=r"(r0), "=r"(r1), "=r"(r2), "=r"(r3) : "r"(a));
}
__device__ __forceinline__ void ldm_x4t(uint32_t& r0, uint32_t& r1,
                                        uint32_t& r2, uint32_t& r3, uint32_t a) {
    asm volatile("ldmatrix.sync.aligned.m8n8.x4.trans.shared.b16 {%0,%1,%2,%3}, [%4];"
                 : "=r"(r0), "=r"(r1), "=r"(r2), "=r"(r3) : "r"(a));
}
__device__ __forceinline__ void mma16816(float* c, const uint32_t* a,
                                         const uint32_t* b) {
    asm volatile(
        "mma.sync.aligned.m16n8k16.row.col.f32.bf16.bf16.f32 "
        "{%0,%1,%2,%3}, {%4,%5,%6,%7}, {%8,%9}, {%0,%1,%2,%3};"
        : "+f"(c[0]), "+f"(c[1]), "+f"(c[2]), "+f"(c[3])
        : "r"(a[0]), "r"(a[1]), "r"(a[2]), "r"(a[3]), "r"(b[0]), "r"(b[1]));
}
__device__ __forceinline__ uint32_t pack_bf16x2(float lo, float hi) {
    __nv_bfloat162 t = __floats2bfloat162_rn(lo, hi);
    return *reinterpret_cast<uint32_t*>(&t);
}

// ---------------- 3xBF16 splits: segments along K' -------------------------
__global__ __launch_bounds__(256)
void split_a(const float* __restrict__ in, __nv_bfloat16* __restrict__ out)
{
    size_t i = (size_t)blockIdx.x * 256 + threadIdx.x;
    size_t row = i >> 11;
    size_t k   = i & (HID - 1);
    float a = in[i];
    __nv_bfloat16 hi = __float2bfloat16(a);
    __nv_bfloat16 lo = __float2bfloat16(a - __bfloat162float(hi));
    __nv_bfloat16* o = out + row * KP3;
    o[k]            = hi;
    o[HID + k]      = lo;
    o[2 * HID + k]  = hi;
}
__global__ __launch_bounds__(256)
void split_b(const float* __restrict__ in, __nv_bfloat16* __restrict__ out)
{
    size_t i = (size_t)blockIdx.x * 256 + threadIdx.x;
    size_t row = i >> 11;
    size_t k   = i & (HID - 1);
    float a = in[i];
    __nv_bfloat16 hi = __float2bfloat16(a);
    __nv_bfloat16 lo = __float2bfloat16(a - __bfloat162float(hi));
    __nv_bfloat16* o = out + row * KP3;
    o[k]            = hi;
    o[HID + k]      = hi;
    o[2 * HID + k]  = lo;
}

// ---------------- tiny spacer so the GEMM lands in ncu's -s 5 slot ---------
__global__ void nop_kernel() {}

// ---------------- HMMA GEMM v2: BK=64, dynamic smem, fewer syncs -----------
// CTA 128x128, 256 threads = 2(M) x 4(N) warps, warp tile 64x32.
__global__ __launch_bounds__(256)
void gemm_mma(const __nv_bfloat16* __restrict__ A3,
              const __nv_bfloat16* __restrict__ B3,
              const float* __restrict__ bias,
              float* __restrict__ C, int Nstride)
{
    extern __shared__ __nv_bfloat16 sg[];
    __nv_bfloat16* As = sg;                          // [2][128*LDA2]
    __nv_bfloat16* Bs = sg + 2 * 128 * LDA2;

    const int tid  = threadIdx.x;
    const int warp = tid >> 5;
    const int lane = tid & 31;
    const int wm = warp & 1;
    const int wn = warp >> 1;
    const int m0 = blockIdx.y * 128;
    const int n0 = blockIdx.x * 128;

    float acc[16][4];
#pragma unroll
    for (int i = 0; i < 16; i++)
#pragma unroll
        for (int j = 0; j < 4; j++) acc[i][j] = 0.f;

    // copy mapping: chunk c = tid + i*256 (i<4); row = c>>3, col16 = c&7
#define PREF(stage, kt) do {                                                   \
    const __nv_bfloat16* _ab = A3 + (size_t)m0 * KP3 + (size_t)(kt) * BK2;     \
    const __nv_bfloat16* _bb = B3 + (size_t)n0 * KP3 + (size_t)(kt) * BK2;     \
    _Pragma("unroll")                                                          \
    for (int _i = 0; _i < 4; _i++) {                                           \
        int _c   = tid + _i * 256;                                             \
        int _row = _c >> 3;                                                    \
        int _c8  = (_c & 7) * 8;                                               \
        uint32_t _so = (uint32_t)((stage) * 128 * LDA2 + _row * LDA2 + _c8);   \
        asm volatile("cp.async.cg.shared.global [%0], [%1], 16;"               \
            :: "r"(smem_u32(As + _so)),                                        \
               "l"(_ab + (size_t)_row * KP3 + _c8) : "memory");                \
        asm volatile("cp.async.cg.shared.global [%0], [%1], 16;"               \
            :: "r"(smem_u32(Bs + _so)),                                        \
               "l"(_bb + (size_t)_row * KP3 + _c8) : "memory");                \
    }                                                                          \
    asm volatile("cp.async.commit_group;" ::: "memory");                       \
} while (0)

    PREF(0, 0);

    const int a_r = lane & 15;
    const int a_c = (lane >> 4) * 8;
    const int b_r = (lane & 7) + ((lane >> 4) & 1) * 8;
    const int b_c = ((lane >> 3) & 1) * 8;

    // precomputed smem base addresses (ALU trim)
    const uint32_t aBase = smem_u32(As) + (uint32_t)(wm * 64 + a_r) * (LDA2 * 2) + a_c * 2;
    const uint32_t bBase = smem_u32(Bs) + (uint32_t)(wn * 32 + b_r) * (LDA2 * 2) + b_c * 2;
    const uint32_t stageB = 128 * LDA2 * 2;   // bytes per stage

    for (int kt = 0; kt < NIT2; kt++) {
        const int buf = kt & 1;
        if (kt + 1 < NIT2) PREF(buf ^ 1, kt + 1);
        if (kt + 1 < NIT2)
            asm volatile("cp.async.wait_group %0;" :: "n"(1) : "memory");
        else
            asm volatile("cp.async.wait_group 0;" ::: "memory");
        __syncthreads();

        const uint32_t aS = aBase + buf * stageB;
        const uint32_t bS = bBase + buf * stageB;

#pragma unroll
        for (int s = 0; s < 4; s++) {
            uint32_t a[4][4], b[2][4];
#pragma unroll
            for (int mi = 0; mi < 4; mi++)
                ldm_x4(a[mi][0], a[mi][1], a[mi][2], a[mi][3],
                       aS + (uint32_t)(mi * 16) * (LDA2 * 2) + s * 32);
#pragma unroll
            for (int p = 0; p < 2; p++)
                ldm_x4(b[p][0], b[p][1], b[p][2], b[p][3],
                       bS + (uint32_t)(p * 16) * (LDA2 * 2) + s * 32);
#pragma unroll
            for (int mi = 0; mi < 4; mi++)
#pragma unroll
                for (int ni = 0; ni < 4; ni++) {
                    const uint32_t* bf = &b[ni >> 1][(ni & 1) * 2];
                    mma16816(acc[mi * 4 + ni], a[mi], bf);
                }
        }
        __syncthreads();
    }

    const int er = lane >> 2;
    const int ec = (lane & 3) * 2;
#pragma unroll
    for (int mi = 0; mi < 4; mi++) {
        int gm = m0 + wm * 64 + mi * 16 + er;
#pragma unroll
        for (int ni = 0; ni < 4; ni++) {
            int gn = n0 + wn * 32 + ni * 8 + ec;
            float* c = acc[mi * 4 + ni];
            float2 w0, w1;
            w0.x = c[0] + bias[gn];
            w0.y = c[1] + bias[gn + 1];
            w1.x = c[2] + bias[gn];
            w1.y = c[3] + bias[gn + 1];
            *(float2*)(C + (size_t)gm * Nstride + gn) = w0;
            *(float2*)(C + (size_t)(gm + 8) * Nstride + gn) = w1;
        }
    }
}

// ---------------- RoPE + bf16 hi/lo planes + cache scatter -----------------
__global__ __launch_bounds__(256)
void rope_scatter(const float* __restrict__ cosp, const float* __restrict__ sinp,
                  const int* __restrict__ slots,
                  float* __restrict__ kc_out, float* __restrict__ vc_out)
{
    int idx = blockIdx.x * 256 + threadIdx.x;
    int d = idx & (HD - 1);
    int h = (idx >> 7) & (NH - 1);
    int t = idx >> 11;

    const float* base = g_qkv + (size_t)t * QKV_N;
    float qv = base[h * HD + d];
    float kv = base[HID + h * HD + d];
    float vv = base[2 * HID + h * HD + d];

    if (d < ROTD) {
        if (d < HROT) {
            float c = cosp[t * HROT + d];
            float s = sinp[t * HROT + d];
            float q2 = base[h * HD + d + HROT];
            float k2 = base[HID + h * HD + d + HROT];
            qv = qv * c - q2 * s;
            kv = kv * c - k2 * s;
        } else {
            float c = cosp[t * HROT + d - HROT];
            float s = sinp[t * HROT + d - HROT];
            float q1 = base[h * HD + d - HROT];
            float k1 = base[HID + h * HD + d - HROT];
            qv = qv * c + q1 * s;
            kv = kv * c + k1 * s;
        }
    }

    float qs = qv * 0.08838834764831845f;
    __nv_bfloat16 qh = __float2bfloat16(qs);
    g_qh[idx] = qh;
    g_ql[idx] = __float2bfloat16(qs - __bfloat162float(qh));
    __nv_bfloat16 kh = __float2bfloat16(kv);
    g_kh[idx] = kh;
    g_kl[idx] = __float2bfloat16(kv - __bfloat162float(kh));
    __nv_bfloat16 vh = __float2bfloat16(vv);
    g_vh[idx] = vh;
    g_vl[idx] = __float2bfloat16(vv - __bfloat162float(vh));

    int slot = slots[t];
    size_t co = (size_t)slot * (NH * HD) + h * HD + d;
    kc_out[co] = kv;
    vc_out[co] = vv;
}

// ---------------- flash attention v4: HMMA split-bf16 (unchanged) ----------
#define LDT 136

__global__ __launch_bounds__(128)
void attn_mma()
{
    extern __shared__ __nv_bfloat16 sb[];
    __nv_bfloat16* Qh = sb;
    __nv_bfloat16* Ql = sb + 1 * 64 * LDT;
    __nv_bfloat16* Kh = sb + 2 * 64 * LDT;
    __nv_bfloat16* Kl = sb + 3 * 64 * LDT;
    __nv_bfloat16* Vh = sb + 4 * 64 * LDT;
    __nv_bfloat16* Vl = sb + 5 * 64 * LDT;

    const int b  = blockIdx.z;
    const int h  = blockIdx.y;
    const int qt = (int)gridDim.x - 1 - (int)blockIdx.x;
    const int tid  = threadIdx.x;
    const int warp = tid >> 5;
    const int lane = tid & 31;

    const int er = lane >> 2;
    const int ec = (lane & 3) * 2;
    const int a_r = lane & 15;
    const int a_c = (lane >> 4) * 8;
    const int b_r = (lane & 7) + ((lane >> 4) & 1) * 8;
    const int b_c = ((lane >> 3) & 1) * 8;
    const int v_r = (lane & 7) + ((lane >> 3) & 1) * 8;
    const int v_c = (lane >> 4) * 8;

    const size_t qgbase = (size_t)(b * SS + qt * 64) * HID + h * HD;
#pragma unroll
    for (int it = 0; it < 8; it++) {
        int idx = tid + it * 128;
        int row = idx >> 4, c8 = idx & 15;
        size_t g = qgbase + (size_t)row * HID + c8 * 8;
        *(float4*)(Qh + row * LDT + c8 * 8) = *(const float4*)(g_qh + g);
        *(float4*)(Ql + row * LDT + c8 * 8) = *(const float4*)(g_ql + g);
    }

    float O[16][4];
#pragma unroll
    for (int i = 0; i < 16; i++)
#pragma unroll
        for (int j = 0; j < 4; j++) O[i][j] = 0.f;
    float m0 = -1e30f, m1 = -1e30f, l0 = 0.f, l1 = 0.f;

    for (int kt = 0; kt <= qt; kt++) {
        __syncthreads();
        const size_t kgbase = (size_t)(b * SS + kt * 64) * HID + h * HD;
#pragma unroll
        for (int it = 0; it < 8; it++) {
            int idx = tid + it * 128;
            int row = idx >> 4, c8 = idx & 15;
            size_t g = kgbase + (size_t)row * HID + c8 * 8;
            uint32_t so = row * LDT + c8 * 8;
            *(float4*)(Kh + so) = *(const float4*)(g_kh + g);
            *(float4*)(Kl + so) = *(const float4*)(g_kl + g);
            *(float4*)(Vh + so) = *(const float4*)(g_vh + g);
            *(float4*)(Vl + so) = *(const float4*)(g_vl + g);
        }
        __syncthreads();

        float S[8][4];
#pragma unroll
        for (int i = 0; i < 8; i++)
#pragma unroll
            for (int j = 0; j < 4; j++) S[i][j] = 0.f;

#pragma unroll
        for (int ks = 0; ks < 8; ks++) {
            uint32_t qh4[4], ql4[4];
            ldm_x4(qh4[0], qh4[1], qh4[2], qh4[3],
                   smem_u32(&Qh[(warp * 16 + a_r) * LDT + ks * 16 + a_c]));
            ldm_x4(ql4[0], ql4[1], ql4[2], ql4[3],
                   smem_u32(&Ql[(warp * 16 + a_r) * LDT + ks * 16 + a_c]));
            uint32_t kh4[4][4], kl4[4][4];
#pragma unroll
            for (int p = 0; p < 4; p++) {
                ldm_x4(kh4[p][0], kh4[p][1], kh4[p][2], kh4[p][3],
                       smem_u32(&Kh[(p * 16 + b_r) * LDT + ks * 16 + b_c]));
                ldm_x4(kl4[p][0], kl4[p][1], kl4[p][2], kl4[p][3],
                       smem_u32(&Kl[(p * 16 + b_r) * LDT + ks * 16 + b_c]));
            }
#pragma unroll
            for (int ni = 0; ni < 8; ni++) {
                const uint32_t* bh = &kh4[ni >> 1][(ni & 1) * 2];
                const uint32_t* bl = &kl4[ni >> 1][(ni & 1) * 2];
                mma16816(S[ni], qh4, bh);
                mma16816(S[ni], ql4, bh);
                mma16816(S[ni], qh4, bl);
            }
        }

        if (kt == qt) {
            const int q0 = warp * 16 + er;
            const int q1 = q0 + 8;
#pragma unroll
            for (int ni = 0; ni < 8; ni++) {
                int key = ni * 8 + ec;
                if (key     > q0) S[ni][0] = -1e30f;
                if (key + 1 > q0) S[ni][1] = -1e30f;
                if (key     > q1) S[ni][2] = -1e30f;
                if (key + 1 > q1) S[ni][3] = -1e30f;
            }
        }

        float rx0 = -1e30f, rx1 = -1e30f;
#pragma unroll
        for (int ni = 0; ni < 8; ni++) {
            rx0 = fmaxf(rx0, fmaxf(S[ni][0], S[ni][1]));
            rx1 = fmaxf(rx1, fmaxf(S[ni][2], S[ni][3]));
        }
        rx0 = fmaxf(rx0, __shfl_xor_sync(0xffffffffu, rx0, 1));
        rx0 = fmaxf(rx0, __shfl_xor_sync(0xffffffffu, rx0, 2));
        rx1 = fmaxf(rx1, __shfl_xor_sync(0xffffffffu, rx1, 1));
        rx1 = fmaxf(rx1, __shfl_xor_sync(0xffffffffu, rx1, 2));

        float mn0 = fmaxf(m0, rx0), mn1 = fmaxf(m1, rx1);
        float c0 = __expf(m0 - mn0), c1 = __expf(m1 - mn1);
        l0 *= c0; l1 *= c1;
        m0 = mn0; m1 = mn1;
#pragma unroll
        for (int ni = 0; ni < 16; ni++) {
            O[ni][0] *= c0; O[ni][1] *= c0;
            O[ni][2] *= c1; O[ni][3] *= c1;
        }

        uint32_t PH[4][4], PL[4][4];
        float ls0 = 0.f, ls1 = 0.f;
#pragma unroll
        for (int ni = 0; ni < 8; ni++) {
            float p00 = __expf(S[ni][0] - mn0);
            float p01 = __expf(S[ni][1] - mn0);
            float p10 = __expf(S[ni][2] - mn1);
            float p11 = __expf(S[ni][3] - mn1);
            ls0 += p00 + p01;
            ls1 += p10 + p11;

            __nv_bfloat16 h00 = __float2bfloat16(p00);
            __nv_bfloat16 h01 = __float2bfloat16(p01);
            __nv_bfloat16 h10 = __float2bfloat16(p10);
            __nv_bfloat16 h11 = __float2bfloat16(p11);
            int kk = ni >> 1, base = (ni & 1) * 2;
            PH[kk][base + 0] = pack_bf16x2(__bfloat162float(h00), __bfloat162float(h01));
            PH[kk][base + 1] = pack_bf16x2(__bfloat162float(h10), __bfloat162float(h11));
            PL[kk][base + 0] = pack_bf16x2(p00 - __bfloat162float(h00),
                                           p01 - __bfloat162float(h01));
            PL[kk][base + 1] = pack_bf16x2(p10 - __bfloat162float(h10),
                                           p11 - __bfloat162float(h11));
        }
        ls0 += __shfl_xor_sync(0xffffffffu, ls0, 1);
        ls0 += __shfl_xor_sync(0xffffffffu, ls0, 2);
        ls1 += __shfl_xor_sync(0xffffffffu, ls1, 1);
        ls1 += __shfl_xor_sync(0xffffffffu, ls1, 2);
        l0 += ls0; l1 += ls1;

#pragma unroll
        for (int kk = 0; kk < 4; kk++) {
#pragma unroll
            for (int dp = 0; dp < 8; dp++) {
                uint32_t vh4[4], vl4[4];
                ldm_x4t(vh4[0], vh4[1], vh4[2], vh4[3],
                        smem_u32(&Vh[(kk * 16 + v_r) * LDT + dp * 16 + v_c]));
                ldm_x4t(vl4[0], vl4[1], vl4[2], vl4[3],
                        smem_u32(&Vl[(kk * 16 + v_r) * LDT + dp * 16 + v_c]));
                mma16816(O[dp * 2],     PH[kk], &vh4[0]);
                mma16816(O[dp * 2],     PL[kk], &vh4[0]);
                mma16816(O[dp * 2],     PH[kk], &vl4[0]);
                mma16816(O[dp * 2 + 1], PH[kk], &vh4[2]);
                mma16816(O[dp * 2 + 1], PL[kk], &vh4[2]);
                mma16816(O[dp * 2 + 1], PH[kk], &vl4[2]);
            }
        }
    }

    float inv0 = 1.f / l0, inv1 = 1.f / l1;
    const size_t tq0 = (size_t)(b * SS + qt * 64 + warp * 16 + er);
    const size_t tq1 = tq0 + 8;
#pragma unroll
    for (int ni = 0; ni < 16; ni++) {
        int d = h * HD + ni * 8 + ec;
        float2 w0, w1;
        w0.x = O[ni][0] * inv0; w0.y = O[ni][1] * inv0;
        w1.x = O[ni][2] * inv1; w1.y = O[ni][3] * inv1;
        *(float2*)(g_attn + tq0 * HID + d) = w0;
        *(float2*)(g_attn + tq1 * HID + d) = w1;
    }
}

// ---------------- launch ----------------
extern "C" void kernel_launch(void* const* d_in, const int* in_sizes, int n_in,
                              void* d_out, int out_size)
{
    const float* hidden  = (const float*)d_in[0];
    const float* cosp    = (const float*)d_in[1];
    const float* sinp    = (const float*)d_in[2];
    const float* w_qkv   = (const float*)d_in[3];
    const float* b_qkv   = (const float*)d_in[4];
    const float* w_dense = (const float*)d_in[5];
    const float* b_dense = (const float*)d_in[6];
    const int*   slots   = (const int*)d_in[9];

    float* out = (float*)d_out;
    float* kc  = out + (size_t)TT * HID;
    float* vc  = kc + (size_t)NSLOTS * NH * HD;

    float *p_qkv, *p_attn;
    __nv_bfloat16 *p_h3, *p_wq3, *p_wd3, *p_a3;
    cudaGetSymbolAddress((void**)&p_qkv,  g_qkv);
    cudaGetSymbolAddress((void**)&p_attn, g_attn);
    cudaGetSymbolAddress((void**)&p_h3,  g_h3);
    cudaGetSymbolAddress((void**)&p_wq3, g_wq3);
    cudaGetSymbolAddress((void**)&p_wd3, g_wd3);
    cudaGetSymbolAddress((void**)&p_a3,  g_a3);

    const int ATTN_SMEM = 6 * 64 * LDT * (int)sizeof(__nv_bfloat16);   // 104448
    const int GEMM_SMEM = 4 * 128 * LDA2 * (int)sizeof(__nv_bfloat16); // 73728
    static int attr_set = 0;
    if (!attr_set) {
        cudaFuncSetAttribute(attn_mma,
                             cudaFuncAttributeMaxDynamicSharedMemorySize,
                             ATTN_SMEM);
        cudaFuncSetAttribute(gemm_mma,
                             cudaFuncAttributeMaxDynamicSharedMemorySize,
                             GEMM_SMEM);
        attr_set = 1;
    }

    // zero both cache regions (contiguous) in one memset
    cudaMemsetAsync(kc, 0, (size_t)2 * NSLOTS * NH * HD * sizeof(float), 0);

    split_a<<<(TT * HID) / 256, 256>>>(hidden, p_h3);
    split_b<<<((size_t)QKV_N * HID) / 256, 256>>>(w_qkv, p_wq3);

    // spacer: pushes the QKV GEMM to ncu launch idx 5
    nop_kernel<<<1, 32>>>();

    // 1) QKV GEMM
    {
        dim3 grid(QKV_N / 128, TT / 128);
        gemm_mma<<<grid, 256, GEMM_SMEM>>>(p_h3, p_wq3, b_qkv, p_qkv, QKV_N);
    }

    // 2) RoPE + bf16 planes + cache scatter
    rope_scatter<<<(TT * HID) / 256, 256>>>(cosp, sinp, slots, kc, vc);

    // 3) flash attention (HMMA)
    {
        dim3 grid(SS / 64, NH, BB);
        attn_mma<<<grid, 128, ATTN_SMEM>>>();
    }

    // 4) dense projection
    split_b<<<((size_t)HID * HID) / 256, 256>>>(w_dense, p_wd3);
    split_a<<<(TT * HID) / 256, 256>>>(p_attn, p_a3);
    {
        dim3 grid(HID / 128, TT / 128);
        gemm_mma<<<grid, 256, GEMM_SMEM>>>(p_a3, p_wd3, b_dense, out, HID);
    }
}

// round 9
// speedup vs baseline: 6.9549x; 1.0389x over previous
#include <cuda_runtime.h>
#include <cuda_bf16.h>
#include <stdint.h>
#include <math.h>

// ---------------- fixed problem shape ----------------
#define TT      4096
#define HID     2048
#define NH      16
#define HD      128
#define ROTD    32
#define HROT    16
#define NSLOTS  16384
#define BB      2
#define SS      2048
#define QKV_N   (3*HID)
#define KP3     (3*HID)      // 3xBF16 split K' = 6144
#define BK2     64
#define LDA2    72           // 64 data + 8 pad bf16 -> 144B row stride
#define NIT2    (KP3/BK2)    // 96 iterations

// ---------------- device scratch (no allocs allowed) ----------------
__device__ float g_qkv[(size_t)TT * QKV_N];   // 96 MB
__device__ float g_attn[(size_t)TT * HID];
__device__ __nv_bfloat16 g_h3 [(size_t)TT * KP3];      // hidden  [ah|al|ah]
__device__ __nv_bfloat16 g_wq3[(size_t)QKV_N * KP3];   // w_qkv   [bh|bh|bl]
__device__ __nv_bfloat16 g_wd3[(size_t)HID * KP3];     // w_dense [bh|bh|bl]
__device__ __nv_bfloat16 g_a3 [(size_t)TT * KP3];      // attn    [ah|al|ah]
// attention operand planes (bf16 hi/lo)
__device__ __nv_bfloat16 g_qh[(size_t)TT * HID];
__device__ __nv_bfloat16 g_ql[(size_t)TT * HID];
__device__ __nv_bfloat16 g_kh[(size_t)TT * HID];
__device__ __nv_bfloat16 g_kl[(size_t)TT * HID];
__device__ __nv_bfloat16 g_vh[(size_t)TT * HID];
__device__ __nv_bfloat16 g_vl[(size_t)TT * HID];

// ---------------- helpers ----------------
__device__ __forceinline__ uint32_t smem_u32(const void* p) {
    uint32_t a;
    asm("{ .reg .u64 t; cvta.to.shared.u64 t, %1; cvt.u32.u64 %0, t; }"
        : "=r"(a) : "l"(p));
    return a;
}
__device__ __forceinline__ void ldm_x4(uint32_t& r0, uint32_t& r1,
                                       uint32_t& r2, uint32_t& r3, uint32_t a) {
    asm volatile("ldmatrix.sync.aligned.m8n8.x4.shared.b16 {%0,%1,%2,%3}, [%4];"
                 : "=r"(r0), "=r"(r1), "=r"(r2), "=r"(r3) : "r"(a));
}
__device__ __forceinline__ void ldm_x4t(uint32_t& r0, uint32_t& r1,
                                        uint32_t& r2, uint32_t& r3, uint32_t a) {
    asm volatile("ldmatrix.sync.aligned.m8n8.x4.trans.shared.b16 {%0,%1,%2,%3}, [%4];"
                 : "=r"(r0), "=r"(r1), "=r"(r2), "=r"(r3) : "r"(a));
}
__device__ __forceinline__ void mma16816(float* c, const uint32_t* a,
                                         const uint32_t* b) {
    asm volatile(
        "mma.sync.aligned.m16n8k16.row.col.f32.bf16.bf16.f32 "
        "{%0,%1,%2,%3}, {%4,%5,%6,%7}, {%8,%9}, {%0,%1,%2,%3};"
        : "+f"(c[0]), "+f"(c[1]), "+f"(c[2]), "+f"(c[3])
        : "r"(a[0]), "r"(a[1]), "r"(a[2]), "r"(a[3]), "r"(b[0]), "r"(b[1]));
}
__device__ __forceinline__ uint32_t pack_bf16x2(float lo, float hi) {
    __nv_bfloat162 t = __floats2bfloat162_rn(lo, hi);
    return *reinterpret_cast<uint32_t*>(&t);
}

// ---------------- 3xBF16 splits: segments along K' -------------------------
__global__ __launch_bounds__(256)
void split_a(const float* __restrict__ in, __nv_bfloat16* __restrict__ out)
{
    size_t i = (size_t)blockIdx.x * 256 + threadIdx.x;
    size_t row = i >> 11;
    size_t k   = i & (HID - 1);
    float a = in[i];
    __nv_bfloat16 hi = __float2bfloat16(a);
    __nv_bfloat16 lo = __float2bfloat16(a - __bfloat162float(hi));
    __nv_bfloat16* o = out + row * KP3;
    o[k]            = hi;
    o[HID + k]      = lo;
    o[2 * HID + k]  = hi;
}
__global__ __launch_bounds__(256)
void split_b(const float* __restrict__ in, __nv_bfloat16* __restrict__ out)
{
    size_t i = (size_t)blockIdx.x * 256 + threadIdx.x;
    size_t row = i >> 11;
    size_t k   = i & (HID - 1);
    float a = in[i];
    __nv_bfloat16 hi = __float2bfloat16(a);
    __nv_bfloat16 lo = __float2bfloat16(a - __bfloat162float(hi));
    __nv_bfloat16* o = out + row * KP3;
    o[k]            = hi;
    o[HID + k]      = hi;
    o[2 * HID + k]  = lo;
}

// ---------------- tiny spacer to keep the GEMM in ncu's -s 5 slot ----------
__global__ void nop_kernel() {}

// ---------------- HMMA GEMM v3: warp tile 64x64, 128 threads ---------------
// CTA 128x128, 4 warps = 2(M) x 2(N), BK=64, cp.async double buffer.
__global__ __launch_bounds__(128)
void gemm_mma(const __nv_bfloat16* __restrict__ A3,
              const __nv_bfloat16* __restrict__ B3,
              const float* __restrict__ bias,
              float* __restrict__ C, int Nstride)
{
    extern __shared__ __nv_bfloat16 sg[];
    __nv_bfloat16* As = sg;                          // [2][128*LDA2]
    __nv_bfloat16* Bs = sg + 2 * 128 * LDA2;

    const int tid  = threadIdx.x;
    const int warp = tid >> 5;
    const int lane = tid & 31;
    const int wm = warp & 1;        // 0..1  (M)
    const int wn = warp >> 1;       // 0..1  (N)
    const int m0 = blockIdx.y * 128;
    const int n0 = blockIdx.x * 128;

    float acc[32][4];
#pragma unroll
    for (int i = 0; i < 32; i++)
#pragma unroll
        for (int j = 0; j < 4; j++) acc[i][j] = 0.f;

    // copy mapping: chunk c = tid + i*128 (i<8); row = c>>3, col16 = c&7
#define PREF(stage, kt) do {                                                   \
    const __nv_bfloat16* _ab = A3 + (size_t)m0 * KP3 + (size_t)(kt) * BK2;     \
    const __nv_bfloat16* _bb = B3 + (size_t)n0 * KP3 + (size_t)(kt) * BK2;     \
    _Pragma("unroll")                                                          \
    for (int _i = 0; _i < 8; _i++) {                                           \
        int _c   = tid + _i * 128;                                             \
        int _row = _c >> 3;                                                    \
        int _c8  = (_c & 7) * 8;                                               \
        uint32_t _so = (uint32_t)((stage) * 128 * LDA2 + _row * LDA2 + _c8);   \
        asm volatile("cp.async.cg.shared.global [%0], [%1], 16;"               \
            :: "r"(smem_u32(As + _so)),                                        \
               "l"(_ab + (size_t)_row * KP3 + _c8) : "memory");                \
        asm volatile("cp.async.cg.shared.global [%0], [%1], 16;"               \
            :: "r"(smem_u32(Bs + _so)),                                        \
               "l"(_bb + (size_t)_row * KP3 + _c8) : "memory");                \
    }                                                                          \
    asm volatile("cp.async.commit_group;" ::: "memory");                       \
} while (0)

    PREF(0, 0);

    const int a_r = lane & 15;
    const int a_c = (lane >> 4) * 8;
    const int b_r = (lane & 7) + ((lane >> 4) & 1) * 8;
    const int b_c = ((lane >> 3) & 1) * 8;

    const uint32_t aBase = smem_u32(As) + (uint32_t)(wm * 64 + a_r) * (LDA2 * 2) + a_c * 2;
    const uint32_t bBase = smem_u32(Bs) + (uint32_t)(wn * 64 + b_r) * (LDA2 * 2) + b_c * 2;
    const uint32_t stageB = 128 * LDA2 * 2;   // bytes per stage

    for (int kt = 0; kt < NIT2; kt++) {
        const int buf = kt & 1;
        if (kt + 1 < NIT2) PREF(buf ^ 1, kt + 1);
        if (kt + 1 < NIT2)
            asm volatile("cp.async.wait_group %0;" :: "n"(1) : "memory");
        else
            asm volatile("cp.async.wait_group 0;" ::: "memory");
        __syncthreads();

        const uint32_t aS = aBase + buf * stageB;
        const uint32_t bS = bBase + buf * stageB;

#pragma unroll
        for (int s = 0; s < 4; s++) {
            uint32_t a[4][4], b[4][4];
#pragma unroll
            for (int mi = 0; mi < 4; mi++)
                ldm_x4(a[mi][0], a[mi][1], a[mi][2], a[mi][3],
                       aS + (uint32_t)(mi * 16) * (LDA2 * 2) + s * 32);
#pragma unroll
            for (int p = 0; p < 4; p++)
                ldm_x4(b[p][0], b[p][1], b[p][2], b[p][3],
                       bS + (uint32_t)(p * 16) * (LDA2 * 2) + s * 32);
#pragma unroll
            for (int mi = 0; mi < 4; mi++)
#pragma unroll
                for (int ni = 0; ni < 8; ni++) {
                    const uint32_t* bf = &b[ni >> 1][(ni & 1) * 2];
                    mma16816(acc[mi * 8 + ni], a[mi], bf);
                }
        }
        __syncthreads();
    }

    const int er = lane >> 2;
    const int ec = (lane & 3) * 2;
#pragma unroll
    for (int mi = 0; mi < 4; mi++) {
        int gm = m0 + wm * 64 + mi * 16 + er;
#pragma unroll
        for (int ni = 0; ni < 8; ni++) {
            int gn = n0 + wn * 64 + ni * 8 + ec;
            float* c = acc[mi * 8 + ni];
            float2 w0, w1;
            w0.x = c[0] + bias[gn];
            w0.y = c[1] + bias[gn + 1];
            w1.x = c[2] + bias[gn];
            w1.y = c[3] + bias[gn + 1];
            *(float2*)(C + (size_t)gm * Nstride + gn) = w0;
            *(float2*)(C + (size_t)(gm + 8) * Nstride + gn) = w1;
        }
    }
}

// ---------------- RoPE + bf16 hi/lo planes + cache scatter -----------------
__global__ __launch_bounds__(256)
void rope_scatter(const float* __restrict__ cosp, const float* __restrict__ sinp,
                  const int* __restrict__ slots,
                  float* __restrict__ kc_out, float* __restrict__ vc_out)
{
    int idx = blockIdx.x * 256 + threadIdx.x;
    int d = idx & (HD - 1);
    int h = (idx >> 7) & (NH - 1);
    int t = idx >> 11;

    const float* base = g_qkv + (size_t)t * QKV_N;
    float qv = base[h * HD + d];
    float kv = base[HID + h * HD + d];
    float vv = base[2 * HID + h * HD + d];

    if (d < ROTD) {
        if (d < HROT) {
            float c = cosp[t * HROT + d];
            float s = sinp[t * HROT + d];
            float q2 = base[h * HD + d + HROT];
            float k2 = base[HID + h * HD + d + HROT];
            qv = qv * c - q2 * s;
            kv = kv * c - k2 * s;
        } else {
            float c = cosp[t * HROT + d - HROT];
            float s = sinp[t * HROT + d - HROT];
            float q1 = base[h * HD + d - HROT];
            float k1 = base[HID + h * HD + d - HROT];
            qv = qv * c + q1 * s;
            kv = kv * c + k1 * s;
        }
    }

    float qs = qv * 0.08838834764831845f;
    __nv_bfloat16 qh = __float2bfloat16(qs);
    g_qh[idx] = qh;
    g_ql[idx] = __float2bfloat16(qs - __bfloat162float(qh));
    __nv_bfloat16 kh = __float2bfloat16(kv);
    g_kh[idx] = kh;
    g_kl[idx] = __float2bfloat16(kv - __bfloat162float(kh));
    __nv_bfloat16 vh = __float2bfloat16(vv);
    g_vh[idx] = vh;
    g_vl[idx] = __float2bfloat16(vv - __bfloat162float(vh));

    int slot = slots[t];
    size_t co = (size_t)slot * (NH * HD) + h * HD + d;
    kc_out[co] = kv;
    vc_out[co] = vv;
}

// ---------------- flash attention v4: HMMA split-bf16 (unchanged) ----------
#define LDT 136

__global__ __launch_bounds__(128)
void attn_mma()
{
    extern __shared__ __nv_bfloat16 sb[];
    __nv_bfloat16* Qh = sb;
    __nv_bfloat16* Ql = sb + 1 * 64 * LDT;
    __nv_bfloat16* Kh = sb + 2 * 64 * LDT;
    __nv_bfloat16* Kl = sb + 3 * 64 * LDT;
    __nv_bfloat16* Vh = sb + 4 * 64 * LDT;
    __nv_bfloat16* Vl = sb + 5 * 64 * LDT;

    const int b  = blockIdx.z;
    const int h  = blockIdx.y;
    const int qt = (int)gridDim.x - 1 - (int)blockIdx.x;
    const int tid  = threadIdx.x;
    const int warp = tid >> 5;
    const int lane = tid & 31;

    const int er = lane >> 2;
    const int ec = (lane & 3) * 2;
    const int a_r = lane & 15;
    const int a_c = (lane >> 4) * 8;
    const int b_r = (lane & 7) + ((lane >> 4) & 1) * 8;
    const int b_c = ((lane >> 3) & 1) * 8;
    const int v_r = (lane & 7) + ((lane >> 3) & 1) * 8;
    const int v_c = (lane >> 4) * 8;

    const size_t qgbase = (size_t)(b * SS + qt * 64) * HID + h * HD;
#pragma unroll
    for (int it = 0; it < 8; it++) {
        int idx = tid + it * 128;
        int row = idx >> 4, c8 = idx & 15;
        size_t g = qgbase + (size_t)row * HID + c8 * 8;
        *(float4*)(Qh + row * LDT + c8 * 8) = *(const float4*)(g_qh + g);
        *(float4*)(Ql + row * LDT + c8 * 8) = *(const float4*)(g_ql + g);
    }

    float O[16][4];
#pragma unroll
    for (int i = 0; i < 16; i++)
#pragma unroll
        for (int j = 0; j < 4; j++) O[i][j] = 0.f;
    float m0 = -1e30f, m1 = -1e30f, l0 = 0.f, l1 = 0.f;

    for (int kt = 0; kt <= qt; kt++) {
        __syncthreads();
        const size_t kgbase = (size_t)(b * SS + kt * 64) * HID + h * HD;
#pragma unroll
        for (int it = 0; it < 8; it++) {
            int idx = tid + it * 128;
            int row = idx >> 4, c8 = idx & 15;
            size_t g = kgbase + (size_t)row * HID + c8 * 8;
            uint32_t so = row * LDT + c8 * 8;
            *(float4*)(Kh + so) = *(const float4*)(g_kh + g);
            *(float4*)(Kl + so) = *(const float4*)(g_kl + g);
            *(float4*)(Vh + so) = *(const float4*)(g_vh + g);
            *(float4*)(Vl + so) = *(const float4*)(g_vl + g);
        }
        __syncthreads();

        float S[8][4];
#pragma unroll
        for (int i = 0; i < 8; i++)
#pragma unroll
            for (int j = 0; j < 4; j++) S[i][j] = 0.f;

#pragma unroll
        for (int ks = 0; ks < 8; ks++) {
            uint32_t qh4[4], ql4[4];
            ldm_x4(qh4[0], qh4[1], qh4[2], qh4[3],
                   smem_u32(&Qh[(warp * 16 + a_r) * LDT + ks * 16 + a_c]));
            ldm_x4(ql4[0], ql4[1], ql4[2], ql4[3],
                   smem_u32(&Ql[(warp * 16 + a_r) * LDT + ks * 16 + a_c]));
            uint32_t kh4[4][4], kl4[4][4];
#pragma unroll
            for (int p = 0; p < 4; p++) {
                ldm_x4(kh4[p][0], kh4[p][1], kh4[p][2], kh4[p][3],
                       smem_u32(&Kh[(p * 16 + b_r) * LDT + ks * 16 + b_c]));
                ldm_x4(kl4[p][0], kl4[p][1], kl4[p][2], kl4[p][3],
                       smem_u32(&Kl[(p * 16 + b_r) * LDT + ks * 16 + b_c]));
            }
#pragma unroll
            for (int ni = 0; ni < 8; ni++) {
                const uint32_t* bh = &kh4[ni >> 1][(ni & 1) * 2];
                const uint32_t* bl = &kl4[ni >> 1][(ni & 1) * 2];
                mma16816(S[ni], qh4, bh);
                mma16816(S[ni], ql4, bh);
                mma16816(S[ni], qh4, bl);
            }
        }

        if (kt == qt) {
            const int q0 = warp * 16 + er;
            const int q1 = q0 + 8;
#pragma unroll
            for (int ni = 0; ni < 8; ni++) {
                int key = ni * 8 + ec;
                if (key     > q0) S[ni][0] = -1e30f;
                if (key + 1 > q0) S[ni][1] = -1e30f;
                if (key     > q1) S[ni][2] = -1e30f;
                if (key + 1 > q1) S[ni][3] = -1e30f;
            }
        }

        float rx0 = -1e30f, rx1 = -1e30f;
#pragma unroll
        for (int ni = 0; ni < 8; ni++) {
            rx0 = fmaxf(rx0, fmaxf(S[ni][0], S[ni][1]));
            rx1 = fmaxf(rx1, fmaxf(S[ni][2], S[ni][3]));
        }
        rx0 = fmaxf(rx0, __shfl_xor_sync(0xffffffffu, rx0, 1));
        rx0 = fmaxf(rx0, __shfl_xor_sync(0xffffffffu, rx0, 2));
        rx1 = fmaxf(rx1, __shfl_xor_sync(0xffffffffu, rx1, 1));
        rx1 = fmaxf(rx1, __shfl_xor_sync(0xffffffffu, rx1, 2));

        float mn0 = fmaxf(m0, rx0), mn1 = fmaxf(m1, rx1);
        float c0 = __expf(m0 - mn0), c1 = __expf(m1 - mn1);
        l0 *= c0; l1 *= c1;
        m0 = mn0; m1 = mn1;
#pragma unroll
        for (int ni = 0; ni < 16; ni++) {
            O[ni][0] *= c0; O[ni][1] *= c0;
            O[ni][2] *= c1; O[ni][3] *= c1;
        }

        uint32_t PH[4][4], PL[4][4];
        float ls0 = 0.f, ls1 = 0.f;
#pragma unroll
        for (int ni = 0; ni < 8; ni++) {
            float p00 = __expf(S[ni][0] - mn0);
            float p01 = __expf(S[ni][1] - mn0);
            float p10 = __expf(S[ni][2] - mn1);
            float p11 = __expf(S[ni][3] - mn1);
            ls0 += p00 + p01;
            ls1 += p10 + p11;

            __nv_bfloat16 h00 = __float2bfloat16(p00);
            __nv_bfloat16 h01 = __float2bfloat16(p01);
            __nv_bfloat16 h10 = __float2bfloat16(p10);
            __nv_bfloat16 h11 = __float2bfloat16(p11);
            int kk = ni >> 1, base = (ni & 1) * 2;
            PH[kk][base + 0] = pack_bf16x2(__bfloat162float(h00), __bfloat162float(h01));
            PH[kk][base + 1] = pack_bf16x2(__bfloat162float(h10), __bfloat162float(h11));
            PL[kk][base + 0] = pack_bf16x2(p00 - __bfloat162float(h00),
                                           p01 - __bfloat162float(h01));
            PL[kk][base + 1] = pack_bf16x2(p10 - __bfloat162float(h10),
                                           p11 - __bfloat162float(h11));
        }
        ls0 += __shfl_xor_sync(0xffffffffu, ls0, 1);
        ls0 += __shfl_xor_sync(0xffffffffu, ls0, 2);
        ls1 += __shfl_xor_sync(0xffffffffu, ls1, 1);
        ls1 += __shfl_xor_sync(0xffffffffu, ls1, 2);
        l0 += ls0; l1 += ls1;

#pragma unroll
        for (int kk = 0; kk < 4; kk++) {
#pragma unroll
            for (int dp = 0; dp < 8; dp++) {
                uint32_t vh4[4], vl4[4];
                ldm_x4t(vh4[0], vh4[1], vh4[2], vh4[3],
                        smem_u32(&Vh[(kk * 16 + v_r) * LDT + dp * 16 + v_c]));
                ldm_x4t(vl4[0], vl4[1], vl4[2], vl4[3],
                        smem_u32(&Vl[(kk * 16 + v_r) * LDT + dp * 16 + v_c]));
                mma16816(O[dp * 2],     PH[kk], &vh4[0]);
                mma16816(O[dp * 2],     PL[kk], &vh4[0]);
                mma16816(O[dp * 2],     PH[kk], &vl4[0]);
                mma16816(O[dp * 2 + 1], PH[kk], &vh4[2]);
                mma16816(O[dp * 2 + 1], PL[kk], &vh4[2]);
                mma16816(O[dp * 2 + 1], PH[kk], &vl4[2]);
            }
        }
    }

    float inv0 = 1.f / l0, inv1 = 1.f / l1;
    const size_t tq0 = (size_t)(b * SS + qt * 64 + warp * 16 + er);
    const size_t tq1 = tq0 + 8;
#pragma unroll
    for (int ni = 0; ni < 16; ni++) {
        int d = h * HD + ni * 8 + ec;
        float2 w0, w1;
        w0.x = O[ni][0] * inv0; w0.y = O[ni][1] * inv0;
        w1.x = O[ni][2] * inv1; w1.y = O[ni][3] * inv1;
        *(float2*)(g_attn + tq0 * HID + d) = w0;
        *(float2*)(g_attn + tq1 * HID + d) = w1;
    }
}

// ---------------- launch ----------------
extern "C" void kernel_launch(void* const* d_in, const int* in_sizes, int n_in,
                              void* d_out, int out_size)
{
    const float* hidden  = (const float*)d_in[0];
    const float* cosp    = (const float*)d_in[1];
    const float* sinp    = (const float*)d_in[2];
    const float* w_qkv   = (const float*)d_in[3];
    const float* b_qkv   = (const float*)d_in[4];
    const float* w_dense = (const float*)d_in[5];
    const float* b_dense = (const float*)d_in[6];
    const int*   slots   = (const int*)d_in[9];

    float* out = (float*)d_out;
    float* kc  = out + (size_t)TT * HID;
    float* vc  = kc + (size_t)NSLOTS * NH * HD;

    float *p_qkv, *p_attn;
    __nv_bfloat16 *p_h3, *p_wq3, *p_wd3, *p_a3;
    cudaGetSymbolAddress((void**)&p_qkv,  g_qkv);
    cudaGetSymbolAddress((void**)&p_attn, g_attn);
    cudaGetSymbolAddress((void**)&p_h3,  g_h3);
    cudaGetSymbolAddress((void**)&p_wq3, g_wq3);
    cudaGetSymbolAddress((void**)&p_wd3, g_wd3);
    cudaGetSymbolAddress((void**)&p_a3,  g_a3);

    const int ATTN_SMEM = 6 * 64 * LDT * (int)sizeof(__nv_bfloat16);   // 104448
    const int GEMM_SMEM = 4 * 128 * LDA2 * (int)sizeof(__nv_bfloat16); // 73728
    static int attr_set = 0;
    if (!attr_set) {
        cudaFuncSetAttribute(attn_mma,
                             cudaFuncAttributeMaxDynamicSharedMemorySize,
                             ATTN_SMEM);
        cudaFuncSetAttribute(gemm_mma,
                             cudaFuncAttributeMaxDynamicSharedMemorySize,
                             GEMM_SMEM);
        attr_set = 1;
    }

    // zero both cache regions (contiguous) in one memset
    cudaMemsetAsync(kc, 0, (size_t)2 * NSLOTS * NH * HD * sizeof(float), 0);

    split_a<<<(TT * HID) / 256, 256>>>(hidden, p_h3);
    split_b<<<((size_t)QKV_N * HID) / 256, 256>>>(w_qkv, p_wq3);

    // spacer: keeps the QKV GEMM at ncu launch idx 5
    nop_kernel<<<1, 32>>>();

    // 1) QKV GEMM
    {
        dim3 grid(QKV_N / 128, TT / 128);
        gemm_mma<<<grid, 128, GEMM_SMEM>>>(p_h3, p_wq3, b_qkv, p_qkv, QKV_N);
    }

    // 2) RoPE + bf16 planes + cache scatter
    rope_scatter<<<(TT * HID) / 256, 256>>>(cosp, sinp, slots, kc, vc);

    // 3) flash attention (HMMA)
    {
        dim3 grid(SS / 64, NH, BB);
        attn_mma<<<grid, 128, ATTN_SMEM>>>();
    }

    // 4) dense projection
    split_b<<<((size_t)HID * HID) / 256, 256>>>(w_dense, p_wd3);
    split_a<<<(TT * HID) / 256, 256>>>(p_attn, p_a3);
    {
        dim3 grid(HID / 128, TT / 128);
        gemm_mma<<<grid, 128, GEMM_SMEM>>>(p_a3, p_wd3, b_dense, out, HID);
    }
}

// round 11
// speedup vs baseline: 7.2460x; 1.0419x over previous
#include <cuda_runtime.h>
#include <cuda_bf16.h>
#include <stdint.h>
#include <math.h>

// ---------------- fixed problem shape ----------------
#define TT      4096
#define HID     2048
#define NH      16
#define HD      128
#define ROTD    32
#define HROT    16
#define NSLOTS  16384
#define BB      2
#define SS      2048
#define QKV_N   (3*HID)
#define KP3     (3*HID)      // 3xBF16 split K' = 6144
#define BK2     64
#define NIT2    (KP3/BK2)    // 96 iterations
#define NSTG    3            // cp.async pipeline depth
#define STG_EL  (128*64)     // bf16 elements per matrix-stage (no pad, swizzled)
#define STG_BYTES (STG_EL*2) // 16384

// ---------------- device scratch (no allocs allowed) ----------------
__device__ float g_qkv[(size_t)TT * QKV_N];   // 96 MB
__device__ float g_attn[(size_t)TT * HID];
__device__ __nv_bfloat16 g_h3 [(size_t)TT * KP3];      // hidden  [ah|al|ah]
__device__ __nv_bfloat16 g_wq3[(size_t)QKV_N * KP3];   // w_qkv   [bh|bh|bl]
__device__ __nv_bfloat16 g_wd3[(size_t)HID * KP3];     // w_dense [bh|bh|bl]
__device__ __nv_bfloat16 g_a3 [(size_t)TT * KP3];      // attn    [ah|al|ah]
// attention operand planes (bf16 hi/lo)
__device__ __nv_bfloat16 g_qh[(size_t)TT * HID];
__device__ __nv_bfloat16 g_ql[(size_t)TT * HID];
__device__ __nv_bfloat16 g_kh[(size_t)TT * HID];
__device__ __nv_bfloat16 g_kl[(size_t)TT * HID];
__device__ __nv_bfloat16 g_vh[(size_t)TT * HID];
__device__ __nv_bfloat16 g_vl[(size_t)TT * HID];

// ---------------- helpers ----------------
__device__ __forceinline__ uint32_t smem_u32(const void* p) {
    uint32_t a;
    asm("{ .reg .u64 t; cvta.to.shared.u64 t, %1; cvt.u32.u64 %0, t; }"
        : "=r"(a) : "l"(p));
    return a;
}
__device__ __forceinline__ void ldm_x4(uint32_t& r0, uint32_t& r1,
                                       uint32_t& r2, uint32_t& r3, uint32_t a) {
    asm volatile("ldmatrix.sync.aligned.m8n8.x4.shared.b16 {%0,%1,%2,%3}, [%4];"
                 : "=r"(r0), "=r"(r1), "=r"(r2), "=r"(r3) : "r"(a));
}
__device__ __forceinline__ void ldm_x4t(uint32_t& r0, uint32_t& r1,
                                        uint32_t& r2, uint32_t& r3, uint32_t a) {
    asm volatile("ldmatrix.sync.aligned.m8n8.x4.trans.shared.b16 {%0,%1,%2,%3}, [%4];"
                 : "=r"(r0), "=r"(r1), "=r"(r2), "=r"(r3) : "r"(a));
}
__device__ __forceinline__ void mma16816(float* c, const uint32_t* a,
                                         const uint32_t* b) {
    asm volatile(
        "mma.sync.aligned.m16n8k16.row.col.f32.bf16.bf16.f32 "
        "{%0,%1,%2,%3}, {%4,%5,%6,%7}, {%8,%9}, {%0,%1,%2,%3};"
        : "+f"(c[0]), "+f"(c[1]), "+f"(c[2]), "+f"(c[3])
        : "r"(a[0]), "r"(a[1]), "r"(a[2]), "r"(a[3]), "r"(b[0]), "r"(b[1]));
}
__device__ __forceinline__ uint32_t pack_bf16x2(float lo, float hi) {
    __nv_bfloat162 t = __floats2bfloat162_rn(lo, hi);
    return *reinterpret_cast<uint32_t*>(&t);
}

// ---------------- 3xBF16 splits: segments along K' -------------------------
__global__ __launch_bounds__(256)
void split_a(const float* __restrict__ in, __nv_bfloat16* __restrict__ out)
{
    size_t i = (size_t)blockIdx.x * 256 + threadIdx.x;
    size_t row = i >> 11;
    size_t k   = i & (HID - 1);
    float a = in[i];
    __nv_bfloat16 hi = __float2bfloat16(a);
    __nv_bfloat16 lo = __float2bfloat16(a - __bfloat162float(hi));
    __nv_bfloat16* o = out + row * KP3;
    o[k]            = hi;
    o[HID + k]      = lo;
    o[2 * HID + k]  = hi;
}
__global__ __launch_bounds__(256)
void split_b(const float* __restrict__ in, __nv_bfloat16* __restrict__ out)
{
    size_t i = (size_t)blockIdx.x * 256 + threadIdx.x;
    size_t row = i >> 11;
    size_t k   = i & (HID - 1);
    float a = in[i];
    __nv_bfloat16 hi = __float2bfloat16(a);
    __nv_bfloat16 lo = __float2bfloat16(a - __bfloat162float(hi));
    __nv_bfloat16* o = out + row * KP3;
    o[k]            = hi;
    o[HID + k]      = hi;
    o[2 * HID + k]  = lo;
}

// ---------------- tiny spacer to keep the GEMM in ncu's -s 5 slot ----------
__global__ void nop_kernel() {}

// ---------------- HMMA GEMM v5: 3-stage pipeline, safe single-sync ---------
// CTA 128x128, 4 warps = 2(M) x 2(N), warp tile 64x64, BK=64.
// smem: row r (0..127) x 8 chunks of 16B; chunk stored at (ch ^ (r&7)).
// loop order per kt: wait_group -> __syncthreads -> PREF(kt+2) -> compute.
//   visibility: sync after wait makes all threads' group-kt data visible.
//   WAR: PREF overwrites stage (kt-1)%3, whose reads all finished before
//        this iteration's sync (they precede sync(kt) program-order).
__global__ __launch_bounds__(128)
void gemm_mma(const __nv_bfloat16* __restrict__ A3,
              const __nv_bfloat16* __restrict__ B3,
              const float* __restrict__ bias,
              float* __restrict__ C, int Nstride)
{
    extern __shared__ __nv_bfloat16 sg[];
    __nv_bfloat16* As = sg;                       // [NSTG][128*64]
    __nv_bfloat16* Bs = sg + NSTG * STG_EL;

    const int tid  = threadIdx.x;
    const int warp = tid >> 5;
    const int lane = tid & 31;
    const int wm = warp & 1;        // 0..1  (M)
    const int wn = warp >> 1;       // 0..1  (N)
    const int m0 = blockIdx.y * 128;
    const int n0 = blockIdx.x * 128;

    float acc[32][4];
#pragma unroll
    for (int i = 0; i < 32; i++)
#pragma unroll
        for (int j = 0; j < 4; j++) acc[i][j] = 0.f;

    // cp.async mapping: chunk c = tid + i*128 (i<8); row=c>>3, ch=c&7,
    // swizzled dst chunk = ch ^ (row&7)
#define PREF(stage, kt) do {                                                   \
    const __nv_bfloat16* _ab = A3 + (size_t)m0 * KP3 + (size_t)(kt) * BK2;     \
    const __nv_bfloat16* _bb = B3 + (size_t)n0 * KP3 + (size_t)(kt) * BK2;     \
    _Pragma("unroll")                                                          \
    for (int _i = 0; _i < 8; _i++) {                                           \
        int _c   = tid + _i * 128;                                             \
        int _row = _c >> 3;                                                    \
        int _ch  = _c & 7;                                                     \
        int _sw  = _ch ^ (_row & 7);                                           \
        uint32_t _so = (uint32_t)((stage) * STG_EL + _row * 64 + _sw * 8);     \
        asm volatile("cp.async.cg.shared.global [%0], [%1], 16;"               \
            :: "r"(smem_u32(As + _so)),                                        \
               "l"(_ab + (size_t)_row * KP3 + _ch * 8) : "memory");            \
        asm volatile("cp.async.cg.shared.global [%0], [%1], 16;"               \
            :: "r"(smem_u32(Bs + _so)),                                        \
               "l"(_bb + (size_t)_row * KP3 + _ch * 8) : "memory");            \
    }                                                                          \
    asm volatile("cp.async.commit_group;" ::: "memory");                       \
} while (0)

    // prologue: stages 0 and 1 in flight (groups 0 and 1)
    PREF(0, 0);
    PREF(1, 1);

    // fragment address lanes
    const int a_r  = lane & 15;             // A row within 16
    const int acb  = lane >> 4;             // A chunk bit (0/1)
    const int b_r  = (lane & 7) + ((lane >> 4) & 1) * 8;
    const int bcb  = (lane >> 3) & 1;
    const int r7   = lane & 7;              // == row&7 for all fragment rows

    const uint32_t aRow = smem_u32(As) + (uint32_t)(wm * 64 + a_r) * 128;
    const uint32_t bRow = smem_u32(Bs) + (uint32_t)(wn * 64 + b_r) * 128;

    for (int kt = 0; kt < NIT2; kt++) {
        const int buf = kt % NSTG;

        // own group kt complete (committed: prologue 2 + one per past iter)
        if (kt == NIT2 - 1)
            asm volatile("cp.async.wait_group 0;" ::: "memory");
        else
            asm volatile("cp.async.wait_group 1;" ::: "memory");
        __syncthreads();   // cross-thread visibility of stage kt data

        if (kt + 2 < NIT2)
            PREF((kt + 2) % NSTG, kt + 2);

        const uint32_t aS = aRow + (uint32_t)buf * STG_BYTES;
        const uint32_t bS = bRow + (uint32_t)buf * STG_BYTES;

#pragma unroll
        for (int s = 0; s < 4; s++) {
            const uint32_t aOff = (uint32_t)(((2 * s + acb) ^ r7) * 16);
            const uint32_t bOff = (uint32_t)(((2 * s + bcb) ^ r7) * 16);
            uint32_t a[4][4], b[4][4];
#pragma unroll
            for (int mi = 0; mi < 4; mi++)
                ldm_x4(a[mi][0], a[mi][1], a[mi][2], a[mi][3],
                       aS + (uint32_t)(mi * 16) * 128 + aOff);
#pragma unroll
            for (int p = 0; p < 4; p++)
                ldm_x4(b[p][0], b[p][1], b[p][2], b[p][3],
                       bS + (uint32_t)(p * 16) * 128 + bOff);
#pragma unroll
            for (int mi = 0; mi < 4; mi++)
#pragma unroll
                for (int ni = 0; ni < 8; ni++) {
                    const uint32_t* bf = &b[ni >> 1][(ni & 1) * 2];
                    mma16816(acc[mi * 8 + ni], a[mi], bf);
                }
        }
    }

    const int er = lane >> 2;
    const int ec = (lane & 3) * 2;
#pragma unroll
    for (int mi = 0; mi < 4; mi++) {
        int gm = m0 + wm * 64 + mi * 16 + er;
#pragma unroll
        for (int ni = 0; ni < 8; ni++) {
            int gn = n0 + wn * 64 + ni * 8 + ec;
            float* c = acc[mi * 8 + ni];
            float2 w0, w1;
            w0.x = c[0] + bias[gn];
            w0.y = c[1] + bias[gn + 1];
            w1.x = c[2] + bias[gn];
            w1.y = c[3] + bias[gn + 1];
            *(float2*)(C + (size_t)gm * Nstride + gn) = w0;
            *(float2*)(C + (size_t)(gm + 8) * Nstride + gn) = w1;
        }
    }
}

// ---------------- RoPE + bf16 hi/lo planes + cache scatter -----------------
__global__ __launch_bounds__(256)
void rope_scatter(const float* __restrict__ cosp, const float* __restrict__ sinp,
                  const int* __restrict__ slots,
                  float* __restrict__ kc_out, float* __restrict__ vc_out)
{
    int idx = blockIdx.x * 256 + threadIdx.x;
    int d = idx & (HD - 1);
    int h = (idx >> 7) & (NH - 1);
    int t = idx >> 11;

    const float* base = g_qkv + (size_t)t * QKV_N;
    float qv = base[h * HD + d];
    float kv = base[HID + h * HD + d];
    float vv = base[2 * HID + h * HD + d];

    if (d < ROTD) {
        if (d < HROT) {
            float c = cosp[t * HROT + d];
            float s = sinp[t * HROT + d];
            float q2 = base[h * HD + d + HROT];
            float k2 = base[HID + h * HD + d + HROT];
            qv = qv * c - q2 * s;
            kv = kv * c - k2 * s;
        } else {
            float c = cosp[t * HROT + d - HROT];
            float s = sinp[t * HROT + d - HROT];
            float q1 = base[h * HD + d - HROT];
            float k1 = base[HID + h * HD + d - HROT];
            qv = qv * c + q1 * s;
            kv = kv * c + k1 * s;
        }
    }

    float qs = qv * 0.08838834764831845f;
    __nv_bfloat16 qh = __float2bfloat16(qs);
    g_qh[idx] = qh;
    g_ql[idx] = __float2bfloat16(qs - __bfloat162float(qh));
    __nv_bfloat16 kh = __float2bfloat16(kv);
    g_kh[idx] = kh;
    g_kl[idx] = __float2bfloat16(kv - __bfloat162float(kh));
    __nv_bfloat16 vh = __float2bfloat16(vv);
    g_vh[idx] = vh;
    g_vl[idx] = __float2bfloat16(vv - __bfloat162float(vh));

    int slot = slots[t];
    size_t co = (size_t)slot * (NH * HD) + h * HD + d;
    kc_out[co] = kv;
    vc_out[co] = vv;
}

// ---------------- flash attention v4: HMMA split-bf16 (unchanged) ----------
#define LDT 136

__global__ __launch_bounds__(128)
void attn_mma()
{
    extern __shared__ __nv_bfloat16 sb[];
    __nv_bfloat16* Qh = sb;
    __nv_bfloat16* Ql = sb + 1 * 64 * LDT;
    __nv_bfloat16* Kh = sb + 2 * 64 * LDT;
    __nv_bfloat16* Kl = sb + 3 * 64 * LDT;
    __nv_bfloat16* Vh = sb + 4 * 64 * LDT;
    __nv_bfloat16* Vl = sb + 5 * 64 * LDT;

    const int b  = blockIdx.z;
    const int h  = blockIdx.y;
    const int qt = (int)gridDim.x - 1 - (int)blockIdx.x;
    const int tid  = threadIdx.x;
    const int warp = tid >> 5;
    const int lane = tid & 31;

    const int er = lane >> 2;
    const int ec = (lane & 3) * 2;
    const int a_r = lane & 15;
    const int a_c = (lane >> 4) * 8;
    const int b_r = (lane & 7) + ((lane >> 4) & 1) * 8;
    const int b_c = ((lane >> 3) & 1) * 8;
    const int v_r = (lane & 7) + ((lane >> 3) & 1) * 8;
    const int v_c = (lane >> 4) * 8;

    const size_t qgbase = (size_t)(b * SS + qt * 64) * HID + h * HD;
#pragma unroll
    for (int it = 0; it < 8; it++) {
        int idx = tid + it * 128;
        int row = idx >> 4, c8 = idx & 15;
        size_t g = qgbase + (size_t)row * HID + c8 * 8;
        *(float4*)(Qh + row * LDT + c8 * 8) = *(const float4*)(g_qh + g);
        *(float4*)(Ql + row * LDT + c8 * 8) = *(const float4*)(g_ql + g);
    }

    float O[16][4];
#pragma unroll
    for (int i = 0; i < 16; i++)
#pragma unroll
        for (int j = 0; j < 4; j++) O[i][j] = 0.f;
    float m0 = -1e30f, m1 = -1e30f, l0 = 0.f, l1 = 0.f;

    for (int kt = 0; kt <= qt; kt++) {
        __syncthreads();
        const size_t kgbase = (size_t)(b * SS + kt * 64) * HID + h * HD;
#pragma unroll
        for (int it = 0; it < 8; it++) {
            int idx = tid + it * 128;
            int row = idx >> 4, c8 = idx & 15;
            size_t g = kgbase + (size_t)row * HID + c8 * 8;
            uint32_t so = row * LDT + c8 * 8;
            *(float4*)(Kh + so) = *(const float4*)(g_kh + g);
            *(float4*)(Kl + so) = *(const float4*)(g_kl + g);
            *(float4*)(Vh + so) = *(const float4*)(g_vh + g);
            *(float4*)(Vl + so) = *(const float4*)(g_vl + g);
        }
        __syncthreads();

        float S[8][4];
#pragma unroll
        for (int i = 0; i < 8; i++)
#pragma unroll
            for (int j = 0; j < 4; j++) S[i][j] = 0.f;

#pragma unroll
        for (int ks = 0; ks < 8; ks++) {
            uint32_t qh4[4], ql4[4];
            ldm_x4(qh4[0], qh4[1], qh4[2], qh4[3],
                   smem_u32(&Qh[(warp * 16 + a_r) * LDT + ks * 16 + a_c]));
            ldm_x4(ql4[0], ql4[1], ql4[2], ql4[3],
                   smem_u32(&Ql[(warp * 16 + a_r) * LDT + ks * 16 + a_c]));
            uint32_t kh4[4][4], kl4[4][4];
#pragma unroll
            for (int p = 0; p < 4; p++) {
                ldm_x4(kh4[p][0], kh4[p][1], kh4[p][2], kh4[p][3],
                       smem_u32(&Kh[(p * 16 + b_r) * LDT + ks * 16 + b_c]));
                ldm_x4(kl4[p][0], kl4[p][1], kl4[p][2], kl4[p][3],
                       smem_u32(&Kl[(p * 16 + b_r) * LDT + ks * 16 + b_c]));
            }
#pragma unroll
            for (int ni = 0; ni < 8; ni++) {
                const uint32_t* bh = &kh4[ni >> 1][(ni & 1) * 2];
                const uint32_t* bl = &kl4[ni >> 1][(ni & 1) * 2];
                mma16816(S[ni], qh4, bh);
                mma16816(S[ni], ql4, bh);
                mma16816(S[ni], qh4, bl);
            }
        }

        if (kt == qt) {
            const int q0 = warp * 16 + er;
            const int q1 = q0 + 8;
#pragma unroll
            for (int ni = 0; ni < 8; ni++) {
                int key = ni * 8 + ec;
                if (key     > q0) S[ni][0] = -1e30f;
                if (key + 1 > q0) S[ni][1] = -1e30f;
                if (key     > q1) S[ni][2] = -1e30f;
                if (key + 1 > q1) S[ni][3] = -1e30f;
            }
        }

        float rx0 = -1e30f, rx1 = -1e30f;
#pragma unroll
        for (int ni = 0; ni < 8; ni++) {
            rx0 = fmaxf(rx0, fmaxf(S[ni][0], S[ni][1]));
            rx1 = fmaxf(rx1, fmaxf(S[ni][2], S[ni][3]));
        }
        rx0 = fmaxf(rx0, __shfl_xor_sync(0xffffffffu, rx0, 1));
        rx0 = fmaxf(rx0, __shfl_xor_sync(0xffffffffu, rx0, 2));
        rx1 = fmaxf(rx1, __shfl_xor_sync(0xffffffffu, rx1, 1));
        rx1 = fmaxf(rx1, __shfl_xor_sync(0xffffffffu, rx1, 2));

        float mn0 = fmaxf(m0, rx0), mn1 = fmaxf(m1, rx1);
        float c0 = __expf(m0 - mn0), c1 = __expf(m1 - mn1);
        l0 *= c0; l1 *= c1;
        m0 = mn0; m1 = mn1;
#pragma unroll
        for (int ni = 0; ni < 16; ni++) {
            O[ni][0] *= c0; O[ni][1] *= c0;
            O[ni][2] *= c1; O[ni][3] *= c1;
        }

        uint32_t PH[4][4], PL[4][4];
        float ls0 = 0.f, ls1 = 0.f;
#pragma unroll
        for (int ni = 0; ni < 8; ni++) {
            float p00 = __expf(S[ni][0] - mn0);
            float p01 = __expf(S[ni][1] - mn0);
            float p10 = __expf(S[ni][2] - mn1);
            float p11 = __expf(S[ni][3] - mn1);
            ls0 += p00 + p01;
            ls1 += p10 + p11;

            __nv_bfloat16 h00 = __float2bfloat16(p00);
            __nv_bfloat16 h01 = __float2bfloat16(p01);
            __nv_bfloat16 h10 = __float2bfloat16(p10);
            __nv_bfloat16 h11 = __float2bfloat16(p11);
            int kk = ni >> 1, base = (ni & 1) * 2;
            PH[kk][base + 0] = pack_bf16x2(__bfloat162float(h00), __bfloat162float(h01));
            PH[kk][base + 1] = pack_bf16x2(__bfloat162float(h10), __bfloat162float(h11));
            PL[kk][base + 0] = pack_bf16x2(p00 - __bfloat162float(h00),
                                           p01 - __bfloat162float(h01));
            PL[kk][base + 1] = pack_bf16x2(p10 - __bfloat162float(h10),
                                           p11 - __bfloat162float(h11));
        }
        ls0 += __shfl_xor_sync(0xffffffffu, ls0, 1);
        ls0 += __shfl_xor_sync(0xffffffffu, ls0, 2);
        ls1 += __shfl_xor_sync(0xffffffffu, ls1, 1);
        ls1 += __shfl_xor_sync(0xffffffffu, ls1, 2);
        l0 += ls0; l1 += ls1;

#pragma unroll
        for (int kk = 0; kk < 4; kk++) {
#pragma unroll
            for (int dp = 0; dp < 8; dp++) {
                uint32_t vh4[4], vl4[4];
                ldm_x4t(vh4[0], vh4[1], vh4[2], vh4[3],
                        smem_u32(&Vh[(kk * 16 + v_r) * LDT + dp * 16 + v_c]));
                ldm_x4t(vl4[0], vl4[1], vl4[2], vl4[3],
                        smem_u32(&Vl[(kk * 16 + v_r) * LDT + dp * 16 + v_c]));
                mma16816(O[dp * 2],     PH[kk], &vh4[0]);
                mma16816(O[dp * 2],     PL[kk], &vh4[0]);
                mma16816(O[dp * 2],     PH[kk], &vl4[0]);
                mma16816(O[dp * 2 + 1], PH[kk], &vh4[2]);
                mma16816(O[dp * 2 + 1], PL[kk], &vh4[2]);
                mma16816(O[dp * 2 + 1], PH[kk], &vl4[2]);
            }
        }
    }

    float inv0 = 1.f / l0, inv1 = 1.f / l1;
    const size_t tq0 = (size_t)(b * SS + qt * 64 + warp * 16 + er);
    const size_t tq1 = tq0 + 8;
#pragma unroll
    for (int ni = 0; ni < 16; ni++) {
        int d = h * HD + ni * 8 + ec;
        float2 w0, w1;
        w0.x = O[ni][0] * inv0; w0.y = O[ni][1] * inv0;
        w1.x = O[ni][2] * inv1; w1.y = O[ni][3] * inv1;
        *(float2*)(g_attn + tq0 * HID + d) = w0;
        *(float2*)(g_attn + tq1 * HID + d) = w1;
    }
}

// ---------------- launch ----------------
extern "C" void kernel_launch(void* const* d_in, const int* in_sizes, int n_in,
                              void* d_out, int out_size)
{
    const float* hidden  = (const float*)d_in[0];
    const float* cosp    = (const float*)d_in[1];
    const float* sinp    = (const float*)d_in[2];
    const float* w_qkv   = (const float*)d_in[3];
    const float* b_qkv   = (const float*)d_in[4];
    const float* w_dense = (const float*)d_in[5];
    const float* b_dense = (const float*)d_in[6];
    const int*   slots   = (const int*)d_in[9];

    float* out = (float*)d_out;
    float* kc  = out + (size_t)TT * HID;
    float* vc  = kc + (size_t)NSLOTS * NH * HD;

    float *p_qkv, *p_attn;
    __nv_bfloat16 *p_h3, *p_wq3, *p_wd3, *p_a3;
    cudaGetSymbolAddress((void**)&p_qkv,  g_qkv);
    cudaGetSymbolAddress((void**)&p_attn, g_attn);
    cudaGetSymbolAddress((void**)&p_h3,  g_h3);
    cudaGetSymbolAddress((void**)&p_wq3, g_wq3);
    cudaGetSymbolAddress((void**)&p_wd3, g_wd3);
    cudaGetSymbolAddress((void**)&p_a3,  g_a3);

    const int ATTN_SMEM = 6 * 64 * LDT * (int)sizeof(__nv_bfloat16);   // 104448
    const int GEMM_SMEM = NSTG * 2 * STG_BYTES;                        // 98304
    static int attr_set = 0;
    if (!attr_set) {
        cudaFuncSetAttribute(attn_mma,
                             cudaFuncAttributeMaxDynamicSharedMemorySize,
                             ATTN_SMEM);
        cudaFuncSetAttribute(gemm_mma,
                             cudaFuncAttributeMaxDynamicSharedMemorySize,
                             GEMM_SMEM);
        attr_set = 1;
    }

    // zero both cache regions (contiguous) in one memset
    cudaMemsetAsync(kc, 0, (size_t)2 * NSLOTS * NH * HD * sizeof(float), 0);

    split_a<<<(TT * HID) / 256, 256>>>(hidden, p_h3);
    split_b<<<((size_t)QKV_N * HID) / 256, 256>>>(w_qkv, p_wq3);

    // spacer: keeps the QKV GEMM at ncu launch idx 5
    nop_kernel<<<1, 32>>>();

    // 1) QKV GEMM
    {
        dim3 grid(QKV_N / 128, TT / 128);
        gemm_mma<<<grid, 128, GEMM_SMEM>>>(p_h3, p_wq3, b_qkv, p_qkv, QKV_N);
    }

    // 2) RoPE + bf16 planes + cache scatter
    rope_scatter<<<(TT * HID) / 256, 256>>>(cosp, sinp, slots, kc, vc);

    // 3) flash attention (HMMA)
    {
        dim3 grid(SS / 64, NH, BB);
        attn_mma<<<grid, 128, ATTN_SMEM>>>();
    }

    // 4) dense projection
    split_b<<<((size_t)HID * HID) / 256, 256>>>(w_dense, p_wd3);
    split_a<<<(TT * HID) / 256, 256>>>(p_attn, p_a3);
    {
        dim3 grid(HID / 128, TT / 128);
        gemm_mma<<<grid, 128, GEMM_SMEM>>>(p_a3, p_wd3, b_dense, out, HID);
    }
}

// round 12
// speedup vs baseline: 7.5787x; 1.0459x over previous
#include <cuda_runtime.h>
#include <cuda_bf16.h>
#include <stdint.h>
#include <math.h>

// ---------------- fixed problem shape ----------------
#define TT      4096
#define HID     2048
#define NH      16
#define HD      128
#define ROTD    32
#define HROT    16
#define NSLOTS  16384
#define BB      2
#define SS      2048
#define QKV_N   (3*HID)
#define KP3     (3*HID)      // 3xBF16 split K' = 6144
#define BK2     64
#define NIT2    (KP3/BK2)    // 96 iterations
#define NSTG    3            // cp.async pipeline depth
#define STG_EL  (128*64)     // bf16 elements per matrix-stage (no pad, swizzled)
#define STG_BYTES (STG_EL*2) // 16384

// ---------------- device scratch (no allocs allowed) ----------------
__device__ float g_qkv[(size_t)TT * QKV_N];   // 96 MB
__device__ float g_attn[(size_t)TT * HID];
__device__ __nv_bfloat16 g_h3 [(size_t)TT * KP3];      // hidden  [ah|al|ah]
__device__ __nv_bfloat16 g_wq3[(size_t)QKV_N * KP3];   // w_qkv   [bh|bh|bl]
__device__ __nv_bfloat16 g_wd3[(size_t)HID * KP3];     // w_dense [bh|bh|bl]
__device__ __nv_bfloat16 g_a3 [(size_t)TT * KP3];      // attn    [ah|al|ah]
// attention operand planes (bf16 hi/lo)
__device__ __nv_bfloat16 g_qh[(size_t)TT * HID];
__device__ __nv_bfloat16 g_ql[(size_t)TT * HID];
__device__ __nv_bfloat16 g_kh[(size_t)TT * HID];
__device__ __nv_bfloat16 g_kl[(size_t)TT * HID];
__device__ __nv_bfloat16 g_vh[(size_t)TT * HID];
__device__ __nv_bfloat16 g_vl[(size_t)TT * HID];

// ---------------- helpers ----------------
__device__ __forceinline__ uint32_t smem_u32(const void* p) {
    uint32_t a;
    asm("{ .reg .u64 t; cvta.to.shared.u64 t, %1; cvt.u32.u64 %0, t; }"
        : "=r"(a) : "l"(p));
    return a;
}
__device__ __forceinline__ void ldm_x4(uint32_t& r0, uint32_t& r1,
                                       uint32_t& r2, uint32_t& r3, uint32_t a) {
    asm volatile("ldmatrix.sync.aligned.m8n8.x4.shared.b16 {%0,%1,%2,%3}, [%4];"
                 : "=r"(r0), "=r"(r1), "=r"(r2), "=r"(r3) : "r"(a));
}
__device__ __forceinline__ void ldm_x4t(uint32_t& r0, uint32_t& r1,
                                        uint32_t& r2, uint32_t& r3, uint32_t a) {
    asm volatile("ldmatrix.sync.aligned.m8n8.x4.trans.shared.b16 {%0,%1,%2,%3}, [%4];"
                 : "=r"(r0), "=r"(r1), "=r"(r2), "=r"(r3) : "r"(a));
}
__device__ __forceinline__ void mma16816(float* c, const uint32_t* a,
                                         const uint32_t* b) {
    asm volatile(
        "mma.sync.aligned.m16n8k16.row.col.f32.bf16.bf16.f32 "
        "{%0,%1,%2,%3}, {%4,%5,%6,%7}, {%8,%9}, {%0,%1,%2,%3};"
        : "+f"(c[0]), "+f"(c[1]), "+f"(c[2]), "+f"(c[3])
        : "r"(a[0]), "r"(a[1]), "r"(a[2]), "r"(a[3]), "r"(b[0]), "r"(b[1]));
}
__device__ __forceinline__ uint32_t pack_bf16x2(float lo, float hi) {
    __nv_bfloat162 t = __floats2bfloat162_rn(lo, hi);
    return *reinterpret_cast<uint32_t*>(&t);
}

// ---------------- 3xBF16 splits: segments along K' -------------------------
__global__ __launch_bounds__(256)
void split_a(const float* __restrict__ in, __nv_bfloat16* __restrict__ out)
{
    size_t i = (size_t)blockIdx.x * 256 + threadIdx.x;
    size_t row = i >> 11;
    size_t k   = i & (HID - 1);
    float a = in[i];
    __nv_bfloat16 hi = __float2bfloat16(a);
    __nv_bfloat16 lo = __float2bfloat16(a - __bfloat162float(hi));
    __nv_bfloat16* o = out + row * KP3;
    o[k]            = hi;
    o[HID + k]      = lo;
    o[2 * HID + k]  = hi;
}
__global__ __launch_bounds__(256)
void split_b(const float* __restrict__ in, __nv_bfloat16* __restrict__ out)
{
    size_t i = (size_t)blockIdx.x * 256 + threadIdx.x;
    size_t row = i >> 11;
    size_t k   = i & (HID - 1);
    float a = in[i];
    __nv_bfloat16 hi = __float2bfloat16(a);
    __nv_bfloat16 lo = __float2bfloat16(a - __bfloat162float(hi));
    __nv_bfloat16* o = out + row * KP3;
    o[k]            = hi;
    o[HID + k]      = hi;
    o[2 * HID + k]  = lo;
}

// ---------------- tiny spacer to keep the GEMM in ncu's -s 5 slot ----------
__global__ void nop_kernel() {}

// ---------------- HMMA GEMM v6: v5 + intra-stage fragment double-buffer ----
// CTA 128x128, 4 warps = 2(M) x 2(N), warp tile 64x64, BK=64, 3-stage smem.
// Fragments for k16-step s+1 are ldmatrix'ed while MMAs of step s issue,
// hiding LDSM latency behind a full MMA block.
__global__ __launch_bounds__(128, 2)
void gemm_mma(const __nv_bfloat16* __restrict__ A3,
              const __nv_bfloat16* __restrict__ B3,
              const float* __restrict__ bias,
              float* __restrict__ C, int Nstride)
{
    extern __shared__ __nv_bfloat16 sg[];
    __nv_bfloat16* As = sg;                       // [NSTG][128*64]
    __nv_bfloat16* Bs = sg + NSTG * STG_EL;

    const int tid  = threadIdx.x;
    const int warp = tid >> 5;
    const int lane = tid & 31;
    const int wm = warp & 1;        // 0..1  (M)
    const int wn = warp >> 1;       // 0..1  (N)
    const int m0 = blockIdx.y * 128;
    const int n0 = blockIdx.x * 128;

    float acc[32][4];
#pragma unroll
    for (int i = 0; i < 32; i++)
#pragma unroll
        for (int j = 0; j < 4; j++) acc[i][j] = 0.f;

    // cp.async mapping: chunk c = tid + i*128 (i<8); row=c>>3, ch=c&7,
    // swizzled dst chunk = ch ^ (row&7)
#define PREF(stage, kt) do {                                                   \
    const __nv_bfloat16* _ab = A3 + (size_t)m0 * KP3 + (size_t)(kt) * BK2;     \
    const __nv_bfloat16* _bb = B3 + (size_t)n0 * KP3 + (size_t)(kt) * BK2;     \
    _Pragma("unroll")                                                          \
    for (int _i = 0; _i < 8; _i++) {                                           \
        int _c   = tid + _i * 128;                                             \
        int _row = _c >> 3;                                                    \
        int _ch  = _c & 7;                                                     \
        int _sw  = _ch ^ (_row & 7);                                           \
        uint32_t _so = (uint32_t)((stage) * STG_EL + _row * 64 + _sw * 8);     \
        asm volatile("cp.async.cg.shared.global [%0], [%1], 16;"               \
            :: "r"(smem_u32(As + _so)),                                        \
               "l"(_ab + (size_t)_row * KP3 + _ch * 8) : "memory");            \
        asm volatile("cp.async.cg.shared.global [%0], [%1], 16;"               \
            :: "r"(smem_u32(Bs + _so)),                                        \
               "l"(_bb + (size_t)_row * KP3 + _ch * 8) : "memory");            \
    }                                                                          \
    asm volatile("cp.async.commit_group;" ::: "memory");                       \
} while (0)

    // prologue: stages 0 and 1 in flight (groups 0 and 1)
    PREF(0, 0);
    PREF(1, 1);

    // fragment address lanes
    const int a_r  = lane & 15;             // A row within 16
    const int acb  = lane >> 4;             // A chunk bit (0/1)
    const int b_r  = (lane & 7) + ((lane >> 4) & 1) * 8;
    const int bcb  = (lane >> 3) & 1;
    const int r7   = lane & 7;              // == row&7 for all fragment rows

    const uint32_t aRow = smem_u32(As) + (uint32_t)(wm * 64 + a_r) * 128;
    const uint32_t bRow = smem_u32(Bs) + (uint32_t)(wn * 64 + b_r) * 128;

    // double-buffered fragments
    uint32_t a[2][4][4], b[2][4][4];

#define LOAD_FRAGS(bufi, aS, bS, s) do {                                       \
    const uint32_t _aOff = (uint32_t)(((2 * (s) + acb) ^ r7) * 16);            \
    const uint32_t _bOff = (uint32_t)(((2 * (s) + bcb) ^ r7) * 16);            \
    _Pragma("unroll")                                                          \
    for (int _mi = 0; _mi < 4; _mi++)                                          \
        ldm_x4(a[bufi][_mi][0], a[bufi][_mi][1],                               \
               a[bufi][_mi][2], a[bufi][_mi][3],                               \
               (aS) + (uint32_t)(_mi * 16) * 128 + _aOff);                     \
    _Pragma("unroll")                                                          \
    for (int _p = 0; _p < 4; _p++)                                             \
        ldm_x4(b[bufi][_p][0], b[bufi][_p][1],                                 \
               b[bufi][_p][2], b[bufi][_p][3],                                 \
               (bS) + (uint32_t)(_p * 16) * 128 + _bOff);                      \
} while (0)

    for (int kt = 0; kt < NIT2; kt++) {
        const int buf = kt % NSTG;

        if (kt == NIT2 - 1)
            asm volatile("cp.async.wait_group 0;" ::: "memory");
        else
            asm volatile("cp.async.wait_group 1;" ::: "memory");
        __syncthreads();   // cross-thread visibility of stage kt data

        if (kt + 2 < NIT2)
            PREF((kt + 2) % NSTG, kt + 2);

        const uint32_t aS = aRow + (uint32_t)buf * STG_BYTES;
        const uint32_t bS = bRow + (uint32_t)buf * STG_BYTES;

        LOAD_FRAGS(0, aS, bS, 0);
#pragma unroll
        for (int s = 0; s < 4; s++) {
            const int cur = s & 1;
            if (s < 3)
                LOAD_FRAGS(cur ^ 1, aS, bS, s + 1);
#pragma unroll
            for (int mi = 0; mi < 4; mi++)
#pragma unroll
                for (int ni = 0; ni < 8; ni++) {
                    const uint32_t* bf = &b[cur][ni >> 1][(ni & 1) * 2];
                    mma16816(acc[mi * 8 + ni], a[cur][mi], bf);
                }
        }
    }

    const int er = lane >> 2;
    const int ec = (lane & 3) * 2;
#pragma unroll
    for (int mi = 0; mi < 4; mi++) {
        int gm = m0 + wm * 64 + mi * 16 + er;
#pragma unroll
        for (int ni = 0; ni < 8; ni++) {
            int gn = n0 + wn * 64 + ni * 8 + ec;
            float* c = acc[mi * 8 + ni];
            float2 w0, w1;
            w0.x = c[0] + bias[gn];
            w0.y = c[1] + bias[gn + 1];
            w1.x = c[2] + bias[gn];
            w1.y = c[3] + bias[gn + 1];
            *(float2*)(C + (size_t)gm * Nstride + gn) = w0;
            *(float2*)(C + (size_t)(gm + 8) * Nstride + gn) = w1;
        }
    }
}

// ---------------- RoPE + bf16 hi/lo planes + cache scatter -----------------
__global__ __launch_bounds__(256)
void rope_scatter(const float* __restrict__ cosp, const float* __restrict__ sinp,
                  const int* __restrict__ slots,
                  float* __restrict__ kc_out, float* __restrict__ vc_out)
{
    int idx = blockIdx.x * 256 + threadIdx.x;
    int d = idx & (HD - 1);
    int h = (idx >> 7) & (NH - 1);
    int t = idx >> 11;

    const float* base = g_qkv + (size_t)t * QKV_N;
    float qv = base[h * HD + d];
    float kv = base[HID + h * HD + d];
    float vv = base[2 * HID + h * HD + d];

    if (d < ROTD) {
        if (d < HROT) {
            float c = cosp[t * HROT + d];
            float s = sinp[t * HROT + d];
            float q2 = base[h * HD + d + HROT];
            float k2 = base[HID + h * HD + d + HROT];
            qv = qv * c - q2 * s;
            kv = kv * c - k2 * s;
        } else {
            float c = cosp[t * HROT + d - HROT];
            float s = sinp[t * HROT + d - HROT];
            float q1 = base[h * HD + d - HROT];
            float k1 = base[HID + h * HD + d - HROT];
            qv = qv * c + q1 * s;
            kv = kv * c + k1 * s;
        }
    }

    float qs = qv * 0.08838834764831845f;
    __nv_bfloat16 qh = __float2bfloat16(qs);
    g_qh[idx] = qh;
    g_ql[idx] = __float2bfloat16(qs - __bfloat162float(qh));
    __nv_bfloat16 kh = __float2bfloat16(kv);
    g_kh[idx] = kh;
    g_kl[idx] = __float2bfloat16(kv - __bfloat162float(kh));
    __nv_bfloat16 vh = __float2bfloat16(vv);
    g_vh[idx] = vh;
    g_vl[idx] = __float2bfloat16(vv - __bfloat162float(vh));

    int slot = slots[t];
    size_t co = (size_t)slot * (NH * HD) + h * HD + d;
    kc_out[co] = kv;
    vc_out[co] = vv;
}

// ---------------- flash attention v4: HMMA split-bf16 (unchanged) ----------
#define LDT 136

__global__ __launch_bounds__(128)
void attn_mma()
{
    extern __shared__ __nv_bfloat16 sb[];
    __nv_bfloat16* Qh = sb;
    __nv_bfloat16* Ql = sb + 1 * 64 * LDT;
    __nv_bfloat16* Kh = sb + 2 * 64 * LDT;
    __nv_bfloat16* Kl = sb + 3 * 64 * LDT;
    __nv_bfloat16* Vh = sb + 4 * 64 * LDT;
    __nv_bfloat16* Vl = sb + 5 * 64 * LDT;

    const int b  = blockIdx.z;
    const int h  = blockIdx.y;
    const int qt = (int)gridDim.x - 1 - (int)blockIdx.x;
    const int tid  = threadIdx.x;
    const int warp = tid >> 5;
    const int lane = tid & 31;

    const int er = lane >> 2;
    const int ec = (lane & 3) * 2;
    const int a_r = lane & 15;
    const int a_c = (lane >> 4) * 8;
    const int b_r = (lane & 7) + ((lane >> 4) & 1) * 8;
    const int b_c = ((lane >> 3) & 1) * 8;
    const int v_r = (lane & 7) + ((lane >> 3) & 1) * 8;
    const int v_c = (lane >> 4) * 8;

    const size_t qgbase = (size_t)(b * SS + qt * 64) * HID + h * HD;
#pragma unroll
    for (int it = 0; it < 8; it++) {
        int idx = tid + it * 128;
        int row = idx >> 4, c8 = idx & 15;
        size_t g = qgbase + (size_t)row * HID + c8 * 8;
        *(float4*)(Qh + row * LDT + c8 * 8) = *(const float4*)(g_qh + g);
        *(float4*)(Ql + row * LDT + c8 * 8) = *(const float4*)(g_ql + g);
    }

    float O[16][4];
#pragma unroll
    for (int i = 0; i < 16; i++)
#pragma unroll
        for (int j = 0; j < 4; j++) O[i][j] = 0.f;
    float m0 = -1e30f, m1 = -1e30f, l0 = 0.f, l1 = 0.f;

    for (int kt = 0; kt <= qt; kt++) {
        __syncthreads();
        const size_t kgbase = (size_t)(b * SS + kt * 64) * HID + h * HD;
#pragma unroll
        for (int it = 0; it < 8; it++) {
            int idx = tid + it * 128;
            int row = idx >> 4, c8 = idx & 15;
            size_t g = kgbase + (size_t)row * HID + c8 * 8;
            uint32_t so = row * LDT + c8 * 8;
            *(float4*)(Kh + so) = *(const float4*)(g_kh + g);
            *(float4*)(Kl + so) = *(const float4*)(g_kl + g);
            *(float4*)(Vh + so) = *(const float4*)(g_vh + g);
            *(float4*)(Vl + so) = *(const float4*)(g_vl + g);
        }
        __syncthreads();

        float S[8][4];
#pragma unroll
        for (int i = 0; i < 8; i++)
#pragma unroll
            for (int j = 0; j < 4; j++) S[i][j] = 0.f;

#pragma unroll
        for (int ks = 0; ks < 8; ks++) {
            uint32_t qh4[4], ql4[4];
            ldm_x4(qh4[0], qh4[1], qh4[2], qh4[3],
                   smem_u32(&Qh[(warp * 16 + a_r) * LDT + ks * 16 + a_c]));
            ldm_x4(ql4[0], ql4[1], ql4[2], ql4[3],
                   smem_u32(&Ql[(warp * 16 + a_r) * LDT + ks * 16 + a_c]));
            uint32_t kh4[4][4], kl4[4][4];
#pragma unroll
            for (int p = 0; p < 4; p++) {
                ldm_x4(kh4[p][0], kh4[p][1], kh4[p][2], kh4[p][3],
                       smem_u32(&Kh[(p * 16 + b_r) * LDT + ks * 16 + b_c]));
                ldm_x4(kl4[p][0], kl4[p][1], kl4[p][2], kl4[p][3],
                       smem_u32(&Kl[(p * 16 + b_r) * LDT + ks * 16 + b_c]));
            }
#pragma unroll
            for (int ni = 0; ni < 8; ni++) {
                const uint32_t* bh = &kh4[ni >> 1][(ni & 1) * 2];
                const uint32_t* bl = &kl4[ni >> 1][(ni & 1) * 2];
                mma16816(S[ni], qh4, bh);
                mma16816(S[ni], ql4, bh);
                mma16816(S[ni], qh4, bl);
            }
        }

        if (kt == qt) {
            const int q0 = warp * 16 + er;
            const int q1 = q0 + 8;
#pragma unroll
            for (int ni = 0; ni < 8; ni++) {
                int key = ni * 8 + ec;
                if (key     > q0) S[ni][0] = -1e30f;
                if (key + 1 > q0) S[ni][1] = -1e30f;
                if (key     > q1) S[ni][2] = -1e30f;
                if (key + 1 > q1) S[ni][3] = -1e30f;
            }
        }

        float rx0 = -1e30f, rx1 = -1e30f;
#pragma unroll
        for (int ni = 0; ni < 8; ni++) {
            rx0 = fmaxf(rx0, fmaxf(S[ni][0], S[ni][1]));
            rx1 = fmaxf(rx1, fmaxf(S[ni][2], S[ni][3]));
        }
        rx0 = fmaxf(rx0, __shfl_xor_sync(0xffffffffu, rx0, 1));
        rx0 = fmaxf(rx0, __shfl_xor_sync(0xffffffffu, rx0, 2));
        rx1 = fmaxf(rx1, __shfl_xor_sync(0xffffffffu, rx1, 1));
        rx1 = fmaxf(rx1, __shfl_xor_sync(0xffffffffu, rx1, 2));

        float mn0 = fmaxf(m0, rx0), mn1 = fmaxf(m1, rx1);
        float c0 = __expf(m0 - mn0), c1 = __expf(m1 - mn1);
        l0 *= c0; l1 *= c1;
        m0 = mn0; m1 = mn1;
#pragma unroll
        for (int ni = 0; ni < 16; ni++) {
            O[ni][0] *= c0; O[ni][1] *= c0;
            O[ni][2] *= c1; O[ni][3] *= c1;
        }

        uint32_t PH[4][4], PL[4][4];
        float ls0 = 0.f, ls1 = 0.f;
#pragma unroll
        for (int ni = 0; ni < 8; ni++) {
            float p00 = __expf(S[ni][0] - mn0);
            float p01 = __expf(S[ni][1] - mn0);
            float p10 = __expf(S[ni][2] - mn1);
            float p11 = __expf(S[ni][3] - mn1);
            ls0 += p00 + p01;
            ls1 += p10 + p11;

            __nv_bfloat16 h00 = __float2bfloat16(p00);
            __nv_bfloat16 h01 = __float2bfloat16(p01);
            __nv_bfloat16 h10 = __float2bfloat16(p10);
            __nv_bfloat16 h11 = __float2bfloat16(p11);
            int kk = ni >> 1, base = (ni & 1) * 2;
            PH[kk][base + 0] = pack_bf16x2(__bfloat162float(h00), __bfloat162float(h01));
            PH[kk][base + 1] = pack_bf16x2(__bfloat162float(h10), __bfloat162float(h11));
            PL[kk][base + 0] = pack_bf16x2(p00 - __bfloat162float(h00),
                                           p01 - __bfloat162float(h01));
            PL[kk][base + 1] = pack_bf16x2(p10 - __bfloat162float(h10),
                                           p11 - __bfloat162float(h11));
        }
        ls0 += __shfl_xor_sync(0xffffffffu, ls0, 1);
        ls0 += __shfl_xor_sync(0xffffffffu, ls0, 2);
        ls1 += __shfl_xor_sync(0xffffffffu, ls1, 1);
        ls1 += __shfl_xor_sync(0xffffffffu, ls1, 2);
        l0 += ls0; l1 += ls1;

#pragma unroll
        for (int kk = 0; kk < 4; kk++) {
#pragma unroll
            for (int dp = 0; dp < 8; dp++) {
                uint32_t vh4[4], vl4[4];
                ldm_x4t(vh4[0], vh4[1], vh4[2], vh4[3],
                        smem_u32(&Vh[(kk * 16 + v_r) * LDT + dp * 16 + v_c]));
                ldm_x4t(vl4[0], vl4[1], vl4[2], vl4[3],
                        smem_u32(&Vl[(kk * 16 + v_r) * LDT + dp * 16 + v_c]));
                mma16816(O[dp * 2],     PH[kk], &vh4[0]);
                mma16816(O[dp * 2],     PL[kk], &vh4[0]);
                mma16816(O[dp * 2],     PH[kk], &vl4[0]);
                mma16816(O[dp * 2 + 1], PH[kk], &vh4[2]);
                mma16816(O[dp * 2 + 1], PL[kk], &vh4[2]);
                mma16816(O[dp * 2 + 1], PH[kk], &vl4[2]);
            }
        }
    }

    float inv0 = 1.f / l0, inv1 = 1.f / l1;
    const size_t tq0 = (size_t)(b * SS + qt * 64 + warp * 16 + er);
    const size_t tq1 = tq0 + 8;
#pragma unroll
    for (int ni = 0; ni < 16; ni++) {
        int d = h * HD + ni * 8 + ec;
        float2 w0, w1;
        w0.x = O[ni][0] * inv0; w0.y = O[ni][1] * inv0;
        w1.x = O[ni][2] * inv1; w1.y = O[ni][3] * inv1;
        *(float2*)(g_attn + tq0 * HID + d) = w0;
        *(float2*)(g_attn + tq1 * HID + d) = w1;
    }
}

// ---------------- launch ----------------
extern "C" void kernel_launch(void* const* d_in, const int* in_sizes, int n_in,
                              void* d_out, int out_size)
{
    const float* hidden  = (const float*)d_in[0];
    const float* cosp    = (const float*)d_in[1];
    const float* sinp    = (const float*)d_in[2];
    const float* w_qkv   = (const float*)d_in[3];
    const float* b_qkv   = (const float*)d_in[4];
    const float* w_dense = (const float*)d_in[5];
    const float* b_dense = (const float*)d_in[6];
    const int*   slots   = (const int*)d_in[9];

    float* out = (float*)d_out;
    float* kc  = out + (size_t)TT * HID;
    float* vc  = kc + (size_t)NSLOTS * NH * HD;

    float *p_qkv, *p_attn;
    __nv_bfloat16 *p_h3, *p_wq3, *p_wd3, *p_a3;
    cudaGetSymbolAddress((void**)&p_qkv,  g_qkv);
    cudaGetSymbolAddress((void**)&p_attn, g_attn);
    cudaGetSymbolAddress((void**)&p_h3,  g_h3);
    cudaGetSymbolAddress((void**)&p_wq3, g_wq3);
    cudaGetSymbolAddress((void**)&p_wd3, g_wd3);
    cudaGetSymbolAddress((void**)&p_a3,  g_a3);

    const int ATTN_SMEM = 6 * 64 * LDT * (int)sizeof(__nv_bfloat16);   // 104448
    const int GEMM_SMEM = NSTG * 2 * STG_BYTES;                        // 98304
    static int attr_set = 0;
    if (!attr_set) {
        cudaFuncSetAttribute(attn_mma,
                             cudaFuncAttributeMaxDynamicSharedMemorySize,
                             ATTN_SMEM);
        cudaFuncSetAttribute(gemm_mma,
                             cudaFuncAttributeMaxDynamicSharedMemorySize,
                             GEMM_SMEM);
        attr_set = 1;
    }

    // zero both cache regions (contiguous) in one memset
    cudaMemsetAsync(kc, 0, (size_t)2 * NSLOTS * NH * HD * sizeof(float), 0);

    split_a<<<(TT * HID) / 256, 256>>>(hidden, p_h3);
    split_b<<<((size_t)QKV_N * HID) / 256, 256>>>(w_qkv, p_wq3);

    // spacer: keeps the QKV GEMM at ncu launch idx 5
    nop_kernel<<<1, 32>>>();

    // 1) QKV GEMM
    {
        dim3 grid(QKV_N / 128, TT / 128);
        gemm_mma<<<grid, 128, GEMM_SMEM>>>(p_h3, p_wq3, b_qkv, p_qkv, QKV_N);
    }

    // 2) RoPE + bf16 planes + cache scatter
    rope_scatter<<<(TT * HID) / 256, 256>>>(cosp, sinp, slots, kc, vc);

    // 3) flash attention (HMMA)
    {
        dim3 grid(SS / 64, NH, BB);
        attn_mma<<<grid, 128, ATTN_SMEM>>>();
    }

    // 4) dense projection
    split_b<<<((size_t)HID * HID) / 256, 256>>>(w_dense, p_wd3);
    split_a<<<(TT * HID) / 256, 256>>>(p_attn, p_a3);
    {
        dim3 grid(HID / 128, TT / 128);
        gemm_mma<<<grid, 128, GEMM_SMEM>>>(p_a3, p_wd3, b_dense, out, HID);
    }
}

// round 13
// speedup vs baseline: 7.5985x; 1.0026x over previous
#include <cuda_runtime.h>
#include <cuda_bf16.h>
#include <stdint.h>
#include <math.h>

// ---------------- fixed problem shape ----------------
#define TT      4096
#define HID     2048
#define NH      16
#define HD      128
#define ROTD    32
#define HROT    16
#define NSLOTS  16384
#define BB      2
#define SS      2048
#define QKV_N   (3*HID)
#define KP3     (3*HID)      // 3xBF16 split K' = 6144
#define BK2     64
#define NIT2    (KP3/BK2)    // 96 iterations
#define NSTG    3            // cp.async pipeline depth
#define STG_EL  (128*64)     // bf16 elements per matrix-stage (swizzled)
#define STG_BYTES (STG_EL*2) // 16384

// ---------------- device scratch (no allocs allowed) ----------------
__device__ float g_qkv[(size_t)TT * QKV_N];   // 96 MB
__device__ __nv_bfloat16 g_h3 [(size_t)TT * KP3];      // hidden  [ah|al|ah]
__device__ __nv_bfloat16 g_wq3[(size_t)QKV_N * KP3];   // w_qkv   [bh|bh|bl]
__device__ __nv_bfloat16 g_wd3[(size_t)HID * KP3];     // w_dense [bh|bh|bl]
__device__ __nv_bfloat16 g_a3 [(size_t)TT * KP3];      // attn    [ah|al|ah]
// attention operand planes (bf16 hi/lo)
__device__ __nv_bfloat16 g_qh[(size_t)TT * HID];
__device__ __nv_bfloat16 g_ql[(size_t)TT * HID];
__device__ __nv_bfloat16 g_kh[(size_t)TT * HID];
__device__ __nv_bfloat16 g_kl[(size_t)TT * HID];
__device__ __nv_bfloat16 g_vh[(size_t)TT * HID];
__device__ __nv_bfloat16 g_vl[(size_t)TT * HID];

// ---------------- helpers ----------------
__device__ __forceinline__ uint32_t smem_u32(const void* p) {
    uint32_t a;
    asm("{ .reg .u64 t; cvta.to.shared.u64 t, %1; cvt.u32.u64 %0, t; }"
        : "=r"(a) : "l"(p));
    return a;
}
__device__ __forceinline__ void ldm_x4(uint32_t& r0, uint32_t& r1,
                                       uint32_t& r2, uint32_t& r3, uint32_t a) {
    asm volatile("ldmatrix.sync.aligned.m8n8.x4.shared.b16 {%0,%1,%2,%3}, [%4];"
                 : "=r"(r0), "=r"(r1), "=r"(r2), "=r"(r3) : "r"(a));
}
__device__ __forceinline__ void ldm_x4t(uint32_t& r0, uint32_t& r1,
                                        uint32_t& r2, uint32_t& r3, uint32_t a) {
    asm volatile("ldmatrix.sync.aligned.m8n8.x4.trans.shared.b16 {%0,%1,%2,%3}, [%4];"
                 : "=r"(r0), "=r"(r1), "=r"(r2), "=r"(r3) : "r"(a));
}
__device__ __forceinline__ void mma16816(float* c, const uint32_t* a,
                                         const uint32_t* b) {
    asm volatile(
        "mma.sync.aligned.m16n8k16.row.col.f32.bf16.bf16.f32 "
        "{%0,%1,%2,%3}, {%4,%5,%6,%7}, {%8,%9}, {%0,%1,%2,%3};"
        : "+f"(c[0]), "+f"(c[1]), "+f"(c[2]), "+f"(c[3])
        : "r"(a[0]), "r"(a[1]), "r"(a[2]), "r"(a[3]), "r"(b[0]), "r"(b[1]));
}
__device__ __forceinline__ uint32_t pack_bf16x2(float lo, float hi) {
    __nv_bfloat162 t = __floats2bfloat162_rn(lo, hi);
    return *reinterpret_cast<uint32_t*>(&t);
}

// ---------------- fused 3xBF16 split (hidden A-style, weights B-style) -----
#define N_HID_EL   ((size_t)TT * HID)          //  8388608
#define N_WQ_EL    ((size_t)QKV_N * HID)       // 12582912
#define N_WD_EL    ((size_t)HID * HID)         //  4194304
__global__ __launch_bounds__(256)
void fused_split(const float* __restrict__ hidden,
                 const float* __restrict__ w_qkv,
                 const float* __restrict__ w_dense)
{
    size_t i = (size_t)blockIdx.x * 256 + threadIdx.x;
    const float* in;
    __nv_bfloat16* out;
    int a_style;
    if (i < N_HID_EL) {
        in = hidden; out = g_h3; a_style = 1;
    } else if (i < N_HID_EL + N_WQ_EL) {
        i -= N_HID_EL;
        in = w_qkv; out = g_wq3; a_style = 0;
    } else {
        i -= N_HID_EL + N_WQ_EL;
        in = w_dense; out = g_wd3; a_style = 0;
    }
    size_t row = i >> 11;
    size_t k   = i & (HID - 1);
    float a = in[i];
    __nv_bfloat16 hi = __float2bfloat16(a);
    __nv_bfloat16 lo = __float2bfloat16(a - __bfloat162float(hi));
    __nv_bfloat16* o = out + row * KP3;
    if (a_style) {              // [hi | lo | hi]
        o[k]            = hi;
        o[HID + k]      = lo;
        o[2 * HID + k]  = hi;
    } else {                    // [hi | hi | lo]
        o[k]            = hi;
        o[HID + k]      = hi;
        o[2 * HID + k]  = lo;
    }
}

// ---------------- HMMA GEMM v6 (unchanged from R12) ------------------------
__global__ __launch_bounds__(128, 2)
void gemm_mma(const __nv_bfloat16* __restrict__ A3,
              const __nv_bfloat16* __restrict__ B3,
              const float* __restrict__ bias,
              float* __restrict__ C, int Nstride)
{
    extern __shared__ __nv_bfloat16 sg[];
    __nv_bfloat16* As = sg;                       // [NSTG][128*64]
    __nv_bfloat16* Bs = sg + NSTG * STG_EL;

    const int tid  = threadIdx.x;
    const int warp = tid >> 5;
    const int lane = tid & 31;
    const int wm = warp & 1;
    const int wn = warp >> 1;
    const int m0 = blockIdx.y * 128;
    const int n0 = blockIdx.x * 128;

    float acc[32][4];
#pragma unroll
    for (int i = 0; i < 32; i++)
#pragma unroll
        for (int j = 0; j < 4; j++) acc[i][j] = 0.f;

#define PREF(stage, kt) do {                                                   \
    const __nv_bfloat16* _ab = A3 + (size_t)m0 * KP3 + (size_t)(kt) * BK2;     \
    const __nv_bfloat16* _bb = B3 + (size_t)n0 * KP3 + (size_t)(kt) * BK2;     \
    _Pragma("unroll")                                                          \
    for (int _i = 0; _i < 8; _i++) {                                           \
        int _c   = tid + _i * 128;                                             \
        int _row = _c >> 3;                                                    \
        int _ch  = _c & 7;                                                     \
        int _sw  = _ch ^ (_row & 7);                                           \
        uint32_t _so = (uint32_t)((stage) * STG_EL + _row * 64 + _sw * 8);     \
        asm volatile("cp.async.cg.shared.global [%0], [%1], 16;"               \
            :: "r"(smem_u32(As + _so)),                                        \
               "l"(_ab + (size_t)_row * KP3 + _ch * 8) : "memory");            \
        asm volatile("cp.async.cg.shared.global [%0], [%1], 16;"               \
            :: "r"(smem_u32(Bs + _so)),                                        \
               "l"(_bb + (size_t)_row * KP3 + _ch * 8) : "memory");            \
    }                                                                          \
    asm volatile("cp.async.commit_group;" ::: "memory");                       \
} while (0)

    PREF(0, 0);
    PREF(1, 1);

    const int a_r  = lane & 15;
    const int acb  = lane >> 4;
    const int b_r  = (lane & 7) + ((lane >> 4) & 1) * 8;
    const int bcb  = (lane >> 3) & 1;
    const int r7   = lane & 7;

    const uint32_t aRow = smem_u32(As) + (uint32_t)(wm * 64 + a_r) * 128;
    const uint32_t bRow = smem_u32(Bs) + (uint32_t)(wn * 64 + b_r) * 128;

    uint32_t a[2][4][4], b[2][4][4];

#define LOAD_FRAGS(bufi, aS, bS, s) do {                                       \
    const uint32_t _aOff = (uint32_t)(((2 * (s) + acb) ^ r7) * 16);            \
    const uint32_t _bOff = (uint32_t)(((2 * (s) + bcb) ^ r7) * 16);            \
    _Pragma("unroll")                                                          \
    for (int _mi = 0; _mi < 4; _mi++)                                          \
        ldm_x4(a[bufi][_mi][0], a[bufi][_mi][1],                               \
               a[bufi][_mi][2], a[bufi][_mi][3],                               \
               (aS) + (uint32_t)(_mi * 16) * 128 + _aOff);                     \
    _Pragma("unroll")                                                          \
    for (int _p = 0; _p < 4; _p++)                                             \
        ldm_x4(b[bufi][_p][0], b[bufi][_p][1],                                 \
               b[bufi][_p][2], b[bufi][_p][3],                                 \
               (bS) + (uint32_t)(_p * 16) * 128 + _bOff);                      \
} while (0)

    for (int kt = 0; kt < NIT2; kt++) {
        const int buf = kt % NSTG;

        if (kt == NIT2 - 1)
            asm volatile("cp.async.wait_group 0;" ::: "memory");
        else
            asm volatile("cp.async.wait_group 1;" ::: "memory");
        __syncthreads();

        if (kt + 2 < NIT2)
            PREF((kt + 2) % NSTG, kt + 2);

        const uint32_t aS = aRow + (uint32_t)buf * STG_BYTES;
        const uint32_t bS = bRow + (uint32_t)buf * STG_BYTES;

        LOAD_FRAGS(0, aS, bS, 0);
#pragma unroll
        for (int s = 0; s < 4; s++) {
            const int cur = s & 1;
            if (s < 3)
                LOAD_FRAGS(cur ^ 1, aS, bS, s + 1);
#pragma unroll
            for (int mi = 0; mi < 4; mi++)
#pragma unroll
                for (int ni = 0; ni < 8; ni++) {
                    const uint32_t* bf = &b[cur][ni >> 1][(ni & 1) * 2];
                    mma16816(acc[mi * 8 + ni], a[cur][mi], bf);
                }
        }
    }

    const int er = lane >> 2;
    const int ec = (lane & 3) * 2;
#pragma unroll
    for (int mi = 0; mi < 4; mi++) {
        int gm = m0 + wm * 64 + mi * 16 + er;
#pragma unroll
        for (int ni = 0; ni < 8; ni++) {
            int gn = n0 + wn * 64 + ni * 8 + ec;
            float* c = acc[mi * 8 + ni];
            float2 w0, w1;
            w0.x = c[0] + bias[gn];
            w0.y = c[1] + bias[gn + 1];
            w1.x = c[2] + bias[gn];
            w1.y = c[3] + bias[gn + 1];
            *(float2*)(C + (size_t)gm * Nstride + gn) = w0;
            *(float2*)(C + (size_t)(gm + 8) * Nstride + gn) = w1;
        }
    }
}

// ---------------- RoPE + bf16 hi/lo planes + cache scatter -----------------
__global__ __launch_bounds__(256)
void rope_scatter(const float* __restrict__ cosp, const float* __restrict__ sinp,
                  const int* __restrict__ slots,
                  float* __restrict__ kc_out, float* __restrict__ vc_out)
{
    int idx = blockIdx.x * 256 + threadIdx.x;
    int d = idx & (HD - 1);
    int h = (idx >> 7) & (NH - 1);
    int t = idx >> 11;

    const float* base = g_qkv + (size_t)t * QKV_N;
    float qv = base[h * HD + d];
    float kv = base[HID + h * HD + d];
    float vv = base[2 * HID + h * HD + d];

    if (d < ROTD) {
        if (d < HROT) {
            float c = cosp[t * HROT + d];
            float s = sinp[t * HROT + d];
            float q2 = base[h * HD + d + HROT];
            float k2 = base[HID + h * HD + d + HROT];
            qv = qv * c - q2 * s;
            kv = kv * c - k2 * s;
        } else {
            float c = cosp[t * HROT + d - HROT];
            float s = sinp[t * HROT + d - HROT];
            float q1 = base[h * HD + d - HROT];
            float k1 = base[HID + h * HD + d - HROT];
            qv = qv * c + q1 * s;
            kv = kv * c + k1 * s;
        }
    }

    float qs = qv * 0.08838834764831845f;
    __nv_bfloat16 qh = __float2bfloat16(qs);
    g_qh[idx] = qh;
    g_ql[idx] = __float2bfloat16(qs - __bfloat162float(qh));
    __nv_bfloat16 kh = __float2bfloat16(kv);
    g_kh[idx] = kh;
    g_kl[idx] = __float2bfloat16(kv - __bfloat162float(kh));
    __nv_bfloat16 vh = __float2bfloat16(vv);
    g_vh[idx] = vh;
    g_vl[idx] = __float2bfloat16(vv - __bfloat162float(vh));

    int slot = slots[t];
    size_t co = (size_t)slot * (NH * HD) + h * HD + d;
    kc_out[co] = kv;
    vc_out[co] = vv;
}

// ---------------- flash attention v5: epilogue writes 3xBF16 directly ------
#define LDT 136

__global__ __launch_bounds__(128)
void attn_mma()
{
    extern __shared__ __nv_bfloat16 sb[];
    __nv_bfloat16* Qh = sb;
    __nv_bfloat16* Ql = sb + 1 * 64 * LDT;
    __nv_bfloat16* Kh = sb + 2 * 64 * LDT;
    __nv_bfloat16* Kl = sb + 3 * 64 * LDT;
    __nv_bfloat16* Vh = sb + 4 * 64 * LDT;
    __nv_bfloat16* Vl = sb + 5 * 64 * LDT;

    const int b  = blockIdx.z;
    const int h  = blockIdx.y;
    const int qt = (int)gridDim.x - 1 - (int)blockIdx.x;
    const int tid  = threadIdx.x;
    const int warp = tid >> 5;
    const int lane = tid & 31;

    const int er = lane >> 2;
    const int ec = (lane & 3) * 2;
    const int a_r = lane & 15;
    const int a_c = (lane >> 4) * 8;
    const int b_r = (lane & 7) + ((lane >> 4) & 1) * 8;
    const int b_c = ((lane >> 3) & 1) * 8;
    const int v_r = (lane & 7) + ((lane >> 3) & 1) * 8;
    const int v_c = (lane >> 4) * 8;

    const size_t qgbase = (size_t)(b * SS + qt * 64) * HID + h * HD;
#pragma unroll
    for (int it = 0; it < 8; it++) {
        int idx = tid + it * 128;
        int row = idx >> 4, c8 = idx & 15;
        size_t g = qgbase + (size_t)row * HID + c8 * 8;
        *(float4*)(Qh + row * LDT + c8 * 8) = *(const float4*)(g_qh + g);
        *(float4*)(Ql + row * LDT + c8 * 8) = *(const float4*)(g_ql + g);
    }

    float O[16][4];
#pragma unroll
    for (int i = 0; i < 16; i++)
#pragma unroll
        for (int j = 0; j < 4; j++) O[i][j] = 0.f;
    float m0 = -1e30f, m1 = -1e30f, l0 = 0.f, l1 = 0.f;

    for (int kt = 0; kt <= qt; kt++) {
        __syncthreads();
        const size_t kgbase = (size_t)(b * SS + kt * 64) * HID + h * HD;
#pragma unroll
        for (int it = 0; it < 8; it++) {
            int idx = tid + it * 128;
            int row = idx >> 4, c8 = idx & 15;
            size_t g = kgbase + (size_t)row * HID + c8 * 8;
            uint32_t so = row * LDT + c8 * 8;
            *(float4*)(Kh + so) = *(const float4*)(g_kh + g);
            *(float4*)(Kl + so) = *(const float4*)(g_kl + g);
            *(float4*)(Vh + so) = *(const float4*)(g_vh + g);
            *(float4*)(Vl + so) = *(const float4*)(g_vl + g);
        }
        __syncthreads();

        float S[8][4];
#pragma unroll
        for (int i = 0; i < 8; i++)
#pragma unroll
            for (int j = 0; j < 4; j++) S[i][j] = 0.f;

#pragma unroll
        for (int ks = 0; ks < 8; ks++) {
            uint32_t qh4[4], ql4[4];
            ldm_x4(qh4[0], qh4[1], qh4[2], qh4[3],
                   smem_u32(&Qh[(warp * 16 + a_r) * LDT + ks * 16 + a_c]));
            ldm_x4(ql4[0], ql4[1], ql4[2], ql4[3],
                   smem_u32(&Ql[(warp * 16 + a_r) * LDT + ks * 16 + a_c]));
            uint32_t kh4[4][4], kl4[4][4];
#pragma unroll
            for (int p = 0; p < 4; p++) {
                ldm_x4(kh4[p][0], kh4[p][1], kh4[p][2], kh4[p][3],
                       smem_u32(&Kh[(p * 16 + b_r) * LDT + ks * 16 + b_c]));
                ldm_x4(kl4[p][0], kl4[p][1], kl4[p][2], kl4[p][3],
                       smem_u32(&Kl[(p * 16 + b_r) * LDT + ks * 16 + b_c]));
            }
#pragma unroll
            for (int ni = 0; ni < 8; ni++) {
                const uint32_t* bh = &kh4[ni >> 1][(ni & 1) * 2];
                const uint32_t* bl = &kl4[ni >> 1][(ni & 1) * 2];
                mma16816(S[ni], qh4, bh);
                mma16816(S[ni], ql4, bh);
                mma16816(S[ni], qh4, bl);
            }
        }

        if (kt == qt) {
            const int q0 = warp * 16 + er;
            const int q1 = q0 + 8;
#pragma unroll
            for (int ni = 0; ni < 8; ni++) {
                int key = ni * 8 + ec;
                if (key     > q0) S[ni][0] = -1e30f;
                if (key + 1 > q0) S[ni][1] = -1e30f;
                if (key     > q1) S[ni][2] = -1e30f;
                if (key + 1 > q1) S[ni][3] = -1e30f;
            }
        }

        float rx0 = -1e30f, rx1 = -1e30f;
#pragma unroll
        for (int ni = 0; ni < 8; ni++) {
            rx0 = fmaxf(rx0, fmaxf(S[ni][0], S[ni][1]));
            rx1 = fmaxf(rx1, fmaxf(S[ni][2], S[ni][3]));
        }
        rx0 = fmaxf(rx0, __shfl_xor_sync(0xffffffffu, rx0, 1));
        rx0 = fmaxf(rx0, __shfl_xor_sync(0xffffffffu, rx0, 2));
        rx1 = fmaxf(rx1, __shfl_xor_sync(0xffffffffu, rx1, 1));
        rx1 = fmaxf(rx1, __shfl_xor_sync(0xffffffffu, rx1, 2));

        float mn0 = fmaxf(m0, rx0), mn1 = fmaxf(m1, rx1);
        float c0 = __expf(m0 - mn0), c1 = __expf(m1 - mn1);
        l0 *= c0; l1 *= c1;
        m0 = mn0; m1 = mn1;
#pragma unroll
        for (int ni = 0; ni < 16; ni++) {
            O[ni][0] *= c0; O[ni][1] *= c0;
            O[ni][2] *= c1; O[ni][3] *= c1;
        }

        uint32_t PH[4][4], PL[4][4];
        float ls0 = 0.f, ls1 = 0.f;
#pragma unroll
        for (int ni = 0; ni < 8; ni++) {
            float p00 = __expf(S[ni][0] - mn0);
            float p01 = __expf(S[ni][1] - mn0);
            float p10 = __expf(S[ni][2] - mn1);
            float p11 = __expf(S[ni][3] - mn1);
            ls0 += p00 + p01;
            ls1 += p10 + p11;

            __nv_bfloat16 h00 = __float2bfloat16(p00);
            __nv_bfloat16 h01 = __float2bfloat16(p01);
            __nv_bfloat16 h10 = __float2bfloat16(p10);
            __nv_bfloat16 h11 = __float2bfloat16(p11);
            int kk = ni >> 1, base = (ni & 1) * 2;
            PH[kk][base + 0] = pack_bf16x2(__bfloat162float(h00), __bfloat162float(h01));
            PH[kk][base + 1] = pack_bf16x2(__bfloat162float(h10), __bfloat162float(h11));
            PL[kk][base + 0] = pack_bf16x2(p00 - __bfloat162float(h00),
                                           p01 - __bfloat162float(h01));
            PL[kk][base + 1] = pack_bf16x2(p10 - __bfloat162float(h10),
                                           p11 - __bfloat162float(h11));
        }
        ls0 += __shfl_xor_sync(0xffffffffu, ls0, 1);
        ls0 += __shfl_xor_sync(0xffffffffu, ls0, 2);
        ls1 += __shfl_xor_sync(0xffffffffu, ls1, 1);
        ls1 += __shfl_xor_sync(0xffffffffu, ls1, 2);
        l0 += ls0; l1 += ls1;

#pragma unroll
        for (int kk = 0; kk < 4; kk++) {
#pragma unroll
            for (int dp = 0; dp < 8; dp++) {
                uint32_t vh4[4], vl4[4];
                ldm_x4t(vh4[0], vh4[1], vh4[2], vh4[3],
                        smem_u32(&Vh[(kk * 16 + v_r) * LDT + dp * 16 + v_c]));
                ldm_x4t(vl4[0], vl4[1], vl4[2], vl4[3],
                        smem_u32(&Vl[(kk * 16 + v_r) * LDT + dp * 16 + v_c]));
                mma16816(O[dp * 2],     PH[kk], &vh4[0]);
                mma16816(O[dp * 2],     PL[kk], &vh4[0]);
                mma16816(O[dp * 2],     PH[kk], &vl4[0]);
                mma16816(O[dp * 2 + 1], PH[kk], &vh4[2]);
                mma16816(O[dp * 2 + 1], PL[kk], &vh4[2]);
                mma16816(O[dp * 2 + 1], PH[kk], &vl4[2]);
            }
        }
    }

    // epilogue: write 3xBF16 A-style segments [hi | lo | hi] directly
    float inv0 = 1.f / l0, inv1 = 1.f / l1;
    const size_t tq0 = (size_t)(b * SS + qt * 64 + warp * 16 + er);
    const size_t tq1 = tq0 + 8;
    __nv_bfloat16* r0 = g_a3 + tq0 * KP3 + h * HD;
    __nv_bfloat16* r1 = g_a3 + tq1 * KP3 + h * HD;
#pragma unroll
    for (int ni = 0; ni < 16; ni++) {
        int d = ni * 8 + ec;
        float x0 = O[ni][0] * inv0, x1 = O[ni][1] * inv0;
        float y0 = O[ni][2] * inv1, y1 = O[ni][3] * inv1;
        __nv_bfloat162 xh = __floats2bfloat162_rn(x0, x1);
        __nv_bfloat162 yh = __floats2bfloat162_rn(y0, y1);
        __nv_bfloat162 xl = __floats2bfloat162_rn(x0 - __bfloat162float(xh.x),
                                                  x1 - __bfloat162float(xh.y));
        __nv_bfloat162 yl = __floats2bfloat162_rn(y0 - __bfloat162float(yh.x),
                                                  y1 - __bfloat162float(yh.y));
        *(__nv_bfloat162*)(r0 + d)            = xh;
        *(__nv_bfloat162*)(r0 + HID + d)      = xl;
        *(__nv_bfloat162*)(r0 + 2 * HID + d)  = xh;
        *(__nv_bfloat162*)(r1 + d)            = yh;
        *(__nv_bfloat162*)(r1 + HID + d)      = yl;
        *(__nv_bfloat162*)(r1 + 2 * HID + d)  = yh;
    }
}

// ---------------- launch ----------------
extern "C" void kernel_launch(void* const* d_in, const int* in_sizes, int n_in,
                              void* d_out, int out_size)
{
    const float* hidden  = (const float*)d_in[0];
    const float* cosp    = (const float*)d_in[1];
    const float* sinp    = (const float*)d_in[2];
    const float* w_qkv   = (const float*)d_in[3];
    const float* b_qkv   = (const float*)d_in[4];
    const float* w_dense = (const float*)d_in[5];
    const float* b_dense = (const float*)d_in[6];
    const int*   slots   = (const int*)d_in[9];

    float* out = (float*)d_out;
    float* kc  = out + (size_t)TT * HID;
    float* vc  = kc + (size_t)NSLOTS * NH * HD;

    float* p_qkv;
    __nv_bfloat16 *p_h3, *p_wq3, *p_wd3, *p_a3;
    cudaGetSymbolAddress((void**)&p_qkv,  g_qkv);
    cudaGetSymbolAddress((void**)&p_h3,  g_h3);
    cudaGetSymbolAddress((void**)&p_wq3, g_wq3);
    cudaGetSymbolAddress((void**)&p_wd3, g_wd3);
    cudaGetSymbolAddress((void**)&p_a3,  g_a3);

    const int ATTN_SMEM = 6 * 64 * LDT * (int)sizeof(__nv_bfloat16);   // 104448
    const int GEMM_SMEM = NSTG * 2 * STG_BYTES;                        // 98304
    static int attr_set = 0;
    if (!attr_set) {
        cudaFuncSetAttribute(attn_mma,
                             cudaFuncAttributeMaxDynamicSharedMemorySize,
                             ATTN_SMEM);
        cudaFuncSetAttribute(gemm_mma,
                             cudaFuncAttributeMaxDynamicSharedMemorySize,
                             GEMM_SMEM);
        attr_set = 1;
    }

    // launch idx 0,1: zero both cache regions (contiguous) in one memset
    cudaMemsetAsync(kc, 0, (size_t)2 * NSLOTS * NH * HD * sizeof(float), 0);

    // idx 2: all three 3xBF16 splits in one kernel
    {
        size_t total = N_HID_EL + N_WQ_EL + N_WD_EL;   // 25165824
        fused_split<<<(unsigned)(total / 256), 256>>>(hidden, w_qkv, w_dense);
    }

    // idx 3: QKV GEMM
    {
        dim3 grid(QKV_N / 128, TT / 128);
        gemm_mma<<<grid, 128, GEMM_SMEM>>>(p_h3, p_wq3, b_qkv, p_qkv, QKV_N);
    }

    // idx 4: RoPE + bf16 planes + cache scatter
    rope_scatter<<<(TT * HID) / 256, 256>>>(cosp, sinp, slots, kc, vc);

    // idx 5: flash attention (HMMA) — profiled this round
    {
        dim3 grid(SS / 64, NH, BB);
        attn_mma<<<grid, 128, ATTN_SMEM>>>();
    }

    // idx 6: dense projection (attention epilogue already produced g_a3)
    {
        dim3 grid(HID / 128, TT / 128);
        gemm_mma<<<grid, 128, GEMM_SMEM>>>(p_a3, p_wd3, b_dense, out, HID);
    }
}

// round 14
// speedup vs baseline: 7.7797x; 1.0238x over previous
#include <cuda_runtime.h>
#include <cuda_bf16.h>
#include <stdint.h>
#include <math.h>

// ---------------- fixed problem shape ----------------
#define TT      4096
#define HID     2048
#define NH      16
#define HD      128
#define ROTD    32
#define HROT    16
#define NSLOTS  16384
#define BB      2
#define SS      2048
#define QKV_N   (3*HID)
#define KP3     (3*HID)      // 3xBF16 split K' = 6144
#define BK2     64
#define NIT2    (KP3/BK2)    // 96 iterations
#define NSTG    3            // GEMM cp.async pipeline depth
#define STG_EL  (128*64)
#define STG_BYTES (STG_EL*2)

// ---------------- device scratch (no allocs allowed) ----------------
__device__ float g_qkv[(size_t)TT * QKV_N];
__device__ __nv_bfloat16 g_h3 [(size_t)TT * KP3];
__device__ __nv_bfloat16 g_wq3[(size_t)QKV_N * KP3];
__device__ __nv_bfloat16 g_wd3[(size_t)HID * KP3];
__device__ __nv_bfloat16 g_a3 [(size_t)TT * KP3];
__device__ __nv_bfloat16 g_qh[(size_t)TT * HID];
__device__ __nv_bfloat16 g_ql[(size_t)TT * HID];
__device__ __nv_bfloat16 g_kh[(size_t)TT * HID];
__device__ __nv_bfloat16 g_kl[(size_t)TT * HID];
__device__ __nv_bfloat16 g_vh[(size_t)TT * HID];
__device__ __nv_bfloat16 g_vl[(size_t)TT * HID];

// ---------------- helpers ----------------
__device__ __forceinline__ uint32_t smem_u32(const void* p) {
    uint32_t a;
    asm("{ .reg .u64 t; cvta.to.shared.u64 t, %1; cvt.u32.u64 %0, t; }"
        : "=r"(a) : "l"(p));
    return a;
}
__device__ __forceinline__ void ldm_x4(uint32_t& r0, uint32_t& r1,
                                       uint32_t& r2, uint32_t& r3, uint32_t a) {
    asm volatile("ldmatrix.sync.aligned.m8n8.x4.shared.b16 {%0,%1,%2,%3}, [%4];"
                 : "=r"(r0), "=r"(r1), "=r"(r2), "=r"(r3) : "r"(a));
}
__device__ __forceinline__ void ldm_x4t(uint32_t& r0, uint32_t& r1,
                                        uint32_t& r2, uint32_t& r3, uint32_t a) {
    asm volatile("ldmatrix.sync.aligned.m8n8.x4.trans.shared.b16 {%0,%1,%2,%3}, [%4];"
                 : "=r"(r0), "=r"(r1), "=r"(r2), "=r"(r3) : "r"(a));
}
__device__ __forceinline__ void mma16816(float* c, const uint32_t* a,
                                         const uint32_t* b) {
    asm volatile(
        "mma.sync.aligned.m16n8k16.row.col.f32.bf16.bf16.f32 "
        "{%0,%1,%2,%3}, {%4,%5,%6,%7}, {%8,%9}, {%0,%1,%2,%3};"
        : "+f"(c[0]), "+f"(c[1]), "+f"(c[2]), "+f"(c[3])
        : "r"(a[0]), "r"(a[1]), "r"(a[2]), "r"(a[3]), "r"(b[0]), "r"(b[1]));
}
__device__ __forceinline__ uint32_t pack_bf16x2(float lo, float hi) {
    __nv_bfloat162 t = __floats2bfloat162_rn(lo, hi);
    return *reinterpret_cast<uint32_t*>(&t);
}

// ---------------- fused 3xBF16 split ---------------------------------------
#define N_HID_EL   ((size_t)TT * HID)
#define N_WQ_EL    ((size_t)QKV_N * HID)
#define N_WD_EL    ((size_t)HID * HID)
__global__ __launch_bounds__(256)
void fused_split(const float* __restrict__ hidden,
                 const float* __restrict__ w_qkv,
                 const float* __restrict__ w_dense)
{
    size_t i = (size_t)blockIdx.x * 256 + threadIdx.x;
    const float* in;
    __nv_bfloat16* out;
    int a_style;
    if (i < N_HID_EL) {
        in = hidden; out = g_h3; a_style = 1;
    } else if (i < N_HID_EL + N_WQ_EL) {
        i -= N_HID_EL;
        in = w_qkv; out = g_wq3; a_style = 0;
    } else {
        i -= N_HID_EL + N_WQ_EL;
        in = w_dense; out = g_wd3; a_style = 0;
    }
    size_t row = i >> 11;
    size_t k   = i & (HID - 1);
    float a = in[i];
    __nv_bfloat16 hi = __float2bfloat16(a);
    __nv_bfloat16 lo = __float2bfloat16(a - __bfloat162float(hi));
    __nv_bfloat16* o = out + row * KP3;
    if (a_style) {
        o[k] = hi; o[HID + k] = lo; o[2 * HID + k] = hi;
    } else {
        o[k] = hi; o[HID + k] = hi; o[2 * HID + k] = lo;
    }
}

// ---------------- HMMA GEMM v6 (unchanged) ---------------------------------
__global__ __launch_bounds__(128, 2)
void gemm_mma(const __nv_bfloat16* __restrict__ A3,
              const __nv_bfloat16* __restrict__ B3,
              const float* __restrict__ bias,
              float* __restrict__ C, int Nstride)
{
    extern __shared__ __nv_bfloat16 sg[];
    __nv_bfloat16* As = sg;
    __nv_bfloat16* Bs = sg + NSTG * STG_EL;

    const int tid  = threadIdx.x;
    const int warp = tid >> 5;
    const int lane = tid & 31;
    const int wm = warp & 1;
    const int wn = warp >> 1;
    const int m0 = blockIdx.y * 128;
    const int n0 = blockIdx.x * 128;

    float acc[32][4];
#pragma unroll
    for (int i = 0; i < 32; i++)
#pragma unroll
        for (int j = 0; j < 4; j++) acc[i][j] = 0.f;

#define PREF(stage, kt) do {                                                   \
    const __nv_bfloat16* _ab = A3 + (size_t)m0 * KP3 + (size_t)(kt) * BK2;     \
    const __nv_bfloat16* _bb = B3 + (size_t)n0 * KP3 + (size_t)(kt) * BK2;     \
    _Pragma("unroll")                                                          \
    for (int _i = 0; _i < 8; _i++) {                                           \
        int _c   = tid + _i * 128;                                             \
        int _row = _c >> 3;                                                    \
        int _ch  = _c & 7;                                                     \
        int _sw  = _ch ^ (_row & 7);                                           \
        uint32_t _so = (uint32_t)((stage) * STG_EL + _row * 64 + _sw * 8);     \
        asm volatile("cp.async.cg.shared.global [%0], [%1], 16;"               \
            :: "r"(smem_u32(As + _so)),                                        \
               "l"(_ab + (size_t)_row * KP3 + _ch * 8) : "memory");            \
        asm volatile("cp.async.cg.shared.global [%0], [%1], 16;"               \
            :: "r"(smem_u32(Bs + _so)),                                        \
               "l"(_bb + (size_t)_row * KP3 + _ch * 8) : "memory");            \
    }                                                                          \
    asm volatile("cp.async.commit_group;" ::: "memory");                       \
} while (0)

    PREF(0, 0);
    PREF(1, 1);

    const int a_r  = lane & 15;
    const int acb  = lane >> 4;
    const int b_r  = (lane & 7) + ((lane >> 4) & 1) * 8;
    const int bcb  = (lane >> 3) & 1;
    const int r7   = lane & 7;

    const uint32_t aRow = smem_u32(As) + (uint32_t)(wm * 64 + a_r) * 128;
    const uint32_t bRow = smem_u32(Bs) + (uint32_t)(wn * 64 + b_r) * 128;

    uint32_t a[2][4][4], b[2][4][4];

#define LOAD_FRAGS(bufi, aS, bS, s) do {                                       \
    const uint32_t _aOff = (uint32_t)(((2 * (s) + acb) ^ r7) * 16);            \
    const uint32_t _bOff = (uint32_t)(((2 * (s) + bcb) ^ r7) * 16);            \
    _Pragma("unroll")                                                          \
    for (int _mi = 0; _mi < 4; _mi++)                                          \
        ldm_x4(a[bufi][_mi][0], a[bufi][_mi][1],                               \
               a[bufi][_mi][2], a[bufi][_mi][3],                               \
               (aS) + (uint32_t)(_mi * 16) * 128 + _aOff);                     \
    _Pragma("unroll")                                                          \
    for (int _p = 0; _p < 4; _p++)                                             \
        ldm_x4(b[bufi][_p][0], b[bufi][_p][1],                                 \
               b[bufi][_p][2], b[bufi][_p][3],                                 \
               (bS) + (uint32_t)(_p * 16) * 128 + _bOff);                      \
} while (0)

    for (int kt = 0; kt < NIT2; kt++) {
        const int buf = kt % NSTG;

        if (kt == NIT2 - 1)
            asm volatile("cp.async.wait_group 0;" ::: "memory");
        else
            asm volatile("cp.async.wait_group 1;" ::: "memory");
        __syncthreads();

        if (kt + 2 < NIT2)
            PREF((kt + 2) % NSTG, kt + 2);

        const uint32_t aS = aRow + (uint32_t)buf * STG_BYTES;
        const uint32_t bS = bRow + (uint32_t)buf * STG_BYTES;

        LOAD_FRAGS(0, aS, bS, 0);
#pragma unroll
        for (int s = 0; s < 4; s++) {
            const int cur = s & 1;
            if (s < 3)
                LOAD_FRAGS(cur ^ 1, aS, bS, s + 1);
#pragma unroll
            for (int mi = 0; mi < 4; mi++)
#pragma unroll
                for (int ni = 0; ni < 8; ni++) {
                    const uint32_t* bf = &b[cur][ni >> 1][(ni & 1) * 2];
                    mma16816(acc[mi * 8 + ni], a[cur][mi], bf);
                }
        }
    }

    const int er = lane >> 2;
    const int ec = (lane & 3) * 2;
#pragma unroll
    for (int mi = 0; mi < 4; mi++) {
        int gm = m0 + wm * 64 + mi * 16 + er;
#pragma unroll
        for (int ni = 0; ni < 8; ni++) {
            int gn = n0 + wn * 64 + ni * 8 + ec;
            float* c = acc[mi * 8 + ni];
            float2 w0, w1;
            w0.x = c[0] + bias[gn];
            w0.y = c[1] + bias[gn + 1];
            w1.x = c[2] + bias[gn];
            w1.y = c[3] + bias[gn + 1];
            *(float2*)(C + (size_t)gm * Nstride + gn) = w0;
            *(float2*)(C + (size_t)(gm + 8) * Nstride + gn) = w1;
        }
    }
}

// ---------------- RoPE + bf16 hi/lo planes + cache scatter -----------------
__global__ __launch_bounds__(256)
void rope_scatter(const float* __restrict__ cosp, const float* __restrict__ sinp,
                  const int* __restrict__ slots,
                  float* __restrict__ kc_out, float* __restrict__ vc_out)
{
    int idx = blockIdx.x * 256 + threadIdx.x;
    int d = idx & (HD - 1);
    int h = (idx >> 7) & (NH - 1);
    int t = idx >> 11;

    const float* base = g_qkv + (size_t)t * QKV_N;
    float qv = base[h * HD + d];
    float kv = base[HID + h * HD + d];
    float vv = base[2 * HID + h * HD + d];

    if (d < ROTD) {
        if (d < HROT) {
            float c = cosp[t * HROT + d];
            float s = sinp[t * HROT + d];
            float q2 = base[h * HD + d + HROT];
            float k2 = base[HID + h * HD + d + HROT];
            qv = qv * c - q2 * s;
            kv = kv * c - k2 * s;
        } else {
            float c = cosp[t * HROT + d - HROT];
            float s = sinp[t * HROT + d - HROT];
            float q1 = base[h * HD + d - HROT];
            float k1 = base[HID + h * HD + d - HROT];
            qv = qv * c + q1 * s;
            kv = kv * c + k1 * s;
        }
    }

    float qs = qv * 0.08838834764831845f;
    __nv_bfloat16 qh = __float2bfloat16(qs);
    g_qh[idx] = qh;
    g_ql[idx] = __float2bfloat16(qs - __bfloat162float(qh));
    __nv_bfloat16 kh = __float2bfloat16(kv);
    g_kh[idx] = kh;
    g_kl[idx] = __float2bfloat16(kv - __bfloat162float(kh));
    __nv_bfloat16 vh = __float2bfloat16(vv);
    g_vh[idx] = vh;
    g_vl[idx] = __float2bfloat16(vv - __bfloat162float(vh));

    int slot = slots[t];
    size_t co = (size_t)slot * (NH * HD) + h * HD + d;
    kc_out[co] = kv;
    vc_out[co] = vv;
}

// ---------------- flash attention v6: 128q tile + cp.async K/V pipeline ----
// 256 threads / 8 warps, each warp = 16 q rows x 64 k. K/V hi/lo double-
// buffered via cp.async; loads of tile kt+1 overlap compute of tile kt.
#define LDT 136
#define KVP (64 * LDT)                  // bf16 elements per K/V plane
#define ATT_Q_EL  (2 * 128 * LDT)       // Qh+Ql
#define ATT_KV_EL (4 * KVP)             // one buffer: Kh,Kl,Vh,Vl

__global__ __launch_bounds__(256, 1)
void attn_mma()
{
    extern __shared__ __nv_bfloat16 sb[];
    __nv_bfloat16* Qh = sb;
    __nv_bfloat16* Ql = sb + 128 * LDT;
    __nv_bfloat16* KV = sb + ATT_Q_EL;  // [2][4][64*LDT]

    const int b  = blockIdx.z;
    const int h  = blockIdx.y;
    const int qt = (int)gridDim.x - 1 - (int)blockIdx.x;  // heaviest first
    const int tid  = threadIdx.x;
    const int warp = tid >> 5;
    const int lane = tid & 31;

    const int er = lane >> 2;
    const int ec = (lane & 3) * 2;
    const int a_r = lane & 15;
    const int a_c = (lane >> 4) * 8;
    const int b_r = (lane & 7) + ((lane >> 4) & 1) * 8;
    const int b_c = ((lane >> 3) & 1) * 8;
    const int v_r = (lane & 7) + ((lane >> 3) & 1) * 8;
    const int v_c = (lane >> 4) * 8;

    const int qrow_base = qt * 128;          // global q row of CTA tile
    const size_t hoff = (size_t)h * HD;

    // ---- load Q tile (128 rows) hi/lo ----
    const size_t qgbase = (size_t)(b * SS + qrow_base) * HID + hoff;
#pragma unroll
    for (int it = 0; it < 8; it++) {
        int idx = tid + it * 256;
        int row = idx >> 4, c8 = idx & 15;
        size_t g = qgbase + (size_t)row * HID + c8 * 8;
        *(float4*)(Qh + row * LDT + c8 * 8) = *(const float4*)(g_qh + g);
        *(float4*)(Ql + row * LDT + c8 * 8) = *(const float4*)(g_ql + g);
    }

    // cp.async K/V prefetch of tile kt into buffer bufi
#define APREF(bufi, kt) do {                                                   \
    const size_t _kb = (size_t)(b * SS + (kt) * 64) * HID + hoff;              \
    __nv_bfloat16* _dst = KV + (bufi) * ATT_KV_EL;                             \
    _Pragma("unroll")                                                          \
    for (int _i = 0; _i < 4; _i++) {                                           \
        int _c   = tid + _i * 256;                                             \
        int _row = _c >> 4;                                                    \
        int _c8  = (_c & 15) * 8;                                              \
        size_t _g = _kb + (size_t)_row * HID + _c8;                            \
        uint32_t _so = (uint32_t)(_row * LDT + _c8);                           \
        asm volatile("cp.async.cg.shared.global [%0], [%1], 16;"               \
            :: "r"(smem_u32(_dst + 0 * KVP + _so)), "l"(g_kh + _g) : "memory");\
        asm volatile("cp.async.cg.shared.global [%0], [%1], 16;"               \
            :: "r"(smem_u32(_dst + 1 * KVP + _so)), "l"(g_kl + _g) : "memory");\
        asm volatile("cp.async.cg.shared.global [%0], [%1], 16;"               \
            :: "r"(smem_u32(_dst + 2 * KVP + _so)), "l"(g_vh + _g) : "memory");\
        asm volatile("cp.async.cg.shared.global [%0], [%1], 16;"               \
            :: "r"(smem_u32(_dst + 3 * KVP + _so)), "l"(g_vl + _g) : "memory");\
    }                                                                          \
    asm volatile("cp.async.commit_group;" ::: "memory");                       \
} while (0)

    float O[16][4];
#pragma unroll
    for (int i = 0; i < 16; i++)
#pragma unroll
        for (int j = 0; j < 4; j++) O[i][j] = 0.f;
    float m0 = -1e30f, m1 = -1e30f, l0 = 0.f, l1 = 0.f;

    const int ntiles = 2 * qt + 2;
    APREF(0, 0);

    for (int kt = 0; kt < ntiles; kt++) {
        const int bufi = kt & 1;
        if (kt + 1 < ntiles) {
            APREF(bufi ^ 1, kt + 1);
            asm volatile("cp.async.wait_group 1;" ::: "memory");
        } else {
            asm volatile("cp.async.wait_group 0;" ::: "memory");
        }
        __syncthreads();   // tile kt visible to all warps

        // warp-uniform skip: whole k-tile above this warp's q rows
        const bool skip = (kt * 64 > qrow_base + warp * 16 + 15);
        if (!skip) {
            const __nv_bfloat16* Kh = KV + bufi * ATT_KV_EL;
            const __nv_bfloat16* Kl = Kh + KVP;
            const __nv_bfloat16* Vh = Kh + 2 * KVP;
            const __nv_bfloat16* Vl = Kh + 3 * KVP;

            float S[8][4];
#pragma unroll
            for (int i = 0; i < 8; i++)
#pragma unroll
                for (int j = 0; j < 4; j++) S[i][j] = 0.f;

#pragma unroll
            for (int ks = 0; ks < 8; ks++) {
                uint32_t qh4[4], ql4[4];
                ldm_x4(qh4[0], qh4[1], qh4[2], qh4[3],
                       smem_u32(&Qh[(warp * 16 + a_r) * LDT + ks * 16 + a_c]));
                ldm_x4(ql4[0], ql4[1], ql4[2], ql4[3],
                       smem_u32(&Ql[(warp * 16 + a_r) * LDT + ks * 16 + a_c]));
                uint32_t kh4[4][4], kl4[4][4];
#pragma unroll
                for (int p = 0; p < 4; p++) {
                    ldm_x4(kh4[p][0], kh4[p][1], kh4[p][2], kh4[p][3],
                           smem_u32(&Kh[(p * 16 + b_r) * LDT + ks * 16 + b_c]));
                    ldm_x4(kl4[p][0], kl4[p][1], kl4[p][2], kl4[p][3],
                           smem_u32(&Kl[(p * 16 + b_r) * LDT + ks * 16 + b_c]));
                }
#pragma unroll
                for (int ni = 0; ni < 8; ni++) {
                    const uint32_t* bh = &kh4[ni >> 1][(ni & 1) * 2];
                    const uint32_t* bl = &kl4[ni >> 1][(ni & 1) * 2];
                    mma16816(S[ni], qh4, bh);
                    mma16816(S[ni], ql4, bh);
                    mma16816(S[ni], qh4, bl);
                }
            }

            // causal mask (global coordinates), only near the diagonal
            if (kt >= 2 * qt) {
                const int q0 = qrow_base + warp * 16 + er;
                const int q1 = q0 + 8;
                const int kbase = kt * 64;
#pragma unroll
                for (int ni = 0; ni < 8; ni++) {
                    int key = kbase + ni * 8 + ec;
                    if (key     > q0) S[ni][0] = -1e30f;
                    if (key + 1 > q0) S[ni][1] = -1e30f;
                    if (key     > q1) S[ni][2] = -1e30f;
                    if (key + 1 > q1) S[ni][3] = -1e30f;
                }
            }

            float rx0 = -1e30f, rx1 = -1e30f;
#pragma unroll
            for (int ni = 0; ni < 8; ni++) {
                rx0 = fmaxf(rx0, fmaxf(S[ni][0], S[ni][1]));
                rx1 = fmaxf(rx1, fmaxf(S[ni][2], S[ni][3]));
            }
            rx0 = fmaxf(rx0, __shfl_xor_sync(0xffffffffu, rx0, 1));
            rx0 = fmaxf(rx0, __shfl_xor_sync(0xffffffffu, rx0, 2));
            rx1 = fmaxf(rx1, __shfl_xor_sync(0xffffffffu, rx1, 1));
            rx1 = fmaxf(rx1, __shfl_xor_sync(0xffffffffu, rx1, 2));

            float mn0 = fmaxf(m0, rx0), mn1 = fmaxf(m1, rx1);
            float c0 = __expf(m0 - mn0), c1 = __expf(m1 - mn1);
            l0 *= c0; l1 *= c1;
            m0 = mn0; m1 = mn1;
#pragma unroll
            for (int ni = 0; ni < 16; ni++) {
                O[ni][0] *= c0; O[ni][1] *= c0;
                O[ni][2] *= c1; O[ni][3] *= c1;
            }

            uint32_t PH[4][4], PL[4][4];
            float ls0 = 0.f, ls1 = 0.f;
#pragma unroll
            for (int ni = 0; ni < 8; ni++) {
                float p00 = __expf(S[ni][0] - mn0);
                float p01 = __expf(S[ni][1] - mn0);
                float p10 = __expf(S[ni][2] - mn1);
                float p11 = __expf(S[ni][3] - mn1);
                ls0 += p00 + p01;
                ls1 += p10 + p11;

                __nv_bfloat16 h00 = __float2bfloat16(p00);
                __nv_bfloat16 h01 = __float2bfloat16(p01);
                __nv_bfloat16 h10 = __float2bfloat16(p10);
                __nv_bfloat16 h11 = __float2bfloat16(p11);
                int kk = ni >> 1, base = (ni & 1) * 2;
                PH[kk][base + 0] = pack_bf16x2(__bfloat162float(h00), __bfloat162float(h01));
                PH[kk][base + 1] = pack_bf16x2(__bfloat162float(h10), __bfloat162float(h11));
                PL[kk][base + 0] = pack_bf16x2(p00 - __bfloat162float(h00),
                                               p01 - __bfloat162float(h01));
                PL[kk][base + 1] = pack_bf16x2(p10 - __bfloat162float(h10),
                                               p11 - __bfloat162float(h11));
            }
            ls0 += __shfl_xor_sync(0xffffffffu, ls0, 1);
            ls0 += __shfl_xor_sync(0xffffffffu, ls0, 2);
            ls1 += __shfl_xor_sync(0xffffffffu, ls1, 1);
            ls1 += __shfl_xor_sync(0xffffffffu, ls1, 2);
            l0 += ls0; l1 += ls1;

#pragma unroll
            for (int kk = 0; kk < 4; kk++) {
#pragma unroll
                for (int dp = 0; dp < 8; dp++) {
                    uint32_t vh4[4], vl4[4];
                    ldm_x4t(vh4[0], vh4[1], vh4[2], vh4[3],
                            smem_u32(&Vh[(kk * 16 + v_r) * LDT + dp * 16 + v_c]));
                    ldm_x4t(vl4[0], vl4[1], vl4[2], vl4[3],
                            smem_u32(&Vl[(kk * 16 + v_r) * LDT + dp * 16 + v_c]));
                    mma16816(O[dp * 2],     PH[kk], &vh4[0]);
                    mma16816(O[dp * 2],     PL[kk], &vh4[0]);
                    mma16816(O[dp * 2],     PH[kk], &vl4[0]);
                    mma16816(O[dp * 2 + 1], PH[kk], &vh4[2]);
                    mma16816(O[dp * 2 + 1], PL[kk], &vh4[2]);
                    mma16816(O[dp * 2 + 1], PH[kk], &vl4[2]);
                }
            }
        }
        __syncthreads();   // all warps done reading buffer bufi (WAR)
    }

    // epilogue: write 3xBF16 A-style segments [hi | lo | hi] directly
    float inv0 = 1.f / l0, inv1 = 1.f / l1;
    const size_t tq0 = (size_t)(b * SS + qrow_base + warp * 16 + er);
    const size_t tq1 = tq0 + 8;
    __nv_bfloat16* r0 = g_a3 + tq0 * KP3 + hoff;
    __nv_bfloat16* r1 = g_a3 + tq1 * KP3 + hoff;
#pragma unroll
    for (int ni = 0; ni < 16; ni++) {
        int d = ni * 8 + ec;
        float x0 = O[ni][0] * inv0, x1 = O[ni][1] * inv0;
        float y0 = O[ni][2] * inv1, y1 = O[ni][3] * inv1;
        __nv_bfloat162 xh = __floats2bfloat162_rn(x0, x1);
        __nv_bfloat162 yh = __floats2bfloat162_rn(y0, y1);
        __nv_bfloat162 xl = __floats2bfloat162_rn(x0 - __bfloat162float(xh.x),
                                                  x1 - __bfloat162float(xh.y));
        __nv_bfloat162 yl = __floats2bfloat162_rn(y0 - __bfloat162float(yh.x),
                                                  y1 - __bfloat162float(yh.y));
        *(__nv_bfloat162*)(r0 + d)            = xh;
        *(__nv_bfloat162*)(r0 + HID + d)      = xl;
        *(__nv_bfloat162*)(r0 + 2 * HID + d)  = xh;
        *(__nv_bfloat162*)(r1 + d)            = yh;
        *(__nv_bfloat162*)(r1 + HID + d)      = yl;
        *(__nv_bfloat162*)(r1 + 2 * HID + d)  = yh;
    }
}

// ---------------- launch ----------------
extern "C" void kernel_launch(void* const* d_in, const int* in_sizes, int n_in,
                              void* d_out, int out_size)
{
    const float* hidden  = (const float*)d_in[0];
    const float* cosp    = (const float*)d_in[1];
    const float* sinp    = (const float*)d_in[2];
    const float* w_qkv   = (const float*)d_in[3];
    const float* b_qkv   = (const float*)d_in[4];
    const float* w_dense = (const float*)d_in[5];
    const float* b_dense = (const float*)d_in[6];
    const int*   slots   = (const int*)d_in[9];

    float* out = (float*)d_out;
    float* kc  = out + (size_t)TT * HID;
    float* vc  = kc + (size_t)NSLOTS * NH * HD;

    float* p_qkv;
    __nv_bfloat16 *p_h3, *p_wq3, *p_wd3, *p_a3;
    cudaGetSymbolAddress((void**)&p_qkv,  g_qkv);
    cudaGetSymbolAddress((void**)&p_h3,  g_h3);
    cudaGetSymbolAddress((void**)&p_wq3, g_wq3);
    cudaGetSymbolAddress((void**)&p_wd3, g_wd3);
    cudaGetSymbolAddress((void**)&p_a3,  g_a3);

    const int ATTN_SMEM = (ATT_Q_EL + 2 * ATT_KV_EL) * (int)sizeof(__nv_bfloat16); // 208896
    const int GEMM_SMEM = NSTG * 2 * STG_BYTES;                                    // 98304
    static int attr_set = 0;
    if (!attr_set) {
        cudaFuncSetAttribute(attn_mma,
                             cudaFuncAttributeMaxDynamicSharedMemorySize,
                             ATTN_SMEM);
        cudaFuncSetAttribute(gemm_mma,
                             cudaFuncAttributeMaxDynamicSharedMemorySize,
                             GEMM_SMEM);
        attr_set = 1;
    }

    // idx 0,1: zero both cache regions (contiguous) in one memset
    cudaMemsetAsync(kc, 0, (size_t)2 * NSLOTS * NH * HD * sizeof(float), 0);

    // idx 2: fused 3xBF16 splits
    {
        size_t total = N_HID_EL + N_WQ_EL + N_WD_EL;
        fused_split<<<(unsigned)(total / 256), 256>>>(hidden, w_qkv, w_dense);
    }

    // idx 3: QKV GEMM
    {
        dim3 grid(QKV_N / 128, TT / 128);
        gemm_mma<<<grid, 128, GEMM_SMEM>>>(p_h3, p_wq3, b_qkv, p_qkv, QKV_N);
    }

    // idx 4: RoPE + bf16 planes + cache scatter
    rope_scatter<<<(TT * HID) / 256, 256>>>(cosp, sinp, slots, kc, vc);

    // idx 5: flash attention v6 (profiled)
    {
        dim3 grid(SS / 128, NH, BB);
        attn_mma<<<grid, 256, ATTN_SMEM>>>();
    }

    // idx 6: dense projection
    {
        dim3 grid(HID / 128, TT / 128);
        gemm_mma<<<grid, 128, GEMM_SMEM>>>(p_a3, p_wd3, b_dense, out, HID);
    }
}

// round 15
// speedup vs baseline: 7.8422x; 1.0080x over previous
#include <cuda_runtime.h>
#include <cuda_bf16.h>
#include <stdint.h>
#include <math.h>

// ---------------- fixed problem shape ----------------
#define TT      4096
#define HID     2048
#define NH      16
#define HD      128
#define ROTD    32
#define HROT    16
#define NSLOTS  16384
#define BB      2
#define SS      2048
#define QKV_N   (3*HID)
#define KP3     (3*HID)
#define BK2     64
#define NIT2    (KP3/BK2)
#define NSTG    3
#define STG_EL  (128*64)
#define STG_BYTES (STG_EL*2)

// ---------------- device scratch ----------------
__device__ float g_qkv[(size_t)TT * QKV_N];
__device__ __nv_bfloat16 g_h3 [(size_t)TT * KP3];
__device__ __nv_bfloat16 g_wq3[(size_t)QKV_N * KP3];
__device__ __nv_bfloat16 g_wd3[(size_t)HID * KP3];
__device__ __nv_bfloat16 g_a3 [(size_t)TT * KP3];
__device__ __nv_bfloat16 g_qh[(size_t)TT * HID];
__device__ __nv_bfloat16 g_ql[(size_t)TT * HID];
__device__ __nv_bfloat16 g_kh[(size_t)TT * HID];
__device__ __nv_bfloat16 g_kl[(size_t)TT * HID];
__device__ __nv_bfloat16 g_vh[(size_t)TT * HID];
__device__ __nv_bfloat16 g_vl[(size_t)TT * HID];

// ---------------- helpers ----------------
__device__ __forceinline__ uint32_t smem_u32(const void* p) {
    uint32_t a;
    asm("{ .reg .u64 t; cvta.to.shared.u64 t, %1; cvt.u32.u64 %0, t; }"
        : "=r"(a) : "l"(p));
    return a;
}
__device__ __forceinline__ void ldm_x4(uint32_t& r0, uint32_t& r1,
                                       uint32_t& r2, uint32_t& r3, uint32_t a) {
    asm volatile("ldmatrix.sync.aligned.m8n8.x4.shared.b16 {%0,%1,%2,%3}, [%4];"
                 : "=r"(r0), "=r"(r1), "=r"(r2), "=r"(r3) : "r"(a));
}
__device__ __forceinline__ void ldm_x4t(uint32_t& r0, uint32_t& r1,
                                        uint32_t& r2, uint32_t& r3, uint32_t a) {
    asm volatile("ldmatrix.sync.aligned.m8n8.x4.trans.shared.b16 {%0,%1,%2,%3}, [%4];"
                 : "=r"(r0), "=r"(r1), "=r"(r2), "=r"(r3) : "r"(a));
}
__device__ __forceinline__ void mma16816(float* c, const uint32_t* a,
                                         const uint32_t* b) {
    asm volatile(
        "mma.sync.aligned.m16n8k16.row.col.f32.bf16.bf16.f32 "
        "{%0,%1,%2,%3}, {%4,%5,%6,%7}, {%8,%9}, {%0,%1,%2,%3};"
        : "+f"(c[0]), "+f"(c[1]), "+f"(c[2]), "+f"(c[3])
        : "r"(a[0]), "r"(a[1]), "r"(a[2]), "r"(a[3]), "r"(b[0]), "r"(b[1]));
}
__device__ __forceinline__ uint32_t pack_bf16x2(float lo, float hi) {
    __nv_bfloat162 t = __floats2bfloat162_rn(lo, hi);
    return *reinterpret_cast<uint32_t*>(&t);
}

// ---------------- fused 3xBF16 split ----------------
#define N_HID_EL   ((size_t)TT * HID)
#define N_WQ_EL    ((size_t)QKV_N * HID)
#define N_WD_EL    ((size_t)HID * HID)
__global__ __launch_bounds__(256)
void fused_split(const float* __restrict__ hidden,
                 const float* __restrict__ w_qkv,
                 const float* __restrict__ w_dense)
{
    size_t i = (size_t)blockIdx.x * 256 + threadIdx.x;
    const float* in;
    __nv_bfloat16* out;
    int a_style;
    if (i < N_HID_EL) {
        in = hidden; out = g_h3; a_style = 1;
    } else if (i < N_HID_EL + N_WQ_EL) {
        i -= N_HID_EL;
        in = w_qkv; out = g_wq3; a_style = 0;
    } else {
        i -= N_HID_EL + N_WQ_EL;
        in = w_dense; out = g_wd3; a_style = 0;
    }
    size_t row = i >> 11;
    size_t k   = i & (HID - 1);
    float a = in[i];
    __nv_bfloat16 hi = __float2bfloat16(a);
    __nv_bfloat16 lo = __float2bfloat16(a - __bfloat162float(hi));
    __nv_bfloat16* o = out + row * KP3;
    if (a_style) {
        o[k] = hi; o[HID + k] = lo; o[2 * HID + k] = hi;
    } else {
        o[k] = hi; o[HID + k] = hi; o[2 * HID + k] = lo;
    }
}

// ---------------- spacer ----------------
__global__ void nop_kernel() {}

// ---------------- HMMA GEMM v6 (frozen) ----------------
__global__ __launch_bounds__(128, 2)
void gemm_mma(const __nv_bfloat16* __restrict__ A3,
              const __nv_bfloat16* __restrict__ B3,
              const float* __restrict__ bias,
              float* __restrict__ C, int Nstride)
{
    extern __shared__ __nv_bfloat16 sg[];
    __nv_bfloat16* As = sg;
    __nv_bfloat16* Bs = sg + NSTG * STG_EL;

    const int tid  = threadIdx.x;
    const int warp = tid >> 5;
    const int lane = tid & 31;
    const int wm = warp & 1;
    const int wn = warp >> 1;
    const int m0 = blockIdx.y * 128;
    const int n0 = blockIdx.x * 128;

    float acc[32][4];
#pragma unroll
    for (int i = 0; i < 32; i++)
#pragma unroll
        for (int j = 0; j < 4; j++) acc[i][j] = 0.f;

#define PREF(stage, kt) do {                                                   \
    const __nv_bfloat16* _ab = A3 + (size_t)m0 * KP3 + (size_t)(kt) * BK2;     \
    const __nv_bfloat16* _bb = B3 + (size_t)n0 * KP3 + (size_t)(kt) * BK2;     \
    _Pragma("unroll")                                                          \
    for (int _i = 0; _i < 8; _i++) {                                           \
        int _c   = tid + _i * 128;                                             \
        int _row = _c >> 3;                                                    \
        int _ch  = _c & 7;                                                     \
        int _sw  = _ch ^ (_row & 7);                                           \
        uint32_t _so = (uint32_t)((stage) * STG_EL + _row * 64 + _sw * 8);     \
        asm volatile("cp.async.cg.shared.global [%0], [%1], 16;"               \
            :: "r"(smem_u32(As + _so)),                                        \
               "l"(_ab + (size_t)_row * KP3 + _ch * 8) : "memory");            \
        asm volatile("cp.async.cg.shared.global [%0], [%1], 16;"               \
            :: "r"(smem_u32(Bs + _so)),                                        \
               "l"(_bb + (size_t)_row * KP3 + _ch * 8) : "memory");            \
    }                                                                          \
    asm volatile("cp.async.commit_group;" ::: "memory");                       \
} while (0)

    PREF(0, 0);
    PREF(1, 1);

    const int a_r  = lane & 15;
    const int acb  = lane >> 4;
    const int b_r  = (lane & 7) + ((lane >> 4) & 1) * 8;
    const int bcb  = (lane >> 3) & 1;
    const int r7   = lane & 7;

    const uint32_t aRow = smem_u32(As) + (uint32_t)(wm * 64 + a_r) * 128;
    const uint32_t bRow = smem_u32(Bs) + (uint32_t)(wn * 64 + b_r) * 128;

    uint32_t a[2][4][4], b[2][4][4];

#define LOAD_FRAGS(bufi, aS, bS, s) do {                                       \
    const uint32_t _aOff = (uint32_t)(((2 * (s) + acb) ^ r7) * 16);            \
    const uint32_t _bOff = (uint32_t)(((2 * (s) + bcb) ^ r7) * 16);            \
    _Pragma("unroll")                                                          \
    for (int _mi = 0; _mi < 4; _mi++)                                          \
        ldm_x4(a[bufi][_mi][0], a[bufi][_mi][1],                               \
               a[bufi][_mi][2], a[bufi][_mi][3],                               \
               (aS) + (uint32_t)(_mi * 16) * 128 + _aOff);                     \
    _Pragma("unroll")                                                          \
    for (int _p = 0; _p < 4; _p++)                                             \
        ldm_x4(b[bufi][_p][0], b[bufi][_p][1],                                 \
               b[bufi][_p][2], b[bufi][_p][3],                                 \
               (bS) + (uint32_t)(_p * 16) * 128 + _bOff);                      \
} while (0)

    for (int kt = 0; kt < NIT2; kt++) {
        const int buf = kt % NSTG;

        if (kt == NIT2 - 1)
            asm volatile("cp.async.wait_group 0;" ::: "memory");
        else
            asm volatile("cp.async.wait_group 1;" ::: "memory");
        __syncthreads();

        if (kt + 2 < NIT2)
            PREF((kt + 2) % NSTG, kt + 2);

        const uint32_t aS = aRow + (uint32_t)buf * STG_BYTES;
        const uint32_t bS = bRow + (uint32_t)buf * STG_BYTES;

        LOAD_FRAGS(0, aS, bS, 0);
#pragma unroll
        for (int s = 0; s < 4; s++) {
            const int cur = s & 1;
            if (s < 3)
                LOAD_FRAGS(cur ^ 1, aS, bS, s + 1);
#pragma unroll
            for (int mi = 0; mi < 4; mi++)
#pragma unroll
                for (int ni = 0; ni < 8; ni++) {
                    const uint32_t* bf = &b[cur][ni >> 1][(ni & 1) * 2];
                    mma16816(acc[mi * 8 + ni], a[cur][mi], bf);
                }
        }
    }

    const int er = lane >> 2;
    const int ec = (lane & 3) * 2;
#pragma unroll
    for (int mi = 0; mi < 4; mi++) {
        int gm = m0 + wm * 64 + mi * 16 + er;
#pragma unroll
        for (int ni = 0; ni < 8; ni++) {
            int gn = n0 + wn * 64 + ni * 8 + ec;
            float* c = acc[mi * 8 + ni];
            float2 w0, w1;
            w0.x = c[0] + bias[gn];
            w0.y = c[1] + bias[gn + 1];
            w1.x = c[2] + bias[gn];
            w1.y = c[3] + bias[gn + 1];
            *(float2*)(C + (size_t)gm * Nstride + gn) = w0;
            *(float2*)(C + (size_t)(gm + 8) * Nstride + gn) = w1;
        }
    }
}

// ---------------- RoPE + planes + cache scatter + zero of unused slots -----
// blocks [0, ROPE_BLKS): rope for t in [0,TT); writes kc/vc at slots[t].
// blocks [ROPE_BLKS, ..): zero cache slots [TT, NSLOTS) (float4 stores).
#define ROPE_BLKS  ((TT * HID) / 256)                       // 32768
#define ZERO_F4    (((size_t)(NSLOTS - TT) * NH * HD) / 4)  // 6291456
#define ZERO_BLKS  ((int)(ZERO_F4 / 256))                   // 24576

__global__ __launch_bounds__(256)
void rope_zero(const float* __restrict__ cosp, const float* __restrict__ sinp,
               const int* __restrict__ slots,
               float* __restrict__ kc_out, float* __restrict__ vc_out)
{
    int bid = blockIdx.x;
    if (bid >= ROPE_BLKS) {
        // zero the never-written cache slots
        size_t zi = (size_t)(bid - ROPE_BLKS) * 256 + threadIdx.x;
        size_t off = (size_t)TT * NH * HD + zi * 4;
        float4 z = make_float4(0.f, 0.f, 0.f, 0.f);
        *(float4*)(kc_out + off) = z;
        *(float4*)(vc_out + off) = z;
        return;
    }

    int idx = bid * 256 + threadIdx.x;
    int d = idx & (HD - 1);
    int h = (idx >> 7) & (NH - 1);
    int t = idx >> 11;

    const float* base = g_qkv + (size_t)t * QKV_N;
    float qv = base[h * HD + d];
    float kv = base[HID + h * HD + d];
    float vv = base[2 * HID + h * HD + d];

    if (d < ROTD) {
        if (d < HROT) {
            float c = cosp[t * HROT + d];
            float s = sinp[t * HROT + d];
            float q2 = base[h * HD + d + HROT];
            float k2 = base[HID + h * HD + d + HROT];
            qv = qv * c - q2 * s;
            kv = kv * c - k2 * s;
        } else {
            float c = cosp[t * HROT + d - HROT];
            float s = sinp[t * HROT + d - HROT];
            float q1 = base[h * HD + d - HROT];
            float k1 = base[HID + h * HD + d - HROT];
            qv = qv * c + q1 * s;
            kv = kv * c + k1 * s;
        }
    }

    float qs = qv * 0.08838834764831845f;
    __nv_bfloat16 qh = __float2bfloat16(qs);
    g_qh[idx] = qh;
    g_ql[idx] = __float2bfloat16(qs - __bfloat162float(qh));
    __nv_bfloat16 kh = __float2bfloat16(kv);
    g_kh[idx] = kh;
    g_kl[idx] = __float2bfloat16(kv - __bfloat162float(kh));
    __nv_bfloat16 vh = __float2bfloat16(vv);
    g_vh[idx] = vh;
    g_vl[idx] = __float2bfloat16(vv - __bfloat162float(vh));

    int slot = slots[t];
    size_t co = (size_t)slot * (NH * HD) + h * HD + d;
    kc_out[co] = kv;
    vc_out[co] = vv;
}

// ---------------- flash attention v7: fewer softmax instructions -----------
#define LDT 136
#define KVP (64 * LDT)
#define ATT_Q_EL  (2 * 128 * LDT)
#define ATT_KV_EL (4 * KVP)

__global__ __launch_bounds__(256, 1)
void attn_mma()
{
    extern __shared__ __nv_bfloat16 sb[];
    __nv_bfloat16* Qh = sb;
    __nv_bfloat16* Ql = sb + 128 * LDT;
    __nv_bfloat16* KV = sb + ATT_Q_EL;

    const int b  = blockIdx.z;
    const int h  = blockIdx.y;
    const int qt = (int)gridDim.x - 1 - (int)blockIdx.x;
    const int tid  = threadIdx.x;
    const int warp = tid >> 5;
    const int lane = tid & 31;

    const int er = lane >> 2;
    const int ec = (lane & 3) * 2;
    const int a_r = lane & 15;
    const int a_c = (lane >> 4) * 8;
    const int b_r = (lane & 7) + ((lane >> 4) & 1) * 8;
    const int b_c = ((lane >> 3) & 1) * 8;
    const int v_r = (lane & 7) + ((lane >> 3) & 1) * 8;
    const int v_c = (lane >> 4) * 8;

    const int qrow_base = qt * 128;
    const size_t hoff = (size_t)h * HD;

    const size_t qgbase = (size_t)(b * SS + qrow_base) * HID + hoff;
#pragma unroll
    for (int it = 0; it < 8; it++) {
        int idx = tid + it * 256;
        int row = idx >> 4, c8 = idx & 15;
        size_t g = qgbase + (size_t)row * HID + c8 * 8;
        *(float4*)(Qh + row * LDT + c8 * 8) = *(const float4*)(g_qh + g);
        *(float4*)(Ql + row * LDT + c8 * 8) = *(const float4*)(g_ql + g);
    }

#define APREF(bufi, kt) do {                                                   \
    const size_t _kb = (size_t)(b * SS + (kt) * 64) * HID + hoff;              \
    __nv_bfloat16* _dst = KV + (bufi) * ATT_KV_EL;                             \
    _Pragma("unroll")                                                          \
    for (int _i = 0; _i < 4; _i++) {                                           \
        int _c   = tid + _i * 256;                                             \
        int _row = _c >> 4;                                                    \
        int _c8  = (_c & 15) * 8;                                              \
        size_t _g = _kb + (size_t)_row * HID + _c8;                            \
        uint32_t _so = (uint32_t)(_row * LDT + _c8);                           \
        asm volatile("cp.async.cg.shared.global [%0], [%1], 16;"               \
            :: "r"(smem_u32(_dst + 0 * KVP + _so)), "l"(g_kh + _g) : "memory");\
        asm volatile("cp.async.cg.shared.global [%0], [%1], 16;"               \
            :: "r"(smem_u32(_dst + 1 * KVP + _so)), "l"(g_kl + _g) : "memory");\
        asm volatile("cp.async.cg.shared.global [%0], [%1], 16;"               \
            :: "r"(smem_u32(_dst + 2 * KVP + _so)), "l"(g_vh + _g) : "memory");\
        asm volatile("cp.async.cg.shared.global [%0], [%1], 16;"               \
            :: "r"(smem_u32(_dst + 3 * KVP + _so)), "l"(g_vl + _g) : "memory");\
    }                                                                          \
    asm volatile("cp.async.commit_group;" ::: "memory");                       \
} while (0)

    float O[16][4];
#pragma unroll
    for (int i = 0; i < 16; i++)
#pragma unroll
        for (int j = 0; j < 4; j++) O[i][j] = 0.f;
    float m0 = -1e30f, m1 = -1e30f, l0 = 0.f, l1 = 0.f;

    const int ntiles = 2 * qt + 2;
    APREF(0, 0);

    for (int kt = 0; kt < ntiles; kt++) {
        const int bufi = kt & 1;
        if (kt + 1 < ntiles) {
            APREF(bufi ^ 1, kt + 1);
            asm volatile("cp.async.wait_group 1;" ::: "memory");
        } else {
            asm volatile("cp.async.wait_group 0;" ::: "memory");
        }
        __syncthreads();

        const bool skip = (kt * 64 > qrow_base + warp * 16 + 15);
        if (!skip) {
            const __nv_bfloat16* Kh = KV + bufi * ATT_KV_EL;
            const __nv_bfloat16* Kl = Kh + KVP;
            const __nv_bfloat16* Vh = Kh + 2 * KVP;
            const __nv_bfloat16* Vl = Kh + 3 * KVP;

            float S[8][4];
#pragma unroll
            for (int i = 0; i < 8; i++)
#pragma unroll
                for (int j = 0; j < 4; j++) S[i][j] = 0.f;

#pragma unroll
            for (int ks = 0; ks < 8; ks++) {
                uint32_t qh4[4], ql4[4];
                ldm_x4(qh4[0], qh4[1], qh4[2], qh4[3],
                       smem_u32(&Qh[(warp * 16 + a_r) * LDT + ks * 16 + a_c]));
                ldm_x4(ql4[0], ql4[1], ql4[2], ql4[3],
                       smem_u32(&Ql[(warp * 16 + a_r) * LDT + ks * 16 + a_c]));
                uint32_t kh4[4][4], kl4[4][4];
#pragma unroll
                for (int p = 0; p < 4; p++) {
                    ldm_x4(kh4[p][0], kh4[p][1], kh4[p][2], kh4[p][3],
                           smem_u32(&Kh[(p * 16 + b_r) * LDT + ks * 16 + b_c]));
                    ldm_x4(kl4[p][0], kl4[p][1], kl4[p][2], kl4[p][3],
                           smem_u32(&Kl[(p * 16 + b_r) * LDT + ks * 16 + b_c]));
                }
#pragma unroll
                for (int ni = 0; ni < 8; ni++) {
                    const uint32_t* bh = &kh4[ni >> 1][(ni & 1) * 2];
                    const uint32_t* bl = &kl4[ni >> 1][(ni & 1) * 2];
                    mma16816(S[ni], qh4, bh);
                    mma16816(S[ni], ql4, bh);
                    mma16816(S[ni], qh4, bl);
                }
            }

            if (kt >= 2 * qt) {
                const int q0 = qrow_base + warp * 16 + er;
                const int q1 = q0 + 8;
                const int kbase = kt * 64;
#pragma unroll
                for (int ni = 0; ni < 8; ni++) {
                    int key = kbase + ni * 8 + ec;
                    if (key     > q0) S[ni][0] = -1e30f;
                    if (key + 1 > q0) S[ni][1] = -1e30f;
                    if (key     > q1) S[ni][2] = -1e30f;
                    if (key + 1 > q1) S[ni][3] = -1e30f;
                }
            }

            float rx0 = -1e30f, rx1 = -1e30f;
#pragma unroll
            for (int ni = 0; ni < 8; ni++) {
                rx0 = fmaxf(rx0, fmaxf(S[ni][0], S[ni][1]));
                rx1 = fmaxf(rx1, fmaxf(S[ni][2], S[ni][3]));
            }
            rx0 = fmaxf(rx0, __shfl_xor_sync(0xffffffffu, rx0, 1));
            rx0 = fmaxf(rx0, __shfl_xor_sync(0xffffffffu, rx0, 2));
            rx1 = fmaxf(rx1, __shfl_xor_sync(0xffffffffu, rx1, 1));
            rx1 = fmaxf(rx1, __shfl_xor_sync(0xffffffffu, rx1, 2));

            float mn0 = fmaxf(m0, rx0), mn1 = fmaxf(m1, rx1);
            // skip the rescale entirely when no lane's max moved (corr==1.0)
            bool changed = (mn0 != m0) || (mn1 != m1);
            if (__any_sync(0xffffffffu, changed)) {
                float c0 = __expf(m0 - mn0), c1 = __expf(m1 - mn1);
                l0 *= c0; l1 *= c1;
#pragma unroll
                for (int ni = 0; ni < 16; ni++) {
                    O[ni][0] *= c0; O[ni][1] *= c0;
                    O[ni][2] *= c1; O[ni][3] *= c1;
                }
            }
            m0 = mn0; m1 = mn1;

            uint32_t PH[4][4], PL[4][4];
            float ls0 = 0.f, ls1 = 0.f;
#pragma unroll
            for (int ni = 0; ni < 8; ni++) {
                float p00 = __expf(S[ni][0] - mn0);
                float p01 = __expf(S[ni][1] - mn0);
                float p10 = __expf(S[ni][2] - mn1);
                float p11 = __expf(S[ni][3] - mn1);
                ls0 += p00 + p01;
                ls1 += p10 + p11;

                int kk = ni >> 1, base = (ni & 1) * 2;
                // PH directly via packed cvt; recover hi-as-float from bits
                uint32_t ph0 = pack_bf16x2(p00, p01);
                uint32_t ph1 = pack_bf16x2(p10, p11);
                PH[kk][base + 0] = ph0;
                PH[kk][base + 1] = ph1;
                float h00f = __uint_as_float(ph0 << 16);
                float h01f = __uint_as_float(ph0 & 0xffff0000u);
                float h10f = __uint_as_float(ph1 << 16);
                float h11f = __uint_as_float(ph1 & 0xffff0000u);
                PL[kk][base + 0] = pack_bf16x2(p00 - h00f, p01 - h01f);
                PL[kk][base + 1] = pack_bf16x2(p10 - h10f, p11 - h11f);
            }
            ls0 += __shfl_xor_sync(0xffffffffu, ls0, 1);
            ls0 += __shfl_xor_sync(0xffffffffu, ls0, 2);
            ls1 += __shfl_xor_sync(0xffffffffu, ls1, 1);
            ls1 += __shfl_xor_sync(0xffffffffu, ls1, 2);
            l0 += ls0; l1 += ls1;

#pragma unroll
            for (int kk = 0; kk < 4; kk++) {
#pragma unroll
                for (int dp = 0; dp < 8; dp++) {
                    uint32_t vh4[4], vl4[4];
                    ldm_x4t(vh4[0], vh4[1], vh4[2], vh4[3],
                            smem_u32(&Vh[(kk * 16 + v_r) * LDT + dp * 16 + v_c]));
                    ldm_x4t(vl4[0], vl4[1], vl4[2], vl4[3],
                            smem_u32(&Vl[(kk * 16 + v_r) * LDT + dp * 16 + v_c]));
                    mma16816(O[dp * 2],     PH[kk], &vh4[0]);
                    mma16816(O[dp * 2],     PL[kk], &vh4[0]);
                    mma16816(O[dp * 2],     PH[kk], &vl4[0]);
                    mma16816(O[dp * 2 + 1], PH[kk], &vh4[2]);
                    mma16816(O[dp * 2 + 1], PL[kk], &vh4[2]);
                    mma16816(O[dp * 2 + 1], PH[kk], &vl4[2]);
                }
            }
        }
        __syncthreads();
    }

    // epilogue: write 3xBF16 A-style segments [hi | lo | hi]
    float inv0 = 1.f / l0, inv1 = 1.f / l1;
    const size_t tq0 = (size_t)(b * SS + qrow_base + warp * 16 + er);
    const size_t tq1 = tq0 + 8;
    __nv_bfloat16* r0 = g_a3 + tq0 * KP3 + hoff;
    __nv_bfloat16* r1 = g_a3 + tq1 * KP3 + hoff;
#pragma unroll
    for (int ni = 0; ni < 16; ni++) {
        int d = ni * 8 + ec;
        float x0 = O[ni][0] * inv0, x1 = O[ni][1] * inv0;
        float y0 = O[ni][2] * inv1, y1 = O[ni][3] * inv1;
        __nv_bfloat162 xh = __floats2bfloat162_rn(x0, x1);
        __nv_bfloat162 yh = __floats2bfloat162_rn(y0, y1);
        __nv_bfloat162 xl = __floats2bfloat162_rn(x0 - __bfloat162float(xh.x),
                                                  x1 - __bfloat162float(xh.y));
        __nv_bfloat162 yl = __floats2bfloat162_rn(y0 - __bfloat162float(yh.x),
                                                  y1 - __bfloat162float(yh.y));
        *(__nv_bfloat162*)(r0 + d)            = xh;
        *(__nv_bfloat162*)(r0 + HID + d)      = xl;
        *(__nv_bfloat162*)(r0 + 2 * HID + d)  = xh;
        *(__nv_bfloat162*)(r1 + d)            = yh;
        *(__nv_bfloat162*)(r1 + HID + d)      = yl;
        *(__nv_bfloat162*)(r1 + 2 * HID + d)  = yh;
    }
}

// ---------------- launch ----------------
extern "C" void kernel_launch(void* const* d_in, const int* in_sizes, int n_in,
                              void* d_out, int out_size)
{
    const float* hidden  = (const float*)d_in[0];
    const float* cosp    = (const float*)d_in[1];
    const float* sinp    = (const float*)d_in[2];
    const float* w_qkv   = (const float*)d_in[3];
    const float* b_qkv   = (const float*)d_in[4];
    const float* w_dense = (const float*)d_in[5];
    const float* b_dense = (const float*)d_in[6];
    const int*   slots   = (const int*)d_in[9];

    float* out = (float*)d_out;
    float* kc  = out + (size_t)TT * HID;
    float* vc  = kc + (size_t)NSLOTS * NH * HD;

    float* p_qkv;
    __nv_bfloat16 *p_h3, *p_wq3, *p_wd3, *p_a3;
    cudaGetSymbolAddress((void**)&p_qkv,  g_qkv);
    cudaGetSymbolAddress((void**)&p_h3,  g_h3);
    cudaGetSymbolAddress((void**)&p_wq3, g_wq3);
    cudaGetSymbolAddress((void**)&p_wd3, g_wd3);
    cudaGetSymbolAddress((void**)&p_a3,  g_a3);

    const int ATTN_SMEM = (ATT_Q_EL + 2 * ATT_KV_EL) * (int)sizeof(__nv_bfloat16);
    const int GEMM_SMEM = NSTG * 2 * STG_BYTES;
    static int attr_set = 0;
    if (!attr_set) {
        cudaFuncSetAttribute(attn_mma,
                             cudaFuncAttributeMaxDynamicSharedMemorySize,
                             ATTN_SMEM);
        cudaFuncSetAttribute(gemm_mma,
                             cudaFuncAttributeMaxDynamicSharedMemorySize,
                             GEMM_SMEM);
        attr_set = 1;
    }

    // idx 0: fused 3xBF16 splits
    {
        size_t total = N_HID_EL + N_WQ_EL + N_WD_EL;
        fused_split<<<(unsigned)(total / 256), 256>>>(hidden, w_qkv, w_dense);
    }

    // idx 1,2: spacers so attention lands at ncu idx 5
    nop_kernel<<<1, 32>>>();
    nop_kernel<<<1, 32>>>();

    // idx 3: QKV GEMM
    {
        dim3 grid(QKV_N / 128, TT / 128);
        gemm_mma<<<grid, 128, GEMM_SMEM>>>(p_h3, p_wq3, b_qkv, p_qkv, QKV_N);
    }

    // idx 4: RoPE + planes + cache scatter + zero of unused slots
    rope_zero<<<ROPE_BLKS + ZERO_BLKS, 256>>>(cosp, sinp, slots, kc, vc);

    // idx 5: flash attention v7 (profiled)
    {
        dim3 grid(SS / 128, NH, BB);
        attn_mma<<<grid, 256, ATTN_SMEM>>>();
    }

    // idx 6: dense projection
    {
        dim3 grid(HID / 128, TT / 128);
        gemm_mma<<<grid, 128, GEMM_SMEM>>>(p_a3, p_wd3, b_dense, out, HID);
    }
}

// round 16
// speedup vs baseline: 7.8431x; 1.0001x over previous
#include <cuda_runtime.h>
#include <cuda_bf16.h>
#include <stdint.h>
#include <math.h>

// ---------------- fixed problem shape ----------------
#define TT      4096
#define HID     2048
#define NH      16
#define HD      128
#define ROTD    32
#define HROT    16
#define NSLOTS  16384
#define BB      2
#define SS      2048
#define QKV_N   (3*HID)
#define KP3     (3*HID)
#define BK2     64
#define NIT2    (KP3/BK2)
#define NSTG    3
#define STG_EL  (128*64)
#define STG_BYTES (STG_EL*2)
#define QSCALE  0.08838834764831845f

// ---------------- device scratch ----------------
__device__ __nv_bfloat16 g_h3 [(size_t)TT * KP3];
__device__ __nv_bfloat16 g_wq3[(size_t)QKV_N * KP3];
__device__ __nv_bfloat16 g_wd3[(size_t)HID * KP3];
__device__ __nv_bfloat16 g_a3 [(size_t)TT * KP3];
__device__ __nv_bfloat16 g_qh[(size_t)TT * HID];
__device__ __nv_bfloat16 g_ql[(size_t)TT * HID];
__device__ __nv_bfloat16 g_kh[(size_t)TT * HID];
__device__ __nv_bfloat16 g_kl[(size_t)TT * HID];
__device__ __nv_bfloat16 g_vh[(size_t)TT * HID];
__device__ __nv_bfloat16 g_vl[(size_t)TT * HID];

// ---------------- helpers ----------------
__device__ __forceinline__ uint32_t smem_u32(const void* p) {
    uint32_t a;
    asm("{ .reg .u64 t; cvta.to.shared.u64 t, %1; cvt.u32.u64 %0, t; }"
        : "=r"(a) : "l"(p));
    return a;
}
__device__ __forceinline__ void ldm_x4(uint32_t& r0, uint32_t& r1,
                                       uint32_t& r2, uint32_t& r3, uint32_t a) {
    asm volatile("ldmatrix.sync.aligned.m8n8.x4.shared.b16 {%0,%1,%2,%3}, [%4];"
                 : "=r"(r0), "=r"(r1), "=r"(r2), "=r"(r3) : "r"(a));
}
__device__ __forceinline__ void ldm_x4t(uint32_t& r0, uint32_t& r1,
                                        uint32_t& r2, uint32_t& r3, uint32_t a) {
    asm volatile("ldmatrix.sync.aligned.m8n8.x4.trans.shared.b16 {%0,%1,%2,%3}, [%4];"
                 : "=r"(r0), "=r"(r1), "=r"(r2), "=r"(r3) : "r"(a));
}
__device__ __forceinline__ void mma16816(float* c, const uint32_t* a,
                                         const uint32_t* b) {
    asm volatile(
        "mma.sync.aligned.m16n8k16.row.col.f32.bf16.bf16.f32 "
        "{%0,%1,%2,%3}, {%4,%5,%6,%7}, {%8,%9}, {%0,%1,%2,%3};"
        : "+f"(c[0]), "+f"(c[1]), "+f"(c[2]), "+f"(c[3])
        : "r"(a[0]), "r"(a[1]), "r"(a[2]), "r"(a[3]), "r"(b[0]), "r"(b[1]));
}
__device__ __forceinline__ uint32_t pack_bf16x2(float lo, float hi) {
    __nv_bfloat162 t = __floats2bfloat162_rn(lo, hi);
    return *reinterpret_cast<uint32_t*>(&t);
}

// ---------------- fused 3xBF16 split ----------------
#define N_HID_EL   ((size_t)TT * HID)
#define N_WQ_EL    ((size_t)QKV_N * HID)
#define N_WD_EL    ((size_t)HID * HID)
__global__ __launch_bounds__(256)
void fused_split(const float* __restrict__ hidden,
                 const float* __restrict__ w_qkv,
                 const float* __restrict__ w_dense)
{
    size_t i = (size_t)blockIdx.x * 256 + threadIdx.x;
    const float* in;
    __nv_bfloat16* out;
    int a_style;
    if (i < N_HID_EL) {
        in = hidden; out = g_h3; a_style = 1;
    } else if (i < N_HID_EL + N_WQ_EL) {
        i -= N_HID_EL;
        in = w_qkv; out = g_wq3; a_style = 0;
    } else {
        i -= N_HID_EL + N_WQ_EL;
        in = w_dense; out = g_wd3; a_style = 0;
    }
    size_t row = i >> 11;
    size_t k   = i & (HID - 1);
    float a = in[i];
    __nv_bfloat16 hi = __float2bfloat16(a);
    __nv_bfloat16 lo = __float2bfloat16(a - __bfloat162float(hi));
    __nv_bfloat16* o = out + row * KP3;
    if (a_style) {
        o[k] = hi; o[HID + k] = lo; o[2 * HID + k] = hi;
    } else {
        o[k] = hi; o[HID + k] = hi; o[2 * HID + k] = lo;
    }
}

// ---------------- zero unused cache slots [TT, NSLOTS) ----------------
#define ZERO_F4    (((size_t)(NSLOTS - TT) * NH * HD) / 4)
#define ZERO_BLKS  ((int)(ZERO_F4 / 256))
__global__ __launch_bounds__(256)
void zero_cache(float* __restrict__ kc, float* __restrict__ vc)
{
    size_t zi = (size_t)blockIdx.x * 256 + threadIdx.x;
    size_t off = (size_t)TT * NH * HD + zi * 4;
    float4 z = make_float4(0.f, 0.f, 0.f, 0.f);
    *(float4*)(kc + off) = z;
    *(float4*)(vc + off) = z;
}

// ---------------- spacer ----------------
__global__ void nop_kernel() {}

// ============ shared GEMM mainloop (macro) =============
#define GEMM_MAINLOOP(A3, B3)                                                  \
    extern __shared__ __nv_bfloat16 sg[];                                      \
    __nv_bfloat16* As = sg;                                                    \
    __nv_bfloat16* Bs = sg + NSTG * STG_EL;                                    \
    const int tid  = threadIdx.x;                                              \
    const int warp = tid >> 5;                                                 \
    const int lane = tid & 31;                                                 \
    const int wm = warp & 1;                                                   \
    const int wn = warp >> 1;                                                  \
    const int m0 = blockIdx.y * 128;                                           \
    const int n0 = blockIdx.x * 128;                                           \
    float acc[32][4];                                                          \
    _Pragma("unroll")                                                          \
    for (int i = 0; i < 32; i++)                                               \
        _Pragma("unroll")                                                      \
        for (int j = 0; j < 4; j++) acc[i][j] = 0.f;                           \
    PREF(A3, B3, 0, 0);                                                        \
    PREF(A3, B3, 1, 1);                                                        \
    const int a_r  = lane & 15;                                                \
    const int acb  = lane >> 4;                                                \
    const int b_r  = (lane & 7) + ((lane >> 4) & 1) * 8;                       \
    const int bcb  = (lane >> 3) & 1;                                          \
    const int r7   = lane & 7;                                                 \
    const uint32_t aRow = smem_u32(As) + (uint32_t)(wm * 64 + a_r) * 128;      \
    const uint32_t bRow = smem_u32(Bs) + (uint32_t)(wn * 64 + b_r) * 128;      \
    uint32_t a[2][4][4], b[2][4][4];                                           \
    for (int kt = 0; kt < NIT2; kt++) {                                        \
        const int buf = kt % NSTG;                                             \
        if (kt == NIT2 - 1)                                                    \
            asm volatile("cp.async.wait_group 0;" ::: "memory");               \
        else                                                                   \
            asm volatile("cp.async.wait_group 1;" ::: "memory");               \
        __syncthreads();                                                       \
        if (kt + 2 < NIT2)                                                     \
            PREF(A3, B3, (kt + 2) % NSTG, kt + 2);                             \
        const uint32_t aS = aRow + (uint32_t)buf * STG_BYTES;                  \
        const uint32_t bS = bRow + (uint32_t)buf * STG_BYTES;                  \
        LOAD_FRAGS(0, aS, bS, 0);                                              \
        _Pragma("unroll")                                                      \
        for (int s = 0; s < 4; s++) {                                          \
            const int cur = s & 1;                                             \
            if (s < 3)                                                         \
                LOAD_FRAGS(cur ^ 1, aS, bS, s + 1);                            \
            _Pragma("unroll")                                                  \
            for (int mi = 0; mi < 4; mi++)                                     \
                _Pragma("unroll")                                              \
                for (int ni = 0; ni < 8; ni++) {                               \
                    const uint32_t* bf = &b[cur][ni >> 1][(ni & 1) * 2];       \
                    mma16816(acc[mi * 8 + ni], a[cur][mi], bf);                \
                }                                                              \
        }                                                                      \
    }

#define PREF(A3, B3, stage, kt) do {                                           \
    const __nv_bfloat16* _ab = (A3) + (size_t)m0 * KP3 + (size_t)(kt) * BK2;   \
    const __nv_bfloat16* _bb = (B3) + (size_t)n0 * KP3 + (size_t)(kt) * BK2;   \
    _Pragma("unroll")                                                          \
    for (int _i = 0; _i < 8; _i++) {                                           \
        int _c   = tid + _i * 128;                                             \
        int _row = _c >> 3;                                                    \
        int _ch  = _c & 7;                                                     \
        int _sw  = _ch ^ (_row & 7);                                           \
        uint32_t _so = (uint32_t)((stage) * STG_EL + _row * 64 + _sw * 8);     \
        asm volatile("cp.async.cg.shared.global [%0], [%1], 16;"               \
            :: "r"(smem_u32(As + _so)),                                        \
               "l"(_ab + (size_t)_row * KP3 + _ch * 8) : "memory");            \
        asm volatile("cp.async.cg.shared.global [%0], [%1], 16;"               \
            :: "r"(smem_u32(Bs + _so)),                                        \
               "l"(_bb + (size_t)_row * KP3 + _ch * 8) : "memory");            \
    }                                                                          \
    asm volatile("cp.async.commit_group;" ::: "memory");                       \
} while (0)

#define LOAD_FRAGS(bufi, aS, bS, s) do {                                       \
    const uint32_t _aOff = (uint32_t)(((2 * (s) + acb) ^ r7) * 16);            \
    const uint32_t _bOff = (uint32_t)(((2 * (s) + bcb) ^ r7) * 16);            \
    _Pragma("unroll")                                                          \
    for (int _mi = 0; _mi < 4; _mi++)                                          \
        ldm_x4(a[bufi][_mi][0], a[bufi][_mi][1],                               \
               a[bufi][_mi][2], a[bufi][_mi][3],                               \
               (aS) + (uint32_t)(_mi * 16) * 128 + _aOff);                     \
    _Pragma("unroll")                                                          \
    for (int _p = 0; _p < 4; _p++)                                             \
        ldm_x4(b[bufi][_p][0], b[bufi][_p][1],                                 \
               b[bufi][_p][2], b[bufi][_p][3],                                 \
               (bS) + (uint32_t)(_p * 16) * 128 + _bOff);                      \
} while (0)

// ---------------- dense GEMM (standard epilogue, frozen) --------------------
__global__ __launch_bounds__(128, 2)
void gemm_mma(const __nv_bfloat16* __restrict__ A3,
              const __nv_bfloat16* __restrict__ B3,
              const float* __restrict__ bias,
              float* __restrict__ C, int Nstride)
{
    GEMM_MAINLOOP(A3, B3)

    const int er = lane >> 2;
    const int ec = (lane & 3) * 2;
#pragma unroll
    for (int mi = 0; mi < 4; mi++) {
        int gm = m0 + wm * 64 + mi * 16 + er;
#pragma unroll
        for (int ni = 0; ni < 8; ni++) {
            int gn = n0 + wn * 64 + ni * 8 + ec;
            float* c = acc[mi * 8 + ni];
            float2 w0, w1;
            w0.x = c[0] + bias[gn];
            w0.y = c[1] + bias[gn + 1];
            w1.x = c[2] + bias[gn];
            w1.y = c[3] + bias[gn + 1];
            *(float2*)(C + (size_t)gm * Nstride + gn) = w0;
            *(float2*)(C + (size_t)(gm + 8) * Nstride + gn) = w1;
        }
    }
}

// ---------------- QKV GEMM with fused bias+RoPE+split+cache epilogue -------
// N tile (128) == one (matrix, head): mat = n0>>11, h = (n0&2047)>>7.
// RoPE partner col d+16 is fragment ni+2 of the SAME thread.
__global__ __launch_bounds__(128, 2)
void gemm_qkv(const __nv_bfloat16* __restrict__ A3,
              const __nv_bfloat16* __restrict__ B3,
              const float* __restrict__ bias,
              const float* __restrict__ cosp,
              const float* __restrict__ sinp,
              const int*   __restrict__ slots,
              float* __restrict__ kc_out,
              float* __restrict__ vc_out)
{
    GEMM_MAINLOOP(A3, B3)

    const int er = lane >> 2;
    const int ec = (lane & 3) * 2;
    const int mat = n0 >> 11;            // 0=q, 1=k, 2=v
    const int h   = (n0 & 2047) >> 7;
    const size_t hbase = (size_t)h * HD;

#pragma unroll
    for (int mi = 0; mi < 4; mi++) {
        const int r0 = m0 + wm * 64 + mi * 16 + er;
        const int r1 = r0 + 8;

        // biased values: v0/v1 = row r0 cols (d, d+1); v2/v3 = row r1
        float v0[8], v1[8], v2[8], v3[8];
#pragma unroll
        for (int ni = 0; ni < 8; ni++) {
            int gn = n0 + wn * 64 + ni * 8 + ec;
            float b0 = bias[gn], b1 = bias[gn + 1];
            float* c = acc[mi * 8 + ni];
            v0[ni] = c[0] + b0; v1[ni] = c[1] + b1;
            v2[ni] = c[2] + b0; v3[ni] = c[3] + b1;
        }

        // RoPE for q/k on cols 0..31 (wn==0, ni 0..1 paired with ni+2)
        if (mat < 2 && wn == 0) {
#pragma unroll
            for (int ni = 0; ni < 2; ni++) {
                int d = ni * 8 + ec;     // < 16
                float c0a = cosp[r0 * HROT + d], c0b = cosp[r0 * HROT + d + 1];
                float s0a = sinp[r0 * HROT + d], s0b = sinp[r0 * HROT + d + 1];
                float c1a = cosp[r1 * HROT + d], c1b = cosp[r1 * HROT + d + 1];
                float s1a = sinp[r1 * HROT + d], s1b = sinp[r1 * HROT + d + 1];

                float x0 = v0[ni], x1 = v1[ni];
                float y0 = v0[ni + 2], y1 = v1[ni + 2];
                v0[ni]     = x0 * c0a - y0 * s0a;
                v1[ni]     = x1 * c0b - y1 * s0b;
                v0[ni + 2] = y0 * c0a + x0 * s0a;
                v1[ni + 2] = y1 * c0b + x1 * s0b;

                x0 = v2[ni]; x1 = v3[ni];
                y0 = v2[ni + 2]; y1 = v3[ni + 2];
                v2[ni]     = x0 * c1a - y0 * s1a;
                v3[ni]     = x1 * c1b - y1 * s1b;
                v2[ni + 2] = y0 * c1a + x0 * s1a;
                v3[ni + 2] = y1 * c1b + x1 * s1b;
            }
        }

        const size_t i0 = (size_t)r0 * HID + hbase;
        const size_t i1 = (size_t)r1 * HID + hbase;

        if (mat == 0) {
            // q: scale, split hi/lo
#pragma unroll
            for (int ni = 0; ni < 8; ni++) {
                int d = wn * 64 + ni * 8 + ec;
                float a0 = v0[ni] * QSCALE, a1 = v1[ni] * QSCALE;
                float c0 = v2[ni] * QSCALE, c1 = v3[ni] * QSCALE;
                __nv_bfloat162 h0 = __floats2bfloat162_rn(a0, a1);
                __nv_bfloat162 h1 = __floats2bfloat162_rn(c0, c1);
                __nv_bfloat162 l0 = __floats2bfloat162_rn(a0 - __bfloat162float(h0.x),
                                                          a1 - __bfloat162float(h0.y));
                __nv_bfloat162 l1 = __floats2bfloat162_rn(c0 - __bfloat162float(h1.x),
                                                          c1 - __bfloat162float(h1.y));
                *(__nv_bfloat162*)(g_qh + i0 + d) = h0;
                *(__nv_bfloat162*)(g_ql + i0 + d) = l0;
                *(__nv_bfloat162*)(g_qh + i1 + d) = h1;
                *(__nv_bfloat162*)(g_ql + i1 + d) = l1;
            }
        } else if (mat == 1) {
            // k: split hi/lo + fp32 cache scatter
            int sl0 = slots[r0], sl1 = slots[r1];
            float* kc0 = kc_out + (size_t)sl0 * (NH * HD) + hbase;
            float* kc1 = kc_out + (size_t)sl1 * (NH * HD) + hbase;
#pragma unroll
            for (int ni = 0; ni < 8; ni++) {
                int d = wn * 64 + ni * 8 + ec;
                __nv_bfloat162 h0 = __floats2bfloat162_rn(v0[ni], v1[ni]);
                __nv_bfloat162 h1 = __floats2bfloat162_rn(v2[ni], v3[ni]);
                __nv_bfloat162 l0 = __floats2bfloat162_rn(v0[ni] - __bfloat162float(h0.x),
                                                          v1[ni] - __bfloat162float(h0.y));
                __nv_bfloat162 l1 = __floats2bfloat162_rn(v2[ni] - __bfloat162float(h1.x),
                                                          v3[ni] - __bfloat162float(h1.y));
                *(__nv_bfloat162*)(g_kh + i0 + d) = h0;
                *(__nv_bfloat162*)(g_kl + i0 + d) = l0;
                *(__nv_bfloat162*)(g_kh + i1 + d) = h1;
                *(__nv_bfloat162*)(g_kl + i1 + d) = l1;
                *(float2*)(kc0 + d) = make_float2(v0[ni], v1[ni]);
                *(float2*)(kc1 + d) = make_float2(v2[ni], v3[ni]);
            }
        } else {
            // v: split hi/lo + fp32 cache scatter
            int sl0 = slots[r0], sl1 = slots[r1];
            float* vc0 = vc_out + (size_t)sl0 * (NH * HD) + hbase;
            float* vc1 = vc_out + (size_t)sl1 * (NH * HD) + hbase;
#pragma unroll
            for (int ni = 0; ni < 8; ni++) {
                int d = wn * 64 + ni * 8 + ec;
                __nv_bfloat162 h0 = __floats2bfloat162_rn(v0[ni], v1[ni]);
                __nv_bfloat162 h1 = __floats2bfloat162_rn(v2[ni], v3[ni]);
                __nv_bfloat162 l0 = __floats2bfloat162_rn(v0[ni] - __bfloat162float(h0.x),
                                                          v1[ni] - __bfloat162float(h0.y));
                __nv_bfloat162 l1 = __floats2bfloat162_rn(v2[ni] - __bfloat162float(h1.x),
                                                          v3[ni] - __bfloat162float(h1.y));
                *(__nv_bfloat162*)(g_vh + i0 + d) = h0;
                *(__nv_bfloat162*)(g_vl + i0 + d) = l0;
                *(__nv_bfloat162*)(g_vh + i1 + d) = h1;
                *(__nv_bfloat162*)(g_vl + i1 + d) = l1;
                *(float2*)(vc0 + d) = make_float2(v0[ni], v1[ni]);
                *(float2*)(vc1 + d) = make_float2(v2[ni], v3[ni]);
            }
        }
    }
}

// ---------------- flash attention v7 (unchanged from R15) ------------------
#define LDT 136
#define KVP (64 * LDT)
#define ATT_Q_EL  (2 * 128 * LDT)
#define ATT_KV_EL (4 * KVP)

__global__ __launch_bounds__(256, 1)
void attn_mma()
{
    extern __shared__ __nv_bfloat16 sb[];
    __nv_bfloat16* Qh = sb;
    __nv_bfloat16* Ql = sb + 128 * LDT;
    __nv_bfloat16* KV = sb + ATT_Q_EL;

    const int b  = blockIdx.z;
    const int h  = blockIdx.y;
    const int qt = (int)gridDim.x - 1 - (int)blockIdx.x;
    const int tid  = threadIdx.x;
    const int warp = tid >> 5;
    const int lane = tid & 31;

    const int er = lane >> 2;
    const int ec = (lane & 3) * 2;
    const int a_r = lane & 15;
    const int a_c = (lane >> 4) * 8;
    const int b_r = (lane & 7) + ((lane >> 4) & 1) * 8;
    const int b_c = ((lane >> 3) & 1) * 8;
    const int v_r = (lane & 7) + ((lane >> 3) & 1) * 8;
    const int v_c = (lane >> 4) * 8;

    const int qrow_base = qt * 128;
    const size_t hoff = (size_t)h * HD;

    const size_t qgbase = (size_t)(b * SS + qrow_base) * HID + hoff;
#pragma unroll
    for (int it = 0; it < 8; it++) {
        int idx = tid + it * 256;
        int row = idx >> 4, c8 = idx & 15;
        size_t g = qgbase + (size_t)row * HID + c8 * 8;
        *(float4*)(Qh + row * LDT + c8 * 8) = *(const float4*)(g_qh + g);
        *(float4*)(Ql + row * LDT + c8 * 8) = *(const float4*)(g_ql + g);
    }

#define APREF(bufi, kt) do {                                                   \
    const size_t _kb = (size_t)(b * SS + (kt) * 64) * HID + hoff;              \
    __nv_bfloat16* _dst = KV + (bufi) * ATT_KV_EL;                             \
    _Pragma("unroll")                                                          \
    for (int _i = 0; _i < 4; _i++) {                                           \
        int _c   = tid + _i * 256;                                             \
        int _row = _c >> 4;                                                    \
        int _c8  = (_c & 15) * 8;                                              \
        size_t _g = _kb + (size_t)_row * HID + _c8;                            \
        uint32_t _so = (uint32_t)(_row * LDT + _c8);                           \
        asm volatile("cp.async.cg.shared.global [%0], [%1], 16;"               \
            :: "r"(smem_u32(_dst + 0 * KVP + _so)), "l"(g_kh + _g) : "memory");\
        asm volatile("cp.async.cg.shared.global [%0], [%1], 16;"               \
            :: "r"(smem_u32(_dst + 1 * KVP + _so)), "l"(g_kl + _g) : "memory");\
        asm volatile("cp.async.cg.shared.global [%0], [%1], 16;"               \
            :: "r"(smem_u32(_dst + 2 * KVP + _so)), "l"(g_vh + _g) : "memory");\
        asm volatile("cp.async.cg.shared.global [%0], [%1], 16;"               \
            :: "r"(smem_u32(_dst + 3 * KVP + _so)), "l"(g_vl + _g) : "memory");\
    }                                                                          \
    asm volatile("cp.async.commit_group;" ::: "memory");                       \
} while (0)

    float O[16][4];
#pragma unroll
    for (int i = 0; i < 16; i++)
#pragma unroll
        for (int j = 0; j < 4; j++) O[i][j] = 0.f;
    float m0 = -1e30f, m1 = -1e30f, l0 = 0.f, l1 = 0.f;

    const int ntiles = 2 * qt + 2;
    APREF(0, 0);

    for (int kt = 0; kt < ntiles; kt++) {
        const int bufi = kt & 1;
        if (kt + 1 < ntiles) {
            APREF(bufi ^ 1, kt + 1);
            asm volatile("cp.async.wait_group 1;" ::: "memory");
        } else {
            asm volatile("cp.async.wait_group 0;" ::: "memory");
        }
        __syncthreads();

        const bool skip = (kt * 64 > qrow_base + warp * 16 + 15);
        if (!skip) {
            const __nv_bfloat16* Kh = KV + bufi * ATT_KV_EL;
            const __nv_bfloat16* Kl = Kh + KVP;
            const __nv_bfloat16* Vh = Kh + 2 * KVP;
            const __nv_bfloat16* Vl = Kh + 3 * KVP;

            float S[8][4];
#pragma unroll
            for (int i = 0; i < 8; i++)
#pragma unroll
                for (int j = 0; j < 4; j++) S[i][j] = 0.f;

#pragma unroll
            for (int ks = 0; ks < 8; ks++) {
                uint32_t qh4[4], ql4[4];
                ldm_x4(qh4[0], qh4[1], qh4[2], qh4[3],
                       smem_u32(&Qh[(warp * 16 + a_r) * LDT + ks * 16 + a_c]));
                ldm_x4(ql4[0], ql4[1], ql4[2], ql4[3],
                       smem_u32(&Ql[(warp * 16 + a_r) * LDT + ks * 16 + a_c]));
                uint32_t kh4[4][4], kl4[4][4];
#pragma unroll
                for (int p = 0; p < 4; p++) {
                    ldm_x4(kh4[p][0], kh4[p][1], kh4[p][2], kh4[p][3],
                           smem_u32(&Kh[(p * 16 + b_r) * LDT + ks * 16 + b_c]));
                    ldm_x4(kl4[p][0], kl4[p][1], kl4[p][2], kl4[p][3],
                           smem_u32(&Kl[(p * 16 + b_r) * LDT + ks * 16 + b_c]));
                }
#pragma unroll
                for (int ni = 0; ni < 8; ni++) {
                    const uint32_t* bh = &kh4[ni >> 1][(ni & 1) * 2];
                    const uint32_t* bl = &kl4[ni >> 1][(ni & 1) * 2];
                    mma16816(S[ni], qh4, bh);
                    mma16816(S[ni], ql4, bh);
                    mma16816(S[ni], qh4, bl);
                }
            }

            if (kt >= 2 * qt) {
                const int q0 = qrow_base + warp * 16 + er;
                const int q1 = q0 + 8;
                const int kbase = kt * 64;
#pragma unroll
                for (int ni = 0; ni < 8; ni++) {
                    int key = kbase + ni * 8 + ec;
                    if (key     > q0) S[ni][0] = -1e30f;
                    if (key + 1 > q0) S[ni][1] = -1e30f;
                    if (key     > q1) S[ni][2] = -1e30f;
                    if (key + 1 > q1) S[ni][3] = -1e30f;
                }
            }

            float rx0 = -1e30f, rx1 = -1e30f;
#pragma unroll
            for (int ni = 0; ni < 8; ni++) {
                rx0 = fmaxf(rx0, fmaxf(S[ni][0], S[ni][1]));
                rx1 = fmaxf(rx1, fmaxf(S[ni][2], S[ni][3]));
            }
            rx0 = fmaxf(rx0, __shfl_xor_sync(0xffffffffu, rx0, 1));
            rx0 = fmaxf(rx0, __shfl_xor_sync(0xffffffffu, rx0, 2));
            rx1 = fmaxf(rx1, __shfl_xor_sync(0xffffffffu, rx1, 1));
            rx1 = fmaxf(rx1, __shfl_xor_sync(0xffffffffu, rx1, 2));

            float mn0 = fmaxf(m0, rx0), mn1 = fmaxf(m1, rx1);
            bool changed = (mn0 != m0) || (mn1 != m1);
            if (__any_sync(0xffffffffu, changed)) {
                float c0 = __expf(m0 - mn0), c1 = __expf(m1 - mn1);
                l0 *= c0; l1 *= c1;
#pragma unroll
                for (int ni = 0; ni < 16; ni++) {
                    O[ni][0] *= c0; O[ni][1] *= c0;
                    O[ni][2] *= c1; O[ni][3] *= c1;
                }
            }
            m0 = mn0; m1 = mn1;

            uint32_t PH[4][4], PL[4][4];
            float ls0 = 0.f, ls1 = 0.f;
#pragma unroll
            for (int ni = 0; ni < 8; ni++) {
                float p00 = __expf(S[ni][0] - mn0);
                float p01 = __expf(S[ni][1] - mn0);
                float p10 = __expf(S[ni][2] - mn1);
                float p11 = __expf(S[ni][3] - mn1);
                ls0 += p00 + p01;
                ls1 += p10 + p11;

                int kk = ni >> 1, base = (ni & 1) * 2;
                uint32_t ph0 = pack_bf16x2(p00, p01);
                uint32_t ph1 = pack_bf16x2(p10, p11);
                PH[kk][base + 0] = ph0;
                PH[kk][base + 1] = ph1;
                float h00f = __uint_as_float(ph0 << 16);
                float h01f = __uint_as_float(ph0 & 0xffff0000u);
                float h10f = __uint_as_float(ph1 << 16);
                float h11f = __uint_as_float(ph1 & 0xffff0000u);
                PL[kk][base + 0] = pack_bf16x2(p00 - h00f, p01 - h01f);
                PL[kk][base + 1] = pack_bf16x2(p10 - h10f, p11 - h11f);
            }
            ls0 += __shfl_xor_sync(0xffffffffu, ls0, 1);
            ls0 += __shfl_xor_sync(0xffffffffu, ls0, 2);
            ls1 += __shfl_xor_sync(0xffffffffu, ls1, 1);
            ls1 += __shfl_xor_sync(0xffffffffu, ls1, 2);
            l0 += ls0; l1 += ls1;

#pragma unroll
            for (int kk = 0; kk < 4; kk++) {
#pragma unroll
                for (int dp = 0; dp < 8; dp++) {
                    uint32_t vh4[4], vl4[4];
                    ldm_x4t(vh4[0], vh4[1], vh4[2], vh4[3],
                            smem_u32(&Vh[(kk * 16 + v_r) * LDT + dp * 16 + v_c]));
                    ldm_x4t(vl4[0], vl4[1], vl4[2], vl4[3],
                            smem_u32(&Vl[(kk * 16 + v_r) * LDT + dp * 16 + v_c]));
                    mma16816(O[dp * 2],     PH[kk], &vh4[0]);
                    mma16816(O[dp * 2],     PL[kk], &vh4[0]);
                    mma16816(O[dp * 2],     PH[kk], &vl4[0]);
                    mma16816(O[dp * 2 + 1], PH[kk], &vh4[2]);
                    mma16816(O[dp * 2 + 1], PL[kk], &vh4[2]);
                    mma16816(O[dp * 2 + 1], PH[kk], &vl4[2]);
                }
            }
        }
        __syncthreads();
    }

    float inv0 = 1.f / l0, inv1 = 1.f / l1;
    const size_t tq0 = (size_t)(b * SS + qrow_base + warp * 16 + er);
    const size_t tq1 = tq0 + 8;
    __nv_bfloat16* r0 = g_a3 + tq0 * KP3 + hoff;
    __nv_bfloat16* r1 = g_a3 + tq1 * KP3 + hoff;
#pragma unroll
    for (int ni = 0; ni < 16; ni++) {
        int d = ni * 8 + ec;
        float x0 = O[ni][0] * inv0, x1 = O[ni][1] * inv0;
        float y0 = O[ni][2] * inv1, y1 = O[ni][3] * inv1;
        __nv_bfloat162 xh = __floats2bfloat162_rn(x0, x1);
        __nv_bfloat162 yh = __floats2bfloat162_rn(y0, y1);
        __nv_bfloat162 xl = __floats2bfloat162_rn(x0 - __bfloat162float(xh.x),
                                                  x1 - __bfloat162float(xh.y));
        __nv_bfloat162 yl = __floats2bfloat162_rn(y0 - __bfloat162float(yh.x),
                                                  y1 - __bfloat162float(yh.y));
        *(__nv_bfloat162*)(r0 + d)            = xh;
        *(__nv_bfloat162*)(r0 + HID + d)      = xl;
        *(__nv_bfloat162*)(r0 + 2 * HID + d)  = xh;
        *(__nv_bfloat162*)(r1 + d)            = yh;
        *(__nv_bfloat162*)(r1 + HID + d)      = yl;
        *(__nv_bfloat162*)(r1 + 2 * HID + d)  = yh;
    }
}

// ---------------- launch ----------------
extern "C" void kernel_launch(void* const* d_in, const int* in_sizes, int n_in,
                              void* d_out, int out_size)
{
    const float* hidden  = (const float*)d_in[0];
    const float* cosp    = (const float*)d_in[1];
    const float* sinp    = (const float*)d_in[2];
    const float* w_qkv   = (const float*)d_in[3];
    const float* b_qkv   = (const float*)d_in[4];
    const float* w_dense = (const float*)d_in[5];
    const float* b_dense = (const float*)d_in[6];
    const int*   slots   = (const int*)d_in[9];

    float* out = (float*)d_out;
    float* kc  = out + (size_t)TT * HID;
    float* vc  = kc + (size_t)NSLOTS * NH * HD;

    __nv_bfloat16 *p_h3, *p_wq3, *p_wd3, *p_a3;
    cudaGetSymbolAddress((void**)&p_h3,  g_h3);
    cudaGetSymbolAddress((void**)&p_wq3, g_wq3);
    cudaGetSymbolAddress((void**)&p_wd3, g_wd3);
    cudaGetSymbolAddress((void**)&p_a3,  g_a3);

    const int ATTN_SMEM = (ATT_Q_EL + 2 * ATT_KV_EL) * (int)sizeof(__nv_bfloat16);
    const int GEMM_SMEM = NSTG * 2 * STG_BYTES;
    static int attr_set = 0;
    if (!attr_set) {
        cudaFuncSetAttribute(attn_mma,
                             cudaFuncAttributeMaxDynamicSharedMemorySize,
                             ATTN_SMEM);
        cudaFuncSetAttribute(gemm_mma,
                             cudaFuncAttributeMaxDynamicSharedMemorySize,
                             GEMM_SMEM);
        cudaFuncSetAttribute(gemm_qkv,
                             cudaFuncAttributeMaxDynamicSharedMemorySize,
                             GEMM_SMEM);
        attr_set = 1;
    }

    // idx 0: fused 3xBF16 splits
    {
        size_t total = N_HID_EL + N_WQ_EL + N_WD_EL;
        fused_split<<<(unsigned)(total / 256), 256>>>(hidden, w_qkv, w_dense);
    }

    // idx 1: zero unused cache slots
    zero_cache<<<ZERO_BLKS, 256>>>(kc, vc);

    // idx 2,3,4: spacers so the QKV GEMM lands at ncu idx 5
    nop_kernel<<<1, 32>>>();
    nop_kernel<<<1, 32>>>();
    nop_kernel<<<1, 32>>>();

    // idx 5: QKV GEMM with fused bias+RoPE+split+cache epilogue (profiled)
    {
        dim3 grid(QKV_N / 128, TT / 128);
        gemm_qkv<<<grid, 128, GEMM_SMEM>>>(p_h3, p_wq3, b_qkv,
                                           cosp, sinp, slots, kc, vc);
    }

    // idx 6: flash attention
    {
        dim3 grid(SS / 128, NH, BB);
        attn_mma<<<grid, 256, ATTN_SMEM>>>();
    }

    // idx 7: dense projection
    {
        dim3 grid(HID / 128, TT / 128);
        gemm_mma<<<grid, 128, GEMM_SMEM>>>(p_a3, p_wd3, b_dense, out, HID);
    }
}

// round 17
// speedup vs baseline: 8.0992x; 1.0327x over previous
#include <cuda_runtime.h>
#include <cuda_bf16.h>
#include <stdint.h>
#include <math.h>

// ---------------- fixed problem shape ----------------
#define TT      4096
#define HID     2048
#define NH      16
#define HD      128
#define ROTD    32
#define HROT    16
#define NSLOTS  16384
#define BB      2
#define SS      2048
#define QKV_N   (3*HID)
#define KP3     (3*HID)
#define BK2     64
#define NIT2    (KP3/BK2)
#define NSTG    3
#define STG_EL  (128*64)
#define STG_BYTES (STG_EL*2)
#define QSCALE  0.08838834764831845f

// ---------------- device scratch ----------------
__device__ __nv_bfloat16 g_h3 [(size_t)TT * KP3];
__device__ __nv_bfloat16 g_wq3[(size_t)QKV_N * KP3];
__device__ __nv_bfloat16 g_wd3[(size_t)HID * KP3];
__device__ __nv_bfloat16 g_a3 [(size_t)TT * KP3];
__device__ __nv_bfloat16 g_qh[(size_t)TT * HID];
__device__ __nv_bfloat16 g_ql[(size_t)TT * HID];
__device__ __nv_bfloat16 g_kh[(size_t)TT * HID];
__device__ __nv_bfloat16 g_kl[(size_t)TT * HID];
__device__ __nv_bfloat16 g_vh[(size_t)TT * HID];
__device__ __nv_bfloat16 g_vl[(size_t)TT * HID];

// ---------------- helpers ----------------
__device__ __forceinline__ uint32_t smem_u32(const void* p) {
    uint32_t a;
    asm("{ .reg .u64 t; cvta.to.shared.u64 t, %1; cvt.u32.u64 %0, t; }"
        : "=r"(a) : "l"(p));
    return a;
}
__device__ __forceinline__ void ldm_x4(uint32_t& r0, uint32_t& r1,
                                       uint32_t& r2, uint32_t& r3, uint32_t a) {
    asm volatile("ldmatrix.sync.aligned.m8n8.x4.shared.b16 {%0,%1,%2,%3}, [%4];"
                 : "=r"(r0), "=r"(r1), "=r"(r2), "=r"(r3) : "r"(a));
}
__device__ __forceinline__ void ldm_x4t(uint32_t& r0, uint32_t& r1,
                                        uint32_t& r2, uint32_t& r3, uint32_t a) {
    asm volatile("ldmatrix.sync.aligned.m8n8.x4.trans.shared.b16 {%0,%1,%2,%3}, [%4];"
                 : "=r"(r0), "=r"(r1), "=r"(r2), "=r"(r3) : "r"(a));
}
__device__ __forceinline__ void mma16816(float* c, const uint32_t* a,
                                         const uint32_t* b) {
    asm volatile(
        "mma.sync.aligned.m16n8k16.row.col.f32.bf16.bf16.f32 "
        "{%0,%1,%2,%3}, {%4,%5,%6,%7}, {%8,%9}, {%0,%1,%2,%3};"
        : "+f"(c[0]), "+f"(c[1]), "+f"(c[2]), "+f"(c[3])
        : "r"(a[0]), "r"(a[1]), "r"(a[2]), "r"(a[3]), "r"(b[0]), "r"(b[1]));
}
__device__ __forceinline__ uint32_t pack_bf16x2(float lo, float hi) {
    __nv_bfloat162 t = __floats2bfloat162_rn(lo, hi);
    return *reinterpret_cast<uint32_t*>(&t);
}

// ---------------- fused split (x4 vectorized) + cache zero tail ------------
#define N_HID_EL   ((size_t)TT * HID)
#define N_WQ_EL    ((size_t)QKV_N * HID)
#define N_WD_EL    ((size_t)HID * HID)
#define SPLIT_V4   ((N_HID_EL + N_WQ_EL + N_WD_EL) / 4)     // 6291456
#define SPLIT_BLKS ((int)(SPLIT_V4 / 256))                  // 24576
#define ZERO_F4    (((size_t)(NSLOTS - TT) * NH * HD) / 4)  // 6291456
#define ZERO_BLKS  ((int)(ZERO_F4 / 256))                   // 24576

__global__ __launch_bounds__(256)
void fused_split_zero(const float* __restrict__ hidden,
                      const float* __restrict__ w_qkv,
                      const float* __restrict__ w_dense,
                      float* __restrict__ kc, float* __restrict__ vc)
{
    int bid = blockIdx.x;
    if (bid >= SPLIT_BLKS) {
        // zero never-written cache slots [TT, NSLOTS)
        size_t zi = (size_t)(bid - SPLIT_BLKS) * 256 + threadIdx.x;
        size_t off = (size_t)TT * NH * HD + zi * 4;
        float4 z = make_float4(0.f, 0.f, 0.f, 0.f);
        *(float4*)(kc + off) = z;
        *(float4*)(vc + off) = z;
        return;
    }

    size_t i4 = (size_t)bid * 256 + threadIdx.x;   // float4 index
    const float* in;
    __nv_bfloat16* out;
    int a_style;
    if (i4 < N_HID_EL / 4) {
        in = hidden; out = g_h3; a_style = 1;
    } else if (i4 < (N_HID_EL + N_WQ_EL) / 4) {
        i4 -= N_HID_EL / 4;
        in = w_qkv; out = g_wq3; a_style = 0;
    } else {
        i4 -= (N_HID_EL + N_WQ_EL) / 4;
        in = w_dense; out = g_wd3; a_style = 0;
    }
    size_t row = i4 >> 9;          // 512 float4 per 2048-row
    size_t k4  = i4 & 511;
    float4 v = ((const float4*)in)[i4];

    __nv_bfloat162 h0 = __floats2bfloat162_rn(v.x, v.y);
    __nv_bfloat162 h1 = __floats2bfloat162_rn(v.z, v.w);
    __nv_bfloat162 l0 = __floats2bfloat162_rn(v.x - __bfloat162float(h0.x),
                                              v.y - __bfloat162float(h0.y));
    __nv_bfloat162 l1 = __floats2bfloat162_rn(v.z - __bfloat162float(h1.x),
                                              v.w - __bfloat162float(h1.y));

    __nv_bfloat16* o = out + row * KP3 + k4 * 4;
    ((__nv_bfloat162*)o)[0] = h0;
    ((__nv_bfloat162*)o)[1] = h1;
    __nv_bfloat162* o1 = (__nv_bfloat162*)(o + HID);
    __nv_bfloat162* o2 = (__nv_bfloat162*)(o + 2 * HID);
    if (a_style) {                       // [hi | lo | hi]
        o1[0] = l0; o1[1] = l1;
        o2[0] = h0; o2[1] = h1;
    } else {                             // [hi | hi | lo]
        o1[0] = h0; o1[1] = h1;
        o2[0] = l0; o2[1] = l1;
    }
}

// ---------------- spacer ----------------
__global__ void nop_kernel() {}

// ============ shared GEMM mainloop (macro) =============
#define GEMM_MAINLOOP(A3, B3)                                                  \
    extern __shared__ __nv_bfloat16 sg[];                                      \
    __nv_bfloat16* As = sg;                                                    \
    __nv_bfloat16* Bs = sg + NSTG * STG_EL;                                    \
    const int tid  = threadIdx.x;                                              \
    const int warp = tid >> 5;                                                 \
    const int lane = tid & 31;                                                 \
    const int wm = warp & 1;                                                   \
    const int wn = warp >> 1;                                                  \
    const int m0 = blockIdx.y * 128;                                           \
    const int n0 = blockIdx.x * 128;                                           \
    float acc[32][4];                                                          \
    _Pragma("unroll")                                                          \
    for (int i = 0; i < 32; i++)                                               \
        _Pragma("unroll")                                                      \
        for (int j = 0; j < 4; j++) acc[i][j] = 0.f;                           \
    PREF(A3, B3, 0, 0);                                                        \
    PREF(A3, B3, 1, 1);                                                        \
    const int a_r  = lane & 15;                                                \
    const int acb  = lane >> 4;                                                \
    const int b_r  = (lane & 7) + ((lane >> 4) & 1) * 8;                       \
    const int bcb  = (lane >> 3) & 1;                                          \
    const int r7   = lane & 7;                                                 \
    const uint32_t aRow = smem_u32(As) + (uint32_t)(wm * 64 + a_r) * 128;      \
    const uint32_t bRow = smem_u32(Bs) + (uint32_t)(wn * 64 + b_r) * 128;      \
    uint32_t a[2][4][4], b[2][4][4];                                           \
    for (int kt = 0; kt < NIT2; kt++) {                                        \
        const int buf = kt % NSTG;                                             \
        if (kt == NIT2 - 1)                                                    \
            asm volatile("cp.async.wait_group 0;" ::: "memory");               \
        else                                                                   \
            asm volatile("cp.async.wait_group 1;" ::: "memory");               \
        __syncthreads();                                                       \
        if (kt + 2 < NIT2)                                                     \
            PREF(A3, B3, (kt + 2) % NSTG, kt + 2);                             \
        const uint32_t aS = aRow + (uint32_t)buf * STG_BYTES;                  \
        const uint32_t bS = bRow + (uint32_t)buf * STG_BYTES;                  \
        LOAD_FRAGS(0, aS, bS, 0);                                              \
        _Pragma("unroll")                                                      \
        for (int s = 0; s < 4; s++) {                                          \
            const int cur = s & 1;                                             \
            if (s < 3)                                                         \
                LOAD_FRAGS(cur ^ 1, aS, bS, s + 1);                            \
            _Pragma("unroll")                                                  \
            for (int mi = 0; mi < 4; mi++)                                     \
                _Pragma("unroll")                                              \
                for (int ni = 0; ni < 8; ni++) {                               \
                    const uint32_t* bf = &b[cur][ni >> 1][(ni & 1) * 2];       \
                    mma16816(acc[mi * 8 + ni], a[cur][mi], bf);                \
                }                                                              \
        }                                                                      \
    }

#define PREF(A3, B3, stage, kt) do {                                           \
    const __nv_bfloat16* _ab = (A3) + (size_t)m0 * KP3 + (size_t)(kt) * BK2;   \
    const __nv_bfloat16* _bb = (B3) + (size_t)n0 * KP3 + (size_t)(kt) * BK2;   \
    _Pragma("unroll")                                                          \
    for (int _i = 0; _i < 8; _i++) {                                           \
        int _c   = tid + _i * 128;                                             \
        int _row = _c >> 3;                                                    \
        int _ch  = _c & 7;                                                     \
        int _sw  = _ch ^ (_row & 7);                                           \
        uint32_t _so = (uint32_t)((stage) * STG_EL + _row * 64 + _sw * 8);     \
        asm volatile("cp.async.cg.shared.global [%0], [%1], 16;"               \
            :: "r"(smem_u32(As + _so)),                                        \
               "l"(_ab + (size_t)_row * KP3 + _ch * 8) : "memory");            \
        asm volatile("cp.async.cg.shared.global [%0], [%1], 16;"               \
            :: "r"(smem_u32(Bs + _so)),                                        \
               "l"(_bb + (size_t)_row * KP3 + _ch * 8) : "memory");            \
    }                                                                          \
    asm volatile("cp.async.commit_group;" ::: "memory");                       \
} while (0)

#define LOAD_FRAGS(bufi, aS, bS, s) do {                                       \
    const uint32_t _aOff = (uint32_t)(((2 * (s) + acb) ^ r7) * 16);            \
    const uint32_t _bOff = (uint32_t)(((2 * (s) + bcb) ^ r7) * 16);            \
    _Pragma("unroll")                                                          \
    for (int _mi = 0; _mi < 4; _mi++)                                          \
        ldm_x4(a[bufi][_mi][0], a[bufi][_mi][1],                               \
               a[bufi][_mi][2], a[bufi][_mi][3],                               \
               (aS) + (uint32_t)(_mi * 16) * 128 + _aOff);                     \
    _Pragma("unroll")                                                          \
    for (int _p = 0; _p < 4; _p++)                                             \
        ldm_x4(b[bufi][_p][0], b[bufi][_p][1],                                 \
               b[bufi][_p][2], b[bufi][_p][3],                                 \
               (bS) + (uint32_t)(_p * 16) * 128 + _bOff);                      \
} while (0)

// ---------------- dense GEMM (standard epilogue, frozen) --------------------
__global__ __launch_bounds__(128, 2)
void gemm_mma(const __nv_bfloat16* __restrict__ A3,
              const __nv_bfloat16* __restrict__ B3,
              const float* __restrict__ bias,
              float* __restrict__ C, int Nstride)
{
    GEMM_MAINLOOP(A3, B3)

    const int er = lane >> 2;
    const int ec = (lane & 3) * 2;
#pragma unroll
    for (int mi = 0; mi < 4; mi++) {
        int gm = m0 + wm * 64 + mi * 16 + er;
#pragma unroll
        for (int ni = 0; ni < 8; ni++) {
            int gn = n0 + wn * 64 + ni * 8 + ec;
            float* c = acc[mi * 8 + ni];
            float2 w0, w1;
            w0.x = c[0] + bias[gn];
            w0.y = c[1] + bias[gn + 1];
            w1.x = c[2] + bias[gn];
            w1.y = c[3] + bias[gn + 1];
            *(float2*)(C + (size_t)gm * Nstride + gn) = w0;
            *(float2*)(C + (size_t)(gm + 8) * Nstride + gn) = w1;
        }
    }
}

// ---------------- QKV GEMM with fused bias+RoPE+split+cache epilogue -------
__global__ __launch_bounds__(128, 2)
void gemm_qkv(const __nv_bfloat16* __restrict__ A3,
              const __nv_bfloat16* __restrict__ B3,
              const float* __restrict__ bias,
              const float* __restrict__ cosp,
              const float* __restrict__ sinp,
              const int*   __restrict__ slots,
              float* __restrict__ kc_out,
              float* __restrict__ vc_out)
{
    GEMM_MAINLOOP(A3, B3)

    const int er = lane >> 2;
    const int ec = (lane & 3) * 2;
    const int mat = n0 >> 11;            // 0=q, 1=k, 2=v
    const int h   = (n0 & 2047) >> 7;
    const size_t hbase = (size_t)h * HD;

#pragma unroll
    for (int mi = 0; mi < 4; mi++) {
        const int r0 = m0 + wm * 64 + mi * 16 + er;
        const int r1 = r0 + 8;

        float v0[8], v1[8], v2[8], v3[8];
#pragma unroll
        for (int ni = 0; ni < 8; ni++) {
            int gn = n0 + wn * 64 + ni * 8 + ec;
            float b0 = bias[gn], b1 = bias[gn + 1];
            float* c = acc[mi * 8 + ni];
            v0[ni] = c[0] + b0; v1[ni] = c[1] + b1;
            v2[ni] = c[2] + b0; v3[ni] = c[3] + b1;
        }

        if (mat < 2 && wn == 0) {
#pragma unroll
            for (int ni = 0; ni < 2; ni++) {
                int d = ni * 8 + ec;
                float c0a = cosp[r0 * HROT + d], c0b = cosp[r0 * HROT + d + 1];
                float s0a = sinp[r0 * HROT + d], s0b = sinp[r0 * HROT + d + 1];
                float c1a = cosp[r1 * HROT + d], c1b = cosp[r1 * HROT + d + 1];
                float s1a = sinp[r1 * HROT + d], s1b = sinp[r1 * HROT + d + 1];

                float x0 = v0[ni], x1 = v1[ni];
                float y0 = v0[ni + 2], y1 = v1[ni + 2];
                v0[ni]     = x0 * c0a - y0 * s0a;
                v1[ni]     = x1 * c0b - y1 * s0b;
                v0[ni + 2] = y0 * c0a + x0 * s0a;
                v1[ni + 2] = y1 * c0b + x1 * s0b;

                x0 = v2[ni]; x1 = v3[ni];
                y0 = v2[ni + 2]; y1 = v3[ni + 2];
                v2[ni]     = x0 * c1a - y0 * s1a;
                v3[ni]     = x1 * c1b - y1 * s1b;
                v2[ni + 2] = y0 * c1a + x0 * s1a;
                v3[ni + 2] = y1 * c1b + x1 * s1b;
            }
        }

        const size_t i0 = (size_t)r0 * HID + hbase;
        const size_t i1 = (size_t)r1 * HID + hbase;

        if (mat == 0) {
#pragma unroll
            for (int ni = 0; ni < 8; ni++) {
                int d = wn * 64 + ni * 8 + ec;
                float a0 = v0[ni] * QSCALE, a1 = v1[ni] * QSCALE;
                float c0 = v2[ni] * QSCALE, c1 = v3[ni] * QSCALE;
                __nv_bfloat162 h0 = __floats2bfloat162_rn(a0, a1);
                __nv_bfloat162 h1 = __floats2bfloat162_rn(c0, c1);
                __nv_bfloat162 l0 = __floats2bfloat162_rn(a0 - __bfloat162float(h0.x),
                                                          a1 - __bfloat162float(h0.y));
                __nv_bfloat162 l1 = __floats2bfloat162_rn(c0 - __bfloat162float(h1.x),
                                                          c1 - __bfloat162float(h1.y));
                *(__nv_bfloat162*)(g_qh + i0 + d) = h0;
                *(__nv_bfloat162*)(g_ql + i0 + d) = l0;
                *(__nv_bfloat162*)(g_qh + i1 + d) = h1;
                *(__nv_bfloat162*)(g_ql + i1 + d) = l1;
            }
        } else if (mat == 1) {
            int sl0 = slots[r0], sl1 = slots[r1];
            float* kc0 = kc_out + (size_t)sl0 * (NH * HD) + hbase;
            float* kc1 = kc_out + (size_t)sl1 * (NH * HD) + hbase;
#pragma unroll
            for (int ni = 0; ni < 8; ni++) {
                int d = wn * 64 + ni * 8 + ec;
                __nv_bfloat162 h0 = __floats2bfloat162_rn(v0[ni], v1[ni]);
                __nv_bfloat162 h1 = __floats2bfloat162_rn(v2[ni], v3[ni]);
                __nv_bfloat162 l0 = __floats2bfloat162_rn(v0[ni] - __bfloat162float(h0.x),
                                                          v1[ni] - __bfloat162float(h0.y));
                __nv_bfloat162 l1 = __floats2bfloat162_rn(v2[ni] - __bfloat162float(h1.x),
                                                          v3[ni] - __bfloat162float(h1.y));
                *(__nv_bfloat162*)(g_kh + i0 + d) = h0;
                *(__nv_bfloat162*)(g_kl + i0 + d) = l0;
                *(__nv_bfloat162*)(g_kh + i1 + d) = h1;
                *(__nv_bfloat162*)(g_kl + i1 + d) = l1;
                *(float2*)(kc0 + d) = make_float2(v0[ni], v1[ni]);
                *(float2*)(kc1 + d) = make_float2(v2[ni], v3[ni]);
            }
        } else {
            int sl0 = slots[r0], sl1 = slots[r1];
            float* vc0 = vc_out + (size_t)sl0 * (NH * HD) + hbase;
            float* vc1 = vc_out + (size_t)sl1 * (NH * HD) + hbase;
#pragma unroll
            for (int ni = 0; ni < 8; ni++) {
                int d = wn * 64 + ni * 8 + ec;
                __nv_bfloat162 h0 = __floats2bfloat162_rn(v0[ni], v1[ni]);
                __nv_bfloat162 h1 = __floats2bfloat162_rn(v2[ni], v3[ni]);
                __nv_bfloat162 l0 = __floats2bfloat162_rn(v0[ni] - __bfloat162float(h0.x),
                                                          v1[ni] - __bfloat162float(h0.y));
                __nv_bfloat162 l1 = __floats2bfloat162_rn(v2[ni] - __bfloat162float(h1.x),
                                                          v3[ni] - __bfloat162float(h1.y));
                *(__nv_bfloat162*)(g_vh + i0 + d) = h0;
                *(__nv_bfloat162*)(g_vl + i0 + d) = l0;
                *(__nv_bfloat162*)(g_vh + i1 + d) = h1;
                *(__nv_bfloat162*)(g_vl + i1 + d) = l1;
                *(float2*)(vc0 + d) = make_float2(v0[ni], v1[ni]);
                *(float2*)(vc1 + d) = make_float2(v2[ni], v3[ni]);
            }
        }
    }
}

// ---------------- flash attention v8: Qh fragments hoisted to registers ----
#define LDT 136
#define KVP (64 * LDT)
#define ATT_Q_EL  (2 * 128 * LDT)
#define ATT_KV_EL (4 * KVP)

__global__ __launch_bounds__(256, 1)
void attn_mma()
{
    extern __shared__ __nv_bfloat16 sb[];
    __nv_bfloat16* Qh = sb;
    __nv_bfloat16* Ql = sb + 128 * LDT;
    __nv_bfloat16* KV = sb + ATT_Q_EL;

    const int b  = blockIdx.z;
    const int h  = blockIdx.y;
    const int qt = (int)gridDim.x - 1 - (int)blockIdx.x;
    const int tid  = threadIdx.x;
    const int warp = tid >> 5;
    const int lane = tid & 31;

    const int er = lane >> 2;
    const int ec = (lane & 3) * 2;
    const int a_r = lane & 15;
    const int a_c = (lane >> 4) * 8;
    const int b_r = (lane & 7) + ((lane >> 4) & 1) * 8;
    const int b_c = ((lane >> 3) & 1) * 8;
    const int v_r = (lane & 7) + ((lane >> 3) & 1) * 8;
    const int v_c = (lane >> 4) * 8;

    const int qrow_base = qt * 128;
    const size_t hoff = (size_t)h * HD;

    const size_t qgbase = (size_t)(b * SS + qrow_base) * HID + hoff;
#pragma unroll
    for (int it = 0; it < 8; it++) {
        int idx = tid + it * 256;
        int row = idx >> 4, c8 = idx & 15;
        size_t g = qgbase + (size_t)row * HID + c8 * 8;
        *(float4*)(Qh + row * LDT + c8 * 8) = *(const float4*)(g_qh + g);
        *(float4*)(Ql + row * LDT + c8 * 8) = *(const float4*)(g_ql + g);
    }
    __syncthreads();

    // hoist loop-invariant Qh fragments into registers (32 regs)
    uint32_t qhr[8][4];
#pragma unroll
    for (int ks = 0; ks < 8; ks++)
        ldm_x4(qhr[ks][0], qhr[ks][1], qhr[ks][2], qhr[ks][3],
               smem_u32(&Qh[(warp * 16 + a_r) * LDT + ks * 16 + a_c]));

#define APREF(bufi, kt) do {                                                   \
    const size_t _kb = (size_t)(b * SS + (kt) * 64) * HID + hoff;              \
    __nv_bfloat16* _dst = KV + (bufi) * ATT_KV_EL;                             \
    _Pragma("unroll")                                                          \
    for (int _i = 0; _i < 4; _i++) {                                           \
        int _c   = tid + _i * 256;                                             \
        int _row = _c >> 4;                                                    \
        int _c8  = (_c & 15) * 8;                                              \
        size_t _g = _kb + (size_t)_row * HID + _c8;                            \
        uint32_t _so = (uint32_t)(_row * LDT + _c8);                           \
        asm volatile("cp.async.cg.shared.global [%0], [%1], 16;"               \
            :: "r"(smem_u32(_dst + 0 * KVP + _so)), "l"(g_kh + _g) : "memory");\
        asm volatile("cp.async.cg.shared.global [%0], [%1], 16;"               \
            :: "r"(smem_u32(_dst + 1 * KVP + _so)), "l"(g_kl + _g) : "memory");\
        asm volatile("cp.async.cg.shared.global [%0], [%1], 16;"               \
            :: "r"(smem_u32(_dst + 2 * KVP + _so)), "l"(g_vh + _g) : "memory");\
        asm volatile("cp.async.cg.shared.global [%0], [%1], 16;"               \
            :: "r"(smem_u32(_dst + 3 * KVP + _so)), "l"(g_vl + _g) : "memory");\
    }                                                                          \
    asm volatile("cp.async.commit_group;" ::: "memory");                       \
} while (0)

    float O[16][4];
#pragma unroll
    for (int i = 0; i < 16; i++)
#pragma unroll
        for (int j = 0; j < 4; j++) O[i][j] = 0.f;
    float m0 = -1e30f, m1 = -1e30f, l0 = 0.f, l1 = 0.f;

    const int ntiles = 2 * qt + 2;
    APREF(0, 0);

    for (int kt = 0; kt < ntiles; kt++) {
        const int bufi = kt & 1;
        if (kt + 1 < ntiles) {
            APREF(bufi ^ 1, kt + 1);
            asm volatile("cp.async.wait_group 1;" ::: "memory");
        } else {
            asm volatile("cp.async.wait_group 0;" ::: "memory");
        }
        __syncthreads();

        const bool skip = (kt * 64 > qrow_base + warp * 16 + 15);
        if (!skip) {
            const __nv_bfloat16* Kh = KV + bufi * ATT_KV_EL;
            const __nv_bfloat16* Kl = Kh + KVP;
            const __nv_bfloat16* Vh = Kh + 2 * KVP;
            const __nv_bfloat16* Vl = Kh + 3 * KVP;

            float S[8][4];
#pragma unroll
            for (int i = 0; i < 8; i++)
#pragma unroll
                for (int j = 0; j < 4; j++) S[i][j] = 0.f;

#pragma unroll
            for (int ks = 0; ks < 8; ks++) {
                uint32_t ql4[4];
                ldm_x4(ql4[0], ql4[1], ql4[2], ql4[3],
                       smem_u32(&Ql[(warp * 16 + a_r) * LDT + ks * 16 + a_c]));
                uint32_t kh4[4][4], kl4[4][4];
#pragma unroll
                for (int p = 0; p < 4; p++) {
                    ldm_x4(kh4[p][0], kh4[p][1], kh4[p][2], kh4[p][3],
                           smem_u32(&Kh[(p * 16 + b_r) * LDT + ks * 16 + b_c]));
                    ldm_x4(kl4[p][0], kl4[p][1], kl4[p][2], kl4[p][3],
                           smem_u32(&Kl[(p * 16 + b_r) * LDT + ks * 16 + b_c]));
                }
#pragma unroll
                for (int ni = 0; ni < 8; ni++) {
                    const uint32_t* bh = &kh4[ni >> 1][(ni & 1) * 2];
                    const uint32_t* bl = &kl4[ni >> 1][(ni & 1) * 2];
                    mma16816(S[ni], qhr[ks], bh);
                    mma16816(S[ni], ql4,     bh);
                    mma16816(S[ni], qhr[ks], bl);
                }
            }

            if (kt >= 2 * qt) {
                const int q0 = qrow_base + warp * 16 + er;
                const int q1 = q0 + 8;
                const int kbase = kt * 64;
#pragma unroll
                for (int ni = 0; ni < 8; ni++) {
                    int key = kbase + ni * 8 + ec;
                    if (key     > q0) S[ni][0] = -1e30f;
                    if (key + 1 > q0) S[ni][1] = -1e30f;
                    if (key     > q1) S[ni][2] = -1e30f;
                    if (key + 1 > q1) S[ni][3] = -1e30f;
                }
            }

            float rx0 = -1e30f, rx1 = -1e30f;
#pragma unroll
            for (int ni = 0; ni < 8; ni++) {
                rx0 = fmaxf(rx0, fmaxf(S[ni][0], S[ni][1]));
                rx1 = fmaxf(rx1, fmaxf(S[ni][2], S[ni][3]));
            }
            rx0 = fmaxf(rx0, __shfl_xor_sync(0xffffffffu, rx0, 1));
            rx0 = fmaxf(rx0, __shfl_xor_sync(0xffffffffu, rx0, 2));
            rx1 = fmaxf(rx1, __shfl_xor_sync(0xffffffffu, rx1, 1));
            rx1 = fmaxf(rx1, __shfl_xor_sync(0xffffffffu, rx1, 2));

            float mn0 = fmaxf(m0, rx0), mn1 = fmaxf(m1, rx1);
            bool changed = (mn0 != m0) || (mn1 != m1);
            if (__any_sync(0xffffffffu, changed)) {
                float c0 = __expf(m0 - mn0), c1 = __expf(m1 - mn1);
                l0 *= c0; l1 *= c1;
#pragma unroll
                for (int ni = 0; ni < 16; ni++) {
                    O[ni][0] *= c0; O[ni][1] *= c0;
                    O[ni][2] *= c1; O[ni][3] *= c1;
                }
            }
            m0 = mn0; m1 = mn1;

            uint32_t PH[4][4], PL[4][4];
            float ls0 = 0.f, ls1 = 0.f;
#pragma unroll
            for (int ni = 0; ni < 8; ni++) {
                float p00 = __expf(S[ni][0] - mn0);
                float p01 = __expf(S[ni][1] - mn0);
                float p10 = __expf(S[ni][2] - mn1);
                float p11 = __expf(S[ni][3] - mn1);
                ls0 += p00 + p01;
                ls1 += p10 + p11;

                int kk = ni >> 1, base = (ni & 1) * 2;
                uint32_t ph0 = pack_bf16x2(p00, p01);
                uint32_t ph1 = pack_bf16x2(p10, p11);
                PH[kk][base + 0] = ph0;
                PH[kk][base + 1] = ph1;
                float h00f = __uint_as_float(ph0 << 16);
                float h01f = __uint_as_float(ph0 & 0xffff0000u);
                float h10f = __uint_as_float(ph1 << 16);
                float h11f = __uint_as_float(ph1 & 0xffff0000u);
                PL[kk][base + 0] = pack_bf16x2(p00 - h00f, p01 - h01f);
                PL[kk][base + 1] = pack_bf16x2(p10 - h10f, p11 - h11f);
            }
            ls0 += __shfl_xor_sync(0xffffffffu, ls0, 1);
            ls0 += __shfl_xor_sync(0xffffffffu, ls0, 2);
            ls1 += __shfl_xor_sync(0xffffffffu, ls1, 1);
            ls1 += __shfl_xor_sync(0xffffffffu, ls1, 2);
            l0 += ls0; l1 += ls1;

#pragma unroll
            for (int kk = 0; kk < 4; kk++) {
#pragma unroll
                for (int dp = 0; dp < 8; dp++) {
                    uint32_t vh4[4], vl4[4];
                    ldm_x4t(vh4[0], vh4[1], vh4[2], vh4[3],
                            smem_u32(&Vh[(kk * 16 + v_r) * LDT + dp * 16 + v_c]));
                    ldm_x4t(vl4[0], vl4[1], vl4[2], vl4[3],
                            smem_u32(&Vl[(kk * 16 + v_r) * LDT + dp * 16 + v_c]));
                    mma16816(O[dp * 2],     PH[kk], &vh4[0]);
                    mma16816(O[dp * 2],     PL[kk], &vh4[0]);
                    mma16816(O[dp * 2],     PH[kk], &vl4[0]);
                    mma16816(O[dp * 2 + 1], PH[kk], &vh4[2]);
                    mma16816(O[dp * 2 + 1], PL[kk], &vh4[2]);
                    mma16816(O[dp * 2 + 1], PH[kk], &vl4[2]);
                }
            }
        }
        __syncthreads();
    }

    float inv0 = 1.f / l0, inv1 = 1.f / l1;
    const size_t tq0 = (size_t)(b * SS + qrow_base + warp * 16 + er);
    const size_t tq1 = tq0 + 8;
    __nv_bfloat16* r0 = g_a3 + tq0 * KP3 + hoff;
    __nv_bfloat16* r1 = g_a3 + tq1 * KP3 + hoff;
#pragma unroll
    for (int ni = 0; ni < 16; ni++) {
        int d = ni * 8 + ec;
        float x0 = O[ni][0] * inv0, x1 = O[ni][1] * inv0;
        float y0 = O[ni][2] * inv1, y1 = O[ni][3] * inv1;
        __nv_bfloat162 xh = __floats2bfloat162_rn(x0, x1);
        __nv_bfloat162 yh = __floats2bfloat162_rn(y0, y1);
        __nv_bfloat162 xl = __floats2bfloat162_rn(x0 - __bfloat162float(xh.x),
                                                  x1 - __bfloat162float(xh.y));
        __nv_bfloat162 yl = __floats2bfloat162_rn(y0 - __bfloat162float(yh.x),
                                                  y1 - __bfloat162float(yh.y));
        *(__nv_bfloat162*)(r0 + d)            = xh;
        *(__nv_bfloat162*)(r0 + HID + d)      = xl;
        *(__nv_bfloat162*)(r0 + 2 * HID + d)  = xh;
        *(__nv_bfloat162*)(r1 + d)            = yh;
        *(__nv_bfloat162*)(r1 + HID + d)      = yl;
        *(__nv_bfloat162*)(r1 + 2 * HID + d)  = yh;
    }
}

// ---------------- launch ----------------
extern "C" void kernel_launch(void* const* d_in, const int* in_sizes, int n_in,
                              void* d_out, int out_size)
{
    const float* hidden  = (const float*)d_in[0];
    const float* cosp    = (const float*)d_in[1];
    const float* sinp    = (const float*)d_in[2];
    const float* w_qkv   = (const float*)d_in[3];
    const float* b_qkv   = (const float*)d_in[4];
    const float* w_dense = (const float*)d_in[5];
    const float* b_dense = (const float*)d_in[6];
    const int*   slots   = (const int*)d_in[9];

    float* out = (float*)d_out;
    float* kc  = out + (size_t)TT * HID;
    float* vc  = kc + (size_t)NSLOTS * NH * HD;

    __nv_bfloat16 *p_h3, *p_wq3, *p_wd3, *p_a3;
    cudaGetSymbolAddress((void**)&p_h3,  g_h3);
    cudaGetSymbolAddress((void**)&p_wq3, g_wq3);
    cudaGetSymbolAddress((void**)&p_wd3, g_wd3);
    cudaGetSymbolAddress((void**)&p_a3,  g_a3);

    const int ATTN_SMEM = (ATT_Q_EL + 2 * ATT_KV_EL) * (int)sizeof(__nv_bfloat16);
    const int GEMM_SMEM = NSTG * 2 * STG_BYTES;
    static int attr_set = 0;
    if (!attr_set) {
        cudaFuncSetAttribute(attn_mma,
                             cudaFuncAttributeMaxDynamicSharedMemorySize,
                             ATTN_SMEM);
        cudaFuncSetAttribute(gemm_mma,
                             cudaFuncAttributeMaxDynamicSharedMemorySize,
                             GEMM_SMEM);
        cudaFuncSetAttribute(gemm_qkv,
                             cudaFuncAttributeMaxDynamicSharedMemorySize,
                             GEMM_SMEM);
        attr_set = 1;
    }

    // idx 0: fused splits + cache zero (one kernel)
    fused_split_zero<<<SPLIT_BLKS + ZERO_BLKS, 256>>>(hidden, w_qkv, w_dense,
                                                      kc, vc);

    // idx 1,2: spacers so the dense GEMM lands at ncu idx 5
    nop_kernel<<<1, 32>>>();
    nop_kernel<<<1, 32>>>();

    // idx 3: QKV GEMM with fused bias+RoPE+split+cache epilogue
    {
        dim3 grid(QKV_N / 128, TT / 128);
        gemm_qkv<<<grid, 128, GEMM_SMEM>>>(p_h3, p_wq3, b_qkv,
                                           cosp, sinp, slots, kc, vc);
    }

    // idx 4: flash attention v8
    {
        dim3 grid(SS / 128, NH, BB);
        attn_mma<<<grid, 256, ATTN_SMEM>>>();
    }

    // idx 5: dense projection (profiled this round)
    {
        dim3 grid(HID / 128, TT / 128);
        gemm_mma<<<grid, 128, GEMM_SMEM>>>(p_a3, p_wd3, b_dense, out, HID);
    }
}